// round 1
// baseline (speedup 1.0000x reference)
#include <cuda_runtime.h>
#include <math.h>

#define SBH 128
#define SN  3136
#define SM  196
#define SHW 56
#define QS  0.35355339059327379f   /* 64^-0.25 */

// ---------------- scratch (static device globals; no allocation) ----------------
__device__ float g_Ql [SBH*SM*64];
__device__ float g_ql2[SBH*SM];
__device__ float g_qn2[SBH*SN];
__device__ float g_k1 [(size_t)SBH*SN*SM];     // 315 MB
__device__ float g_P  [SBH*SM*SM];
__device__ float g_V1 [SBH*SM*SM];
__device__ float g_V2 [SBH*SM*SM];
__device__ float g_T  [SBH*SM*SM];
__device__ float g_Z  [SBH*SM*64];
__device__ float g_Y  [SBH*SM*64];

// 64x64 tile, BK=16, 256 threads, 4x4 micro-tile
#define GEMM_CORE(As,Bs) \
  _Pragma("unroll") \
  for (int kk = 0; kk < 16; kk++) { \
    float4 a = *(const float4*)(&As[kk][ty*4]); \
    float4 b = *(const float4*)(&Bs[kk][tx*4]); \
    acc[0][0]+=a.x*b.x; acc[0][1]+=a.x*b.y; acc[0][2]+=a.x*b.z; acc[0][3]+=a.x*b.w; \
    acc[1][0]+=a.y*b.x; acc[1][1]+=a.y*b.y; acc[1][2]+=a.y*b.z; acc[1][3]+=a.y*b.w; \
    acc[2][0]+=a.z*b.x; acc[2][1]+=a.z*b.y; acc[2][2]+=a.z*b.z; acc[2][3]+=a.z*b.w; \
    acc[3][0]+=a.w*b.x; acc[3][1]+=a.w*b.y; acc[3][2]+=a.w*b.z; acc[3][3]+=a.w*b.w; \
  }

// ---------------- landmark conv (im2col GEMM) + LayerNorm + GELU + ql2 ----------------
__global__ __launch_bounds__(256) void k_land(const float* __restrict__ Q,
        const float* __restrict__ W, const float* __restrict__ gamma,
        const float* __restrict__ beta) {
  __shared__ __align__(16) float As[16][68];
  __shared__ __align__(16) float Bs[16][68];
  __shared__ __align__(16) float Cs[64][68];
  int bh = blockIdx.z;
  int m0 = blockIdx.y * 64;                 // patch tile
  int tid = threadIdx.x, tx = tid & 15, ty = tid >> 4;
  const float* Qb = Q + (size_t)bh * SN * 64;
  float acc[4][4] = {};
  for (int k0 = 0; k0 < 1024; k0 += 16) {
    #pragma unroll
    for (int l = 0; l < 4; l++) {
      int idx = tid + l * 256;
      { int ii = idx >> 4, kk = idx & 15;
        int m = m0 + ii, k = k0 + kk;
        float v = 0.f;
        if (m < SM) {
          int pix = k >> 6, ci = k & 63;
          int ry = pix >> 2, rx = pix & 3;
          int py = m / 14, px = m % 14;
          int n = (py * 4 + ry) * SHW + px * 4 + rx;
          v = Qb[n * 64 + ci] * QS;
        }
        As[kk][ii] = v;
      }
      { int kk = idx >> 6, jj = idx & 63;
        Bs[kk][jj] = W[(k0 + kk) * 64 + jj];
      }
    }
    __syncthreads();
    GEMM_CORE(As, Bs)
    __syncthreads();
  }
  #pragma unroll
  for (int i = 0; i < 4; i++)
    #pragma unroll
    for (int j = 0; j < 4; j++)
      Cs[ty * 4 + i][tx * 4 + j] = acc[i][j];
  __syncthreads();
  if (tid < 64) {
    int p = m0 + tid;
    if (p < SM) {
      float mu = 0.f;
      #pragma unroll 8
      for (int j = 0; j < 64; j++) mu += Cs[tid][j];
      mu *= (1.f / 64.f);
      float s2 = 0.f;
      #pragma unroll 8
      for (int j = 0; j < 64; j++) { float d = Cs[tid][j] - mu; s2 += d * d; }
      float r = rsqrtf(s2 * (1.f / 64.f) + 1e-5f);
      float q2 = 0.f;
      float* o = g_Ql + ((size_t)bh * SM + p) * 64;
      for (int j = 0; j < 64; j++) {
        float g = (Cs[tid][j] - mu) * r * gamma[j] + beta[j];
        g = 0.5f * g * (1.f + erff(g * 0.7071067811865476f));
        q2 += g * g;
        o[j] = g;
      }
      g_ql2[bh * SM + p] = q2;
    }
  }
}

// ---------------- |scaled q_n|^2 ----------------
__global__ __launch_bounds__(256) void k_qn2(const float* __restrict__ Q) {
  int bh = blockIdx.y;
  int warp = threadIdx.x >> 5, lane = threadIdx.x & 31;
  int n = blockIdx.x * 8 + warp;
  const float* q = Q + ((size_t)bh * SN + n) * 64;
  float v0 = q[lane], v1 = q[lane + 32];
  float s = v0 * v0 + v1 * v1;
  #pragma unroll
  for (int o = 16; o; o >>= 1) s += __shfl_xor_sync(0xffffffffu, s, o);
  if (lane == 0) g_qn2[bh * SN + n] = s * (QS * QS);
}

// ---------------- gauss kernel GEMM: C = exp(dot(A,B) - 0.5(a2+b2)) ----------------
__global__ __launch_bounds__(256) void k_gauss(const float* __restrict__ A,
     const float* __restrict__ B, const float* __restrict__ a2v,
     const float* __restrict__ b2v, float* __restrict__ C,
     int Ma, int Nb, float ascale) {
  __shared__ __align__(16) float As[16][68];
  __shared__ __align__(16) float Bs[16][68];
  int bh = blockIdx.z;
  int m0 = blockIdx.y * 64, n0 = blockIdx.x * 64;
  int tid = threadIdx.x, tx = tid & 15, ty = tid >> 4;
  A += (size_t)bh * Ma * 64;  B += (size_t)bh * Nb * 64;
  a2v += (size_t)bh * Ma;     b2v += (size_t)bh * Nb;
  C += (size_t)bh * Ma * Nb;
  float acc[4][4] = {};
  for (int k0 = 0; k0 < 64; k0 += 16) {
    #pragma unroll
    for (int l = 0; l < 4; l++) {
      int idx = tid + l * 256;
      { int ii = idx >> 4, kk = idx & 15; int m = m0 + ii;
        As[kk][ii] = (m < Ma) ? A[m * 64 + k0 + kk] * ascale : 0.f; }
      { int jj = idx >> 4, kk = idx & 15; int n = n0 + jj;
        Bs[kk][jj] = (n < Nb) ? B[n * 64 + k0 + kk] : 0.f; }
    }
    __syncthreads();
    GEMM_CORE(As, Bs)
    __syncthreads();
  }
  #pragma unroll
  for (int i = 0; i < 4; i++) {
    int m = m0 + ty * 4 + i; if (m >= Ma) continue;
    float am = a2v[m];
    #pragma unroll
    for (int j = 0; j < 4; j++) {
      int n = n0 + tx * 4 + j; if (n >= Nb) continue;
      C[(size_t)m * Nb + n] = expf(acc[i][j] - 0.5f * (am + b2v[n]));
    }
  }
}

// ---------------- Newton-Schulz init: V0 = P^T / (n1 * ninf) ----------------
__global__ __launch_bounds__(256) void k_nsinit() {
  int bh = blockIdx.x;
  const float* P = g_P + (size_t)bh * SM * SM;
  float* V0 = g_V1 + (size_t)bh * SM * SM;
  __shared__ float red[256];
  __shared__ float rmax_s, cmax_s;
  int tid = threadIdx.x;
  float rs = 0.f, cs = 0.f;
  if (tid < SM) {
    for (int j = 0; j < SM; j++) { rs += fabsf(P[tid * SM + j]); cs += fabsf(P[j * SM + tid]); }
  }
  red[tid] = rs; __syncthreads();
  for (int s = 128; s > 0; s >>= 1) { if (tid < s) red[tid] = fmaxf(red[tid], red[tid + s]); __syncthreads(); }
  if (tid == 0) rmax_s = red[0];
  __syncthreads();
  red[tid] = cs; __syncthreads();
  for (int s = 128; s > 0; s >>= 1) { if (tid < s) red[tid] = fmaxf(red[tid], red[tid + s]); __syncthreads(); }
  if (tid == 0) cmax_s = red[0];
  __syncthreads();
  float inv_nn = 1.f / (rmax_s * cmax_s);
  for (int e = tid; e < SM * SM; e += 256) {
    int i = e / SM, j = e % SM;
    V0[e] = P[j * SM + i] * inv_nn;
  }
}

// ---------------- NS step A: T = P @ Vcur ----------------
__global__ __launch_bounds__(256) void k_nsT(int phase) {
  __shared__ __align__(16) float As[16][68];
  __shared__ __align__(16) float Bs[16][68];
  int bh = blockIdx.z;
  int m0 = blockIdx.y * 64, n0 = blockIdx.x * 64;
  int tid = threadIdx.x, tx = tid & 15, ty = tid >> 4;
  const float* Pb = g_P + (size_t)bh * SM * SM;
  const float* Vb = (phase ? g_V2 : g_V1) + (size_t)bh * SM * SM;
  float* Tb = g_T + (size_t)bh * SM * SM;
  float acc[4][4] = {};
  for (int k0 = 0; k0 < SM; k0 += 16) {
    #pragma unroll
    for (int l = 0; l < 4; l++) {
      int idx = tid + l * 256;
      { int ii = idx >> 4, kk = idx & 15; int m = m0 + ii, k = k0 + kk;
        As[kk][ii] = (m < SM && k < SM) ? Pb[m * SM + k] : 0.f; }
      { int kk = idx >> 6, jj = idx & 63; int k = k0 + kk, n = n0 + jj;
        Bs[kk][jj] = (k < SM && n < SM) ? Vb[k * SM + n] : 0.f; }
    }
    __syncthreads();
    GEMM_CORE(As, Bs)
    __syncthreads();
  }
  #pragma unroll
  for (int i = 0; i < 4; i++) {
    int m = m0 + ty * 4 + i; if (m >= SM) continue;
    #pragma unroll
    for (int j = 0; j < 4; j++) {
      int n = n0 + tx * 4 + j; if (n >= SM) continue;
      Tb[m * SM + n] = acc[i][j];
    }
  }
}

// ---------------- NS step B: Vnext = 2*Vcur - Vcur @ T ----------------
__global__ __launch_bounds__(256) void k_nsU(int phase) {
  __shared__ __align__(16) float As[16][68];
  __shared__ __align__(16) float Bs[16][68];
  int bh = blockIdx.z;
  int m0 = blockIdx.y * 64, n0 = blockIdx.x * 64;
  int tid = threadIdx.x, tx = tid & 15, ty = tid >> 4;
  const float* Vb = (phase ? g_V2 : g_V1) + (size_t)bh * SM * SM;
  float* Vn = (phase ? g_V1 : g_V2) + (size_t)bh * SM * SM;
  const float* Tb = g_T + (size_t)bh * SM * SM;
  float acc[4][4] = {};
  for (int k0 = 0; k0 < SM; k0 += 16) {
    #pragma unroll
    for (int l = 0; l < 4; l++) {
      int idx = tid + l * 256;
      { int ii = idx >> 4, kk = idx & 15; int m = m0 + ii, k = k0 + kk;
        As[kk][ii] = (m < SM && k < SM) ? Vb[m * SM + k] : 0.f; }
      { int kk = idx >> 6, jj = idx & 63; int k = k0 + kk, n = n0 + jj;
        Bs[kk][jj] = (k < SM && n < SM) ? Tb[k * SM + n] : 0.f; }
    }
    __syncthreads();
    GEMM_CORE(As, Bs)
    __syncthreads();
  }
  #pragma unroll
  for (int i = 0; i < 4; i++) {
    int m = m0 + ty * 4 + i; if (m >= SM) continue;
    #pragma unroll
    for (int j = 0; j < 4; j++) {
      int n = n0 + tx * 4 + j; if (n >= SM) continue;
      Vn[m * SM + n] = 2.f * Vb[m * SM + n] - acc[i][j];
    }
  }
}

// ---------------- Z = k1^T @ V   [196 x 64, K=3136] ----------------
__global__ __launch_bounds__(256) void k_Z(const float* __restrict__ V) {
  __shared__ __align__(16) float As[16][68];
  __shared__ __align__(16) float Bs[16][68];
  int bh = blockIdx.z;
  int m0 = blockIdx.y * 64;
  int tid = threadIdx.x, tx = tid & 15, ty = tid >> 4;
  const float* k1b = g_k1 + (size_t)bh * SN * SM;
  const float* Vb = V + (size_t)bh * SN * 64;
  float* Zb = g_Z + (size_t)bh * SM * 64;
  float acc[4][4] = {};
  for (int k0 = 0; k0 < SN; k0 += 16) {
    #pragma unroll
    for (int l = 0; l < 4; l++) {
      int idx = tid + l * 256;
      { int kk = idx >> 6, ii = idx & 63; int m = m0 + ii;
        As[kk][ii] = (m < SM) ? k1b[(size_t)(k0 + kk) * SM + m] : 0.f; }
      { int kk = idx >> 6, jj = idx & 63;
        Bs[kk][jj] = Vb[(k0 + kk) * 64 + jj]; }
    }
    __syncthreads();
    GEMM_CORE(As, Bs)
    __syncthreads();
  }
  #pragma unroll
  for (int i = 0; i < 4; i++) {
    int m = m0 + ty * 4 + i; if (m >= SM) continue;
    #pragma unroll
    for (int j = 0; j < 4; j++) {
      int n = tx * 4 + j;
      Zb[m * 64 + n] = acc[i][j];
    }
  }
}

// ---------------- Y = inv @ Z   [196 x 64, K=196] ----------------
__global__ __launch_bounds__(256) void k_Y() {
  __shared__ __align__(16) float As[16][68];
  __shared__ __align__(16) float Bs[16][68];
  int bh = blockIdx.z;
  int m0 = blockIdx.y * 64;
  int tid = threadIdx.x, tx = tid & 15, ty = tid >> 4;
  const float* Ib = g_V1 + (size_t)bh * SM * SM;
  const float* Zb = g_Z + (size_t)bh * SM * 64;
  float* Yb = g_Y + (size_t)bh * SM * 64;
  float acc[4][4] = {};
  for (int k0 = 0; k0 < SM; k0 += 16) {
    #pragma unroll
    for (int l = 0; l < 4; l++) {
      int idx = tid + l * 256;
      { int ii = idx >> 4, kk = idx & 15; int m = m0 + ii, k = k0 + kk;
        As[kk][ii] = (m < SM && k < SM) ? Ib[m * SM + k] : 0.f; }
      { int kk = idx >> 6, jj = idx & 63; int k = k0 + kk;
        Bs[kk][jj] = (k < SM) ? Zb[k * 64 + jj] : 0.f; }
    }
    __syncthreads();
    GEMM_CORE(As, Bs)
    __syncthreads();
  }
  #pragma unroll
  for (int i = 0; i < 4; i++) {
    int m = m0 + ty * 4 + i; if (m >= SM) continue;
    #pragma unroll
    for (int j = 0; j < 4; j++) {
      int n = tx * 4 + j;
      Yb[m * 64 + n] = acc[i][j];
    }
  }
}

// ---------------- depthwise 3x3 conv residual -> d_out ----------------
__global__ __launch_bounds__(256) void k_conv(const float* __restrict__ V,
        const float* __restrict__ cw, float* __restrict__ out) {
  int bh = blockIdx.y;
  int h = bh & 7;
  int e = blockIdx.x * 256 + threadIdx.x;   // < 3136*64
  int c = e & 63, n = e >> 6;
  int y = n / SHW, x = n % SHW;
  const float* Vb = V + (size_t)bh * SN * 64;
  float acc = 0.f;
  #pragma unroll
  for (int dy = -1; dy <= 1; dy++)
    #pragma unroll
    for (int dx = -1; dx <= 1; dx++) {
      int yy = y + dy, xx = x + dx;
      if ((unsigned)yy < SHW && (unsigned)xx < SHW)
        acc += cw[((dy + 1) * 3 + (dx + 1)) * 8 + h] * Vb[(yy * SHW + xx) * 64 + c];
    }
  out[(size_t)bh * SN * 64 + e] = acc;
}

// ---------------- out += k1 @ Y   [3136 x 64, K=196] ----------------
__global__ __launch_bounds__(256) void k_X(float* __restrict__ out) {
  __shared__ __align__(16) float As[16][68];
  __shared__ __align__(16) float Bs[16][68];
  int bh = blockIdx.z;
  int m0 = blockIdx.y * 64;
  int tid = threadIdx.x, tx = tid & 15, ty = tid >> 4;
  const float* k1b = g_k1 + (size_t)bh * SN * SM;
  const float* Yb = g_Y + (size_t)bh * SM * 64;
  float* ob = out + (size_t)bh * SN * 64;
  float acc[4][4] = {};
  for (int k0 = 0; k0 < SM; k0 += 16) {
    #pragma unroll
    for (int l = 0; l < 4; l++) {
      int idx = tid + l * 256;
      { int ii = idx >> 4, kk = idx & 15; int k = k0 + kk;
        As[kk][ii] = (k < SM) ? k1b[(size_t)(m0 + ii) * SM + k] : 0.f; }
      { int kk = idx >> 6, jj = idx & 63; int k = k0 + kk;
        Bs[kk][jj] = (k < SM) ? Yb[k * 64 + jj] : 0.f; }
    }
    __syncthreads();
    GEMM_CORE(As, Bs)
    __syncthreads();
  }
  #pragma unroll
  for (int i = 0; i < 4; i++) {
    int m = m0 + ty * 4 + i;
    #pragma unroll
    for (int j = 0; j < 4; j++) {
      int n = tx * 4 + j;
      ob[m * 64 + n] += acc[i][j];
    }
  }
}

// ---------------- host launch ----------------
extern "C" void kernel_launch(void* const* d_in, const int* in_sizes, int n_in,
                              void* d_out, int out_size) {
  const float* Q     = (const float*)d_in[0];
  const float* V     = (const float*)d_in[1];
  const float* wl    = (const float*)d_in[2];
  const float* gamma = (const float*)d_in[3];
  const float* beta  = (const float*)d_in[4];
  const float* cw    = (const float*)d_in[5];
  float* out = (float*)d_out;

  float *pQl, *pql2, *pqn2, *pk1, *pP;
  cudaGetSymbolAddress((void**)&pQl,  g_Ql);
  cudaGetSymbolAddress((void**)&pql2, g_ql2);
  cudaGetSymbolAddress((void**)&pqn2, g_qn2);
  cudaGetSymbolAddress((void**)&pk1,  g_k1);
  cudaGetSymbolAddress((void**)&pP,   g_P);

  // landmarks (conv + LN + GELU + |ql|^2)
  k_land<<<dim3(1, 4, SBH), 256>>>(Q, wl, gamma, beta);
  // |scaled q|^2
  k_qn2<<<dim3(SN / 8, SBH), 256>>>(Q);
  // k2 = gauss(Ql, Ql) -> g_P
  k_gauss<<<dim3(4, 4, SBH), 256>>>(pQl, pQl, pql2, pql2, pP, SM, SM, 1.f);
  // Newton-Schulz init + 20 iterations (ping-pong V1/V2, final in g_V1)
  k_nsinit<<<SBH, 256>>>();
  for (int i = 0; i < 20; i++) {
    k_nsT<<<dim3(4, 4, SBH), 256>>>(i & 1);
    k_nsU<<<dim3(4, 4, SBH), 256>>>(i & 1);
  }
  // k1 = gauss(Qs, Ql) -> g_k1
  k_gauss<<<dim3(4, 49, SBH), 256>>>(Q, pQl, pqn2, pql2, pk1, SN, SM, QS);
  // Z = k1^T V ; Y = inv Z
  k_Z<<<dim3(1, 4, SBH), 256>>>(V);
  k_Y<<<dim3(1, 4, SBH), 256>>>();
  // depthwise conv residual writes d_out, then out += k1 Y
  k_conv<<<dim3(784, SBH), 256>>>(V, cw, out);
  k_X<<<dim3(1, 49, SBH), 256>>>(out);
}

// round 4
// speedup vs baseline: 1.2631x; 1.2631x over previous
#include <cuda_runtime.h>
#include <cuda_bf16.h>
#include <math.h>
#include <stdint.h>

#define SBH 128
#define SN  3136
#define SM  196
#define SHW 56
#define QS  0.35355339059327379f   /* 64^-0.25 */
#define NSP 256
#define NSE ((size_t)(NSP*NSP))

// ---------------- scratch (static device globals; no allocation) ----------------
__device__ float g_Ql [SBH*SM*64];
__device__ float g_ql2[SBH*SM];
__device__ float g_qn2[SBH*SN];
__device__ float g_k1 [(size_t)SBH*SN*SM];     // 315 MB
__device__ float g_P  [SBH*SM*SM];
__device__ float g_V1 [SBH*SM*SM];
__device__ float g_Z  [SBH*SM*64];
__device__ float g_Y  [SBH*SM*64];
__device__ float g_nsc[SBH];
// bf16 hi/lo split NS operands, padded to 256x256
__device__ __nv_bfloat16 g_Pbh[SBH*NSE], g_Pbl[SBH*NSE];
__device__ __nv_bfloat16 g_Vah[SBH*NSE], g_Val[SBH*NSE];
__device__ __nv_bfloat16 g_Vbh[SBH*NSE], g_Vbl[SBH*NSE];
__device__ __nv_bfloat16 g_Tth[SBH*NSE], g_Ttl[SBH*NSE];

// ================= helpers =================
__device__ __forceinline__ void bsplit(float x, __nv_bfloat16& h, __nv_bfloat16& l) {
  h = __float2bfloat16(x);
  l = __float2bfloat16(x - __bfloat162float(h));
}
__device__ __forceinline__ uint32_t pack2(__nv_bfloat16 a, __nv_bfloat16 b) {
  return (uint32_t)__bfloat16_as_ushort(a) | ((uint32_t)__bfloat16_as_ushort(b) << 16);
}
__device__ __forceinline__ void mma16816(float* c, const uint32_t* a, const uint32_t* b) {
  asm volatile(
    "mma.sync.aligned.m16n8k16.row.col.f32.bf16.bf16.f32 "
    "{%0,%1,%2,%3}, {%4,%5,%6,%7}, {%8,%9}, {%0,%1,%2,%3};"
    : "+f"(c[0]), "+f"(c[1]), "+f"(c[2]), "+f"(c[3])
    : "r"(a[0]), "r"(a[1]), "r"(a[2]), "r"(a[3]), "r"(b[0]), "r"(b[1]));
}

// 64x64 tile, BK=16, 256 threads, 4x4 micro-tile (SIMT fp32 GEMM core)
#define GEMM_CORE(As,Bs) \
  _Pragma("unroll") \
  for (int kk = 0; kk < 16; kk++) { \
    float4 a = *(const float4*)(&As[kk][ty*4]); \
    float4 b = *(const float4*)(&Bs[kk][tx*4]); \
    acc[0][0]+=a.x*b.x; acc[0][1]+=a.x*b.y; acc[0][2]+=a.x*b.z; acc[0][3]+=a.x*b.w; \
    acc[1][0]+=a.y*b.x; acc[1][1]+=a.y*b.y; acc[1][2]+=a.y*b.z; acc[1][3]+=a.y*b.w; \
    acc[2][0]+=a.z*b.x; acc[2][1]+=a.z*b.y; acc[2][2]+=a.z*b.z; acc[2][3]+=a.z*b.w; \
    acc[3][0]+=a.w*b.x; acc[3][1]+=a.w*b.y; acc[3][2]+=a.w*b.z; acc[3][3]+=a.w*b.w; \
  }

// ---------------- landmark conv (im2col GEMM) + LayerNorm + GELU + ql2 ----------------
__global__ __launch_bounds__(256) void k_land(const float* __restrict__ Q,
        const float* __restrict__ W, const float* __restrict__ gamma,
        const float* __restrict__ beta) {
  __shared__ __align__(16) float As[16][68];
  __shared__ __align__(16) float Bs[16][68];
  __shared__ __align__(16) float Cs[64][68];
  int bh = blockIdx.z;
  int m0 = blockIdx.y * 64;
  int tid = threadIdx.x, tx = tid & 15, ty = tid >> 4;
  const float* Qb = Q + (size_t)bh * SN * 64;
  float acc[4][4] = {};
  for (int k0 = 0; k0 < 1024; k0 += 16) {
    #pragma unroll
    for (int l = 0; l < 4; l++) {
      int idx = tid + l * 256;
      { int ii = idx >> 4, kk = idx & 15;
        int m = m0 + ii, k = k0 + kk;
        float v = 0.f;
        if (m < SM) {
          int pix = k >> 6, ci = k & 63;
          int ry = pix >> 2, rx = pix & 3;
          int py = m / 14, px = m % 14;
          int n = (py * 4 + ry) * SHW + px * 4 + rx;
          v = Qb[n * 64 + ci] * QS;
        }
        As[kk][ii] = v;
      }
      { int kk = idx >> 6, jj = idx & 63;
        Bs[kk][jj] = W[(k0 + kk) * 64 + jj];
      }
    }
    __syncthreads();
    GEMM_CORE(As, Bs)
    __syncthreads();
  }
  #pragma unroll
  for (int i = 0; i < 4; i++)
    #pragma unroll
    for (int j = 0; j < 4; j++)
      Cs[ty * 4 + i][tx * 4 + j] = acc[i][j];
  __syncthreads();
  if (tid < 64) {
    int p = m0 + tid;
    if (p < SM) {
      float mu = 0.f;
      #pragma unroll 8
      for (int j = 0; j < 64; j++) mu += Cs[tid][j];
      mu *= (1.f / 64.f);
      float s2 = 0.f;
      #pragma unroll 8
      for (int j = 0; j < 64; j++) { float d = Cs[tid][j] - mu; s2 += d * d; }
      float r = rsqrtf(s2 * (1.f / 64.f) + 1e-5f);
      float q2 = 0.f;
      float* o = g_Ql + ((size_t)bh * SM + p) * 64;
      for (int j = 0; j < 64; j++) {
        float g = (Cs[tid][j] - mu) * r * gamma[j] + beta[j];
        g = 0.5f * g * (1.f + erff(g * 0.7071067811865476f));
        q2 += g * g;
        o[j] = g;
      }
      g_ql2[bh * SM + p] = q2;
    }
  }
}

// ---------------- |scaled q_n|^2 ----------------
__global__ __launch_bounds__(256) void k_qn2(const float* __restrict__ Q) {
  int bh = blockIdx.y;
  int warp = threadIdx.x >> 5, lane = threadIdx.x & 31;
  int n = blockIdx.x * 8 + warp;
  const float* q = Q + ((size_t)bh * SN + n) * 64;
  float v0 = q[lane], v1 = q[lane + 32];
  float s = v0 * v0 + v1 * v1;
  #pragma unroll
  for (int o = 16; o; o >>= 1) s += __shfl_xor_sync(0xffffffffu, s, o);
  if (lane == 0) g_qn2[bh * SN + n] = s * (QS * QS);
}

// ---------------- gauss kernel GEMM: C = exp(dot(A,B) - 0.5(a2+b2)) ----------------
__global__ __launch_bounds__(256) void k_gauss(const float* __restrict__ A,
     const float* __restrict__ B, const float* __restrict__ a2v,
     const float* __restrict__ b2v, float* __restrict__ C,
     int Ma, int Nb, float ascale) {
  __shared__ __align__(16) float As[16][68];
  __shared__ __align__(16) float Bs[16][68];
  int bh = blockIdx.z;
  int m0 = blockIdx.y * 64, n0 = blockIdx.x * 64;
  int tid = threadIdx.x, tx = tid & 15, ty = tid >> 4;
  A += (size_t)bh * Ma * 64;  B += (size_t)bh * Nb * 64;
  a2v += (size_t)bh * Ma;     b2v += (size_t)bh * Nb;
  C += (size_t)bh * Ma * Nb;
  float acc[4][4] = {};
  for (int k0 = 0; k0 < 64; k0 += 16) {
    #pragma unroll
    for (int l = 0; l < 4; l++) {
      int idx = tid + l * 256;
      { int ii = idx >> 4, kk = idx & 15; int m = m0 + ii;
        As[kk][ii] = (m < Ma) ? A[m * 64 + k0 + kk] * ascale : 0.f; }
      { int jj = idx >> 4, kk = idx & 15; int n = n0 + jj;
        Bs[kk][jj] = (n < Nb) ? B[n * 64 + k0 + kk] : 0.f; }
    }
    __syncthreads();
    GEMM_CORE(As, Bs)
    __syncthreads();
  }
  #pragma unroll
  for (int i = 0; i < 4; i++) {
    int m = m0 + ty * 4 + i; if (m >= Ma) continue;
    float am = a2v[m];
    #pragma unroll
    for (int j = 0; j < 4; j++) {
      int n = n0 + tx * 4 + j; if (n >= Nb) continue;
      C[(size_t)m * Nb + n] = expf(acc[i][j] - 0.5f * (am + b2v[n]));
    }
  }
}

// ---------------- NS scale: g_nsc = 1/(n1*ninf) ----------------
__global__ __launch_bounds__(256) void k_scale() {
  int bh = blockIdx.x;
  const float* P = g_P + (size_t)bh * SM * SM;
  __shared__ float red[256];
  __shared__ float rmax_s;
  int tid = threadIdx.x;
  float rs = 0.f, cs = 0.f;
  if (tid < SM) {
    for (int j = 0; j < SM; j++) { rs += fabsf(P[tid * SM + j]); cs += fabsf(P[j * SM + tid]); }
  }
  red[tid] = rs; __syncthreads();
  for (int s = 128; s > 0; s >>= 1) { if (tid < s) red[tid] = fmaxf(red[tid], red[tid + s]); __syncthreads(); }
  if (tid == 0) rmax_s = red[0];
  __syncthreads();
  red[tid] = cs; __syncthreads();
  for (int s = 128; s > 0; s >>= 1) { if (tid < s) red[tid] = fmaxf(red[tid], red[tid + s]); __syncthreads(); }
  if (tid == 0) g_nsc[bh] = 1.f / (rmax_s * red[0]);
}

// ---------------- pad + bf16 hi/lo split of P and V0 ----------------
__global__ __launch_bounds__(256) void k_pad() {
  int bh = blockIdx.y, row = blockIdx.x, j = threadIdx.x;
  float s = g_nsc[bh];
  float v = (row < SM && j < SM) ? g_P[(size_t)bh * SM * SM + row * SM + j] : 0.f;
  size_t o = (size_t)bh * NSE + row * NSP + j;
  __nv_bfloat16 h, l;
  bsplit(v, h, l);      g_Pbh[o] = h; g_Pbl[o] = l;
  bsplit(v * s, h, l);  g_Vah[o] = h; g_Val[o] = l;
}

// ---------------- HMMA NS GEMM: D = A @ B^T (both row-major [256x256] bf16 hi/lo) ----
// All NS iterates are symmetric (polynomials in symmetric P), so B^T == B.
// mode 0:  O = D                 (T = V @ P)
// mode 1:  O = 2*Vep - D         (Vnext = 2V - V @ T)
// CTA: 128x128 tile, 8 warps (4x2), warp tile 32x64, BK=32, 3-pass hi/lo split.
__global__ __launch_bounds__(256) void k_nsmm(
    const __nv_bfloat16* __restrict__ Ahg, const __nv_bfloat16* __restrict__ Alg,
    const __nv_bfloat16* __restrict__ Bhg, const __nv_bfloat16* __restrict__ Blg,
    const __nv_bfloat16* __restrict__ Vh, const __nv_bfloat16* __restrict__ Vl,
    __nv_bfloat16* __restrict__ Oh, __nv_bfloat16* __restrict__ Ol, int mode) {
  __shared__ __align__(16) __nv_bfloat16 sAh[128][40];
  __shared__ __align__(16) __nv_bfloat16 sAl[128][40];
  __shared__ __align__(16) __nv_bfloat16 sBh[128][40];
  __shared__ __align__(16) __nv_bfloat16 sBl[128][40];
  int tid = threadIdx.x, w = tid >> 5, lane = tid & 31;
  int gid = lane >> 2, tig = lane & 3;
  int wm = w & 3, wn = w >> 2;                    // warp grid 4x2
  int bh = blockIdx.z, m0 = blockIdx.y * 128, n0 = blockIdx.x * 128;
  size_t base = (size_t)bh * NSE;

  const uint4* gAh = (const uint4*)(Ahg + base);
  const uint4* gAl = (const uint4*)(Alg + base);
  const uint4* gBh = (const uint4*)(Bhg + base);
  const uint4* gBl = (const uint4*)(Blg + base);

  float acc[2][8][4] = {};

  int r0 = tid >> 2, seg = tid & 3;               // 64 rows per pass, 4 segs of 8 bf16
  for (int kc = 0; kc < 8; kc++) {
    #pragma unroll
    for (int rr = 0; rr < 2; rr++) {
      int r = r0 + rr * 64;
      int ga = (m0 + r) * 32 + kc * 4 + seg;      // uint4 index into [256][256] bf16
      int gb = (n0 + r) * 32 + kc * 4 + seg;
      *(uint4*)&sAh[r][seg * 8] = gAh[ga];
      *(uint4*)&sAl[r][seg * 8] = gAl[ga];
      *(uint4*)&sBh[r][seg * 8] = gBh[gb];
      *(uint4*)&sBl[r][seg * 8] = gBl[gb];
    }
    __syncthreads();
    #pragma unroll
    for (int ks = 0; ks < 2; ks++) {
      int kb = ks * 16;
      uint32_t ah[2][4], al[2][4], bhf[8][2], blf[8][2];
      #pragma unroll
      for (int mt = 0; mt < 2; mt++) {
        int row = wm * 32 + mt * 16 + gid;
        ah[mt][0] = *(const uint32_t*)&sAh[row][kb + tig * 2];
        ah[mt][1] = *(const uint32_t*)&sAh[row + 8][kb + tig * 2];
        ah[mt][2] = *(const uint32_t*)&sAh[row][kb + 8 + tig * 2];
        ah[mt][3] = *(const uint32_t*)&sAh[row + 8][kb + 8 + tig * 2];
        al[mt][0] = *(const uint32_t*)&sAl[row][kb + tig * 2];
        al[mt][1] = *(const uint32_t*)&sAl[row + 8][kb + tig * 2];
        al[mt][2] = *(const uint32_t*)&sAl[row][kb + 8 + tig * 2];
        al[mt][3] = *(const uint32_t*)&sAl[row + 8][kb + 8 + tig * 2];
      }
      #pragma unroll
      for (int nt = 0; nt < 8; nt++) {
        int brow = wn * 64 + nt * 8 + gid;
        bhf[nt][0] = *(const uint32_t*)&sBh[brow][kb + tig * 2];
        bhf[nt][1] = *(const uint32_t*)&sBh[brow][kb + 8 + tig * 2];
        blf[nt][0] = *(const uint32_t*)&sBl[brow][kb + tig * 2];
        blf[nt][1] = *(const uint32_t*)&sBl[brow][kb + 8 + tig * 2];
      }
      #pragma unroll
      for (int mt = 0; mt < 2; mt++)
        #pragma unroll
        for (int nt = 0; nt < 8; nt++) {
          mma16816(acc[mt][nt], ah[mt], bhf[nt]);
          mma16816(acc[mt][nt], ah[mt], blf[nt]);
          mma16816(acc[mt][nt], al[mt], bhf[nt]);
        }
    }
    __syncthreads();
  }

  // epilogue: c0,c1 -> (row, col..col+1); c2,c3 -> (row+8, col..col+1)
  #pragma unroll
  for (int mt = 0; mt < 2; mt++) {
    #pragma unroll
    for (int nt = 0; nt < 8; nt++) {
      int row = m0 + wm * 32 + mt * 16 + gid;
      int col = n0 + wn * 64 + nt * 8 + tig * 2;
      #pragma unroll
      for (int half = 0; half < 2; half++) {
        int r = row + half * 8;
        float d0 = acc[mt][nt][half * 2], d1 = acc[mt][nt][half * 2 + 1];
        size_t off = base + (size_t)r * NSP + col;
        if (mode == 1) {
          uint32_t vhp = *(const uint32_t*)(Vh + off);
          uint32_t vlp = *(const uint32_t*)(Vl + off);
          float v0 = __bfloat162float(__ushort_as_bfloat16((uint16_t)vhp))
                   + __bfloat162float(__ushort_as_bfloat16((uint16_t)vlp));
          float v1 = __bfloat162float(__ushort_as_bfloat16((uint16_t)(vhp >> 16)))
                   + __bfloat162float(__ushort_as_bfloat16((uint16_t)(vlp >> 16)));
          d0 = 2.f * v0 - d0;
          d1 = 2.f * v1 - d1;
        }
        __nv_bfloat16 h0, l0, h1, l1;
        bsplit(d0, h0, l0); bsplit(d1, h1, l1);
        *(uint32_t*)(Oh + off) = pack2(h0, h1);
        *(uint32_t*)(Ol + off) = pack2(l0, l1);
      }
    }
  }
}

// ---------------- unpad: V bf16 hi/lo -> g_V1 fp32 [196x196] ----------------
__global__ __launch_bounds__(256) void k_unpad(const __nv_bfloat16* __restrict__ Vh,
                                               const __nv_bfloat16* __restrict__ Vl) {
  int bh = blockIdx.y, m = blockIdx.x, j = threadIdx.x;
  if (j < SM) {
    size_t i = (size_t)bh * NSE + m * NSP + j;
    g_V1[(size_t)bh * SM * SM + m * SM + j] =
        __bfloat162float(Vh[i]) + __bfloat162float(Vl[i]);
  }
}

// ---------------- Z = k1^T @ V   [196 x 64, K=3136] ----------------
__global__ __launch_bounds__(256) void k_Z(const float* __restrict__ V) {
  __shared__ __align__(16) float As[16][68];
  __shared__ __align__(16) float Bs[16][68];
  int bh = blockIdx.z;
  int m0 = blockIdx.y * 64;
  int tid = threadIdx.x, tx = tid & 15, ty = tid >> 4;
  const float* k1b = g_k1 + (size_t)bh * SN * SM;
  const float* Vb = V + (size_t)bh * SN * 64;
  float* Zb = g_Z + (size_t)bh * SM * 64;
  float acc[4][4] = {};
  for (int k0 = 0; k0 < SN; k0 += 16) {
    #pragma unroll
    for (int l = 0; l < 4; l++) {
      int idx = tid + l * 256;
      { int kk = idx >> 6, ii = idx & 63; int m = m0 + ii;
        As[kk][ii] = (m < SM) ? k1b[(size_t)(k0 + kk) * SM + m] : 0.f; }
      { int kk = idx >> 6, jj = idx & 63;
        Bs[kk][jj] = Vb[(k0 + kk) * 64 + jj]; }
    }
    __syncthreads();
    GEMM_CORE(As, Bs)
    __syncthreads();
  }
  #pragma unroll
  for (int i = 0; i < 4; i++) {
    int m = m0 + ty * 4 + i; if (m >= SM) continue;
    #pragma unroll
    for (int j = 0; j < 4; j++) {
      int n = tx * 4 + j;
      Zb[m * 64 + n] = acc[i][j];
    }
  }
}

// ---------------- Y = inv @ Z   [196 x 64, K=196] ----------------
__global__ __launch_bounds__(256) void k_Y() {
  __shared__ __align__(16) float As[16][68];
  __shared__ __align__(16) float Bs[16][68];
  int bh = blockIdx.z;
  int m0 = blockIdx.y * 64;
  int tid = threadIdx.x, tx = tid & 15, ty = tid >> 4;
  const float* Ib = g_V1 + (size_t)bh * SM * SM;
  const float* Zb = g_Z + (size_t)bh * SM * 64;
  float* Yb = g_Y + (size_t)bh * SM * 64;
  float acc[4][4] = {};
  for (int k0 = 0; k0 < SM; k0 += 16) {
    #pragma unroll
    for (int l = 0; l < 4; l++) {
      int idx = tid + l * 256;
      { int ii = idx >> 4, kk = idx & 15; int m = m0 + ii, k = k0 + kk;
        As[kk][ii] = (m < SM && k < SM) ? Ib[m * SM + k] : 0.f; }
      { int kk = idx >> 6, jj = idx & 63; int k = k0 + kk;
        Bs[kk][jj] = (k < SM) ? Zb[k * 64 + jj] : 0.f; }
    }
    __syncthreads();
    GEMM_CORE(As, Bs)
    __syncthreads();
  }
  #pragma unroll
  for (int i = 0; i < 4; i++) {
    int m = m0 + ty * 4 + i; if (m >= SM) continue;
    #pragma unroll
    for (int j = 0; j < 4; j++) {
      int n = tx * 4 + j;
      Yb[m * 64 + n] = acc[i][j];
    }
  }
}

// ---------------- depthwise 3x3 conv residual -> d_out ----------------
__global__ __launch_bounds__(256) void k_conv(const float* __restrict__ V,
        const float* __restrict__ cw, float* __restrict__ out) {
  int bh = blockIdx.y;
  int h = bh & 7;
  int e = blockIdx.x * 256 + threadIdx.x;
  int c = e & 63, n = e >> 6;
  int y = n / SHW, x = n % SHW;
  const float* Vb = V + (size_t)bh * SN * 64;
  float acc = 0.f;
  #pragma unroll
  for (int dy = -1; dy <= 1; dy++)
    #pragma unroll
    for (int dx = -1; dx <= 1; dx++) {
      int yy = y + dy, xx = x + dx;
      if ((unsigned)yy < SHW && (unsigned)xx < SHW)
        acc += cw[((dy + 1) * 3 + (dx + 1)) * 8 + h] * Vb[(yy * SHW + xx) * 64 + c];
    }
  out[(size_t)bh * SN * 64 + e] = acc;
}

// ---------------- out += k1 @ Y   [3136 x 64, K=196] ----------------
__global__ __launch_bounds__(256) void k_X(float* __restrict__ out) {
  __shared__ __align__(16) float As[16][68];
  __shared__ __align__(16) float Bs[16][68];
  int bh = blockIdx.z;
  int m0 = blockIdx.y * 64;
  int tid = threadIdx.x, tx = tid & 15, ty = tid >> 4;
  const float* k1b = g_k1 + (size_t)bh * SN * SM;
  const float* Yb = g_Y + (size_t)bh * SM * 64;
  float* ob = out + (size_t)bh * SN * 64;
  float acc[4][4] = {};
  for (int k0 = 0; k0 < SM; k0 += 16) {
    #pragma unroll
    for (int l = 0; l < 4; l++) {
      int idx = tid + l * 256;
      { int ii = idx >> 4, kk = idx & 15; int k = k0 + kk;
        As[kk][ii] = (k < SM) ? k1b[(size_t)(m0 + ii) * SM + k] : 0.f; }
      { int kk = idx >> 6, jj = idx & 63; int k = k0 + kk;
        Bs[kk][jj] = (k < SM) ? Yb[k * 64 + jj] : 0.f; }
    }
    __syncthreads();
    GEMM_CORE(As, Bs)
    __syncthreads();
  }
  #pragma unroll
  for (int i = 0; i < 4; i++) {
    int m = m0 + ty * 4 + i;
    #pragma unroll
    for (int j = 0; j < 4; j++) {
      int n = tx * 4 + j;
      ob[m * 64 + n] += acc[i][j];
    }
  }
}

// ---------------- host launch ----------------
extern "C" void kernel_launch(void* const* d_in, const int* in_sizes, int n_in,
                              void* d_out, int out_size) {
  const float* Q     = (const float*)d_in[0];
  const float* V     = (const float*)d_in[1];
  const float* wl    = (const float*)d_in[2];
  const float* gamma = (const float*)d_in[3];
  const float* beta  = (const float*)d_in[4];
  const float* cw    = (const float*)d_in[5];
  float* out = (float*)d_out;

  float *pQl, *pql2, *pqn2, *pk1, *pP;
  cudaGetSymbolAddress((void**)&pQl,  g_Ql);
  cudaGetSymbolAddress((void**)&pql2, g_ql2);
  cudaGetSymbolAddress((void**)&pqn2, g_qn2);
  cudaGetSymbolAddress((void**)&pk1,  g_k1);
  cudaGetSymbolAddress((void**)&pP,   g_P);

  __nv_bfloat16 *pPh, *pPl, *pVah, *pVal, *pVbh, *pVbl, *pTh, *pTl;
  cudaGetSymbolAddress((void**)&pPh,  g_Pbh);
  cudaGetSymbolAddress((void**)&pPl,  g_Pbl);
  cudaGetSymbolAddress((void**)&pVah, g_Vah);
  cudaGetSymbolAddress((void**)&pVal, g_Val);
  cudaGetSymbolAddress((void**)&pVbh, g_Vbh);
  cudaGetSymbolAddress((void**)&pVbl, g_Vbl);
  cudaGetSymbolAddress((void**)&pTh,  g_Tth);
  cudaGetSymbolAddress((void**)&pTl,  g_Ttl);

  // landmarks (conv + LN + GELU + |ql|^2)
  k_land<<<dim3(1, 4, SBH), 256>>>(Q, wl, gamma, beta);
  // |scaled q|^2
  k_qn2<<<dim3(SN / 8, SBH), 256>>>(Q);
  // k2 = gauss(Ql, Ql) -> g_P
  k_gauss<<<dim3(4, 4, SBH), 256>>>(pQl, pQl, pql2, pql2, pP, SM, SM, 1.f);
  // NS scale + bf16 hi/lo padded operands
  k_scale<<<SBH, 256>>>();
  k_pad<<<dim3(NSP, SBH), 256>>>();
  // 20 Newton-Schulz iterations on HMMA (bf16 hi/lo split, fp32 accum)
  __nv_bfloat16 *ch = pVah, *cl = pVal, *oh = pVbh, *ol = pVbl;
  dim3 nsg(2, 2, SBH);
  for (int i = 0; i < 20; i++) {
    // T = V @ P (= V @ P^T, P symmetric)
    k_nsmm<<<nsg, 256>>>(ch, cl, pPh, pPl, nullptr, nullptr, pTh, pTl, 0);
    // Vnext = 2V - V @ T (= V @ T^T, T symmetric)
    k_nsmm<<<nsg, 256>>>(ch, cl, pTh, pTl, ch, cl, oh, ol, 1);
    __nv_bfloat16* t;
    t = ch; ch = oh; oh = t;
    t = cl; cl = ol; ol = t;
  }
  k_unpad<<<dim3(SM, SBH), 256>>>(ch, cl);
  // k1 = gauss(Qs, Ql) -> g_k1
  k_gauss<<<dim3(4, 49, SBH), 256>>>(Q, pQl, pqn2, pql2, pk1, SN, SM, QS);
  // Z = k1^T V ; Y = inv Z
  k_Z<<<dim3(1, 4, SBH), 256>>>(V);
  k_Y<<<dim3(1, 4, SBH), 256>>>();
  // depthwise conv residual writes d_out, then out += k1 Y
  k_conv<<<dim3(784, SBH), 256>>>(V, cw, out);
  k_X<<<dim3(1, 49, SBH), 256>>>(out);
}

// round 5
// speedup vs baseline: 2.0728x; 1.6411x over previous
#include <cuda_runtime.h>
#include <cuda_bf16.h>
#include <math.h>
#include <stdint.h>

#define SBH 128
#define SN  3136
#define SM  196
#define SHW 56
#define QS  0.35355339059327379f   /* 64^-0.25 */
#define NSP 256
#define NSE ((size_t)(NSP*NSP))

// ---------------- scratch (static device globals; no allocation) ----------------
__device__ float g_Ql [SBH*SM*64];
__device__ float g_ql2[SBH*SM];
__device__ float g_qn2[SBH*SN];
__device__ float g_k1 [(size_t)SBH*SN*SM];     // 315 MB
__device__ float g_P  [SBH*SM*SM];
__device__ float g_V1 [SBH*SM*SM];
__device__ float g_Z  [SBH*SM*64];
__device__ float g_Y  [SBH*SM*64];
__device__ float g_nsc[SBH];
// bf16 NS operands, padded to 256x256
__device__ __nv_bfloat16 g_Pb[SBH*NSE];
__device__ __nv_bfloat16 g_Va[SBH*NSE];
__device__ __nv_bfloat16 g_Vb[SBH*NSE];
__device__ __nv_bfloat16 g_Tt[SBH*NSE];

// ================= helpers =================
__device__ __forceinline__ uint32_t pack2(__nv_bfloat16 a, __nv_bfloat16 b) {
  return (uint32_t)__bfloat16_as_ushort(a) | ((uint32_t)__bfloat16_as_ushort(b) << 16);
}
__device__ __forceinline__ void mma16816(float* c, const uint32_t* a, const uint32_t* b) {
  asm volatile(
    "mma.sync.aligned.m16n8k16.row.col.f32.bf16.bf16.f32 "
    "{%0,%1,%2,%3}, {%4,%5,%6,%7}, {%8,%9}, {%0,%1,%2,%3};"
    : "+f"(c[0]), "+f"(c[1]), "+f"(c[2]), "+f"(c[3])
    : "r"(a[0]), "r"(a[1]), "r"(a[2]), "r"(a[3]), "r"(b[0]), "r"(b[1]));
}

// 64x64 tile, BK=16, 256 threads, 4x4 micro-tile (SIMT fp32 GEMM core)
#define GEMM_CORE(As,Bs) \
  _Pragma("unroll") \
  for (int kk = 0; kk < 16; kk++) { \
    float4 a = *(const float4*)(&As[kk][ty*4]); \
    float4 b = *(const float4*)(&Bs[kk][tx*4]); \
    acc[0][0]+=a.x*b.x; acc[0][1]+=a.x*b.y; acc[0][2]+=a.x*b.z; acc[0][3]+=a.x*b.w; \
    acc[1][0]+=a.y*b.x; acc[1][1]+=a.y*b.y; acc[1][2]+=a.y*b.z; acc[1][3]+=a.y*b.w; \
    acc[2][0]+=a.z*b.x; acc[2][1]+=a.z*b.y; acc[2][2]+=a.z*b.z; acc[2][3]+=a.z*b.w; \
    acc[3][0]+=a.w*b.x; acc[3][1]+=a.w*b.y; acc[3][2]+=a.w*b.z; acc[3][3]+=a.w*b.w; \
  }

// ---------------- landmark conv (im2col GEMM) + LayerNorm + GELU + ql2 ----------------
__global__ __launch_bounds__(256) void k_land(const float* __restrict__ Q,
        const float* __restrict__ W, const float* __restrict__ gamma,
        const float* __restrict__ beta) {
  __shared__ __align__(16) float As[16][68];
  __shared__ __align__(16) float Bs[16][68];
  __shared__ __align__(16) float Cs[64][68];
  int bh = blockIdx.z;
  int m0 = blockIdx.y * 64;
  int tid = threadIdx.x, tx = tid & 15, ty = tid >> 4;
  const float* Qb = Q + (size_t)bh * SN * 64;
  float acc[4][4] = {};
  for (int k0 = 0; k0 < 1024; k0 += 16) {
    #pragma unroll
    for (int l = 0; l < 4; l++) {
      int idx = tid + l * 256;
      { int ii = idx >> 4, kk = idx & 15;
        int m = m0 + ii, k = k0 + kk;
        float v = 0.f;
        if (m < SM) {
          int pix = k >> 6, ci = k & 63;
          int ry = pix >> 2, rx = pix & 3;
          int py = m / 14, px = m % 14;
          int n = (py * 4 + ry) * SHW + px * 4 + rx;
          v = Qb[n * 64 + ci] * QS;
        }
        As[kk][ii] = v;
      }
      { int kk = idx >> 6, jj = idx & 63;
        Bs[kk][jj] = W[(k0 + kk) * 64 + jj];
      }
    }
    __syncthreads();
    GEMM_CORE(As, Bs)
    __syncthreads();
  }
  #pragma unroll
  for (int i = 0; i < 4; i++)
    #pragma unroll
    for (int j = 0; j < 4; j++)
      Cs[ty * 4 + i][tx * 4 + j] = acc[i][j];
  __syncthreads();
  if (tid < 64) {
    int p = m0 + tid;
    if (p < SM) {
      float mu = 0.f;
      #pragma unroll 8
      for (int j = 0; j < 64; j++) mu += Cs[tid][j];
      mu *= (1.f / 64.f);
      float s2 = 0.f;
      #pragma unroll 8
      for (int j = 0; j < 64; j++) { float d = Cs[tid][j] - mu; s2 += d * d; }
      float r = rsqrtf(s2 * (1.f / 64.f) + 1e-5f);
      float q2 = 0.f;
      float* o = g_Ql + ((size_t)bh * SM + p) * 64;
      for (int j = 0; j < 64; j++) {
        float g = (Cs[tid][j] - mu) * r * gamma[j] + beta[j];
        g = 0.5f * g * (1.f + erff(g * 0.7071067811865476f));
        q2 += g * g;
        o[j] = g;
      }
      g_ql2[bh * SM + p] = q2;
    }
  }
}

// ---------------- |scaled q_n|^2 ----------------
__global__ __launch_bounds__(256) void k_qn2(const float* __restrict__ Q) {
  int bh = blockIdx.y;
  int warp = threadIdx.x >> 5, lane = threadIdx.x & 31;
  int n = blockIdx.x * 8 + warp;
  const float* q = Q + ((size_t)bh * SN + n) * 64;
  float v0 = q[lane], v1 = q[lane + 32];
  float s = v0 * v0 + v1 * v1;
  #pragma unroll
  for (int o = 16; o; o >>= 1) s += __shfl_xor_sync(0xffffffffu, s, o);
  if (lane == 0) g_qn2[bh * SN + n] = s * (QS * QS);
}

// ---------------- gauss kernel GEMM: C = exp(dot(A,B) - 0.5(a2+b2)) ----------------
__global__ __launch_bounds__(256) void k_gauss(const float* __restrict__ A,
     const float* __restrict__ B, const float* __restrict__ a2v,
     const float* __restrict__ b2v, float* __restrict__ C,
     int Ma, int Nb, float ascale) {
  __shared__ __align__(16) float As[16][68];
  __shared__ __align__(16) float Bs[16][68];
  int bh = blockIdx.z;
  int m0 = blockIdx.y * 64, n0 = blockIdx.x * 64;
  int tid = threadIdx.x, tx = tid & 15, ty = tid >> 4;
  A += (size_t)bh * Ma * 64;  B += (size_t)bh * Nb * 64;
  a2v += (size_t)bh * Ma;     b2v += (size_t)bh * Nb;
  C += (size_t)bh * Ma * Nb;
  float acc[4][4] = {};
  for (int k0 = 0; k0 < 64; k0 += 16) {
    #pragma unroll
    for (int l = 0; l < 4; l++) {
      int idx = tid + l * 256;
      { int ii = idx >> 4, kk = idx & 15; int m = m0 + ii;
        As[kk][ii] = (m < Ma) ? A[m * 64 + k0 + kk] * ascale : 0.f; }
      { int jj = idx >> 4, kk = idx & 15; int n = n0 + jj;
        Bs[kk][jj] = (n < Nb) ? B[n * 64 + k0 + kk] : 0.f; }
    }
    __syncthreads();
    GEMM_CORE(As, Bs)
    __syncthreads();
  }
  #pragma unroll
  for (int i = 0; i < 4; i++) {
    int m = m0 + ty * 4 + i; if (m >= Ma) continue;
    float am = a2v[m];
    #pragma unroll
    for (int j = 0; j < 4; j++) {
      int n = n0 + tx * 4 + j; if (n >= Nb) continue;
      C[(size_t)m * Nb + n] = expf(acc[i][j] - 0.5f * (am + b2v[n]));
    }
  }
}

// ---------------- NS scale: g_nsc = 1/(n1*ninf); P symmetric => n1 == ninf ----------------
__global__ __launch_bounds__(256) void k_scale() {
  int bh = blockIdx.x;
  const float* P = g_P + (size_t)bh * SM * SM;
  __shared__ float red[256];
  int tid = threadIdx.x;
  float rs = 0.f;
  if (tid < SM) {
    for (int j = 0; j < SM; j++) rs += fabsf(P[tid * SM + j]);
  }
  red[tid] = rs; __syncthreads();
  for (int s = 128; s > 0; s >>= 1) { if (tid < s) red[tid] = fmaxf(red[tid], red[tid + s]); __syncthreads(); }
  if (tid == 0) g_nsc[bh] = 1.f / (red[0] * red[0]);
}

// ---------------- pad + bf16 quantize of P and V0 ----------------
__global__ __launch_bounds__(256) void k_pad() {
  int bh = blockIdx.y, row = blockIdx.x, j = threadIdx.x;
  float s = g_nsc[bh];
  float v = (row < SM && j < SM) ? g_P[(size_t)bh * SM * SM + row * SM + j] : 0.f;
  size_t o = (size_t)bh * NSE + row * NSP + j;
  g_Pb[o] = __float2bfloat16(v);
  g_Va[o] = __float2bfloat16(v * s);
}

// ---------------- HMMA NS GEMM: D = A @ B^T (both row-major [256x256] bf16) ----------
// All NS iterates are symmetric (polynomials in symmetric P), so B^T == B.
// mode 0:  O(bf16) = D                 (T = V @ P)
// mode 1:  O(bf16) = 2*Vep - D         (Vnext = 2V - V @ T)
// mode 2:  g_V1(fp32, 196x196) = 2*Vep - D   (final iteration, no bf16 roundtrip)
// CTA: 128x128 tile, 8 warps (4x2), warp tile 32x64, BK=32.
__global__ __launch_bounds__(256) void k_nsmm(
    const __nv_bfloat16* __restrict__ Ag, const __nv_bfloat16* __restrict__ Bg,
    const __nv_bfloat16* __restrict__ Vep, __nv_bfloat16* __restrict__ O, int mode) {
  __shared__ __align__(16) __nv_bfloat16 sA[128][40];
  __shared__ __align__(16) __nv_bfloat16 sB[128][40];
  int tid = threadIdx.x, w = tid >> 5, lane = tid & 31;
  int gid = lane >> 2, tig = lane & 3;
  int wm = w & 3, wn = w >> 2;                    // warp grid 4x2
  int bh = blockIdx.z, m0 = blockIdx.y * 128, n0 = blockIdx.x * 128;
  size_t base = (size_t)bh * NSE;

  const uint4* gA = (const uint4*)(Ag + base);
  const uint4* gB = (const uint4*)(Bg + base);

  float acc[2][8][4] = {};

  int r0 = tid >> 2, seg = tid & 3;               // 64 rows per pass, 4 segs of 8 bf16
  for (int kc = 0; kc < 8; kc++) {
    #pragma unroll
    for (int rr = 0; rr < 2; rr++) {
      int r = r0 + rr * 64;
      *(uint4*)&sA[r][seg * 8] = gA[(m0 + r) * 32 + kc * 4 + seg];
      *(uint4*)&sB[r][seg * 8] = gB[(n0 + r) * 32 + kc * 4 + seg];
    }
    __syncthreads();
    #pragma unroll
    for (int ks = 0; ks < 2; ks++) {
      int kb = ks * 16;
      uint32_t af[2][4], bf[8][2];
      #pragma unroll
      for (int mt = 0; mt < 2; mt++) {
        int row = wm * 32 + mt * 16 + gid;
        af[mt][0] = *(const uint32_t*)&sA[row][kb + tig * 2];
        af[mt][1] = *(const uint32_t*)&sA[row + 8][kb + tig * 2];
        af[mt][2] = *(const uint32_t*)&sA[row][kb + 8 + tig * 2];
        af[mt][3] = *(const uint32_t*)&sA[row + 8][kb + 8 + tig * 2];
      }
      #pragma unroll
      for (int nt = 0; nt < 8; nt++) {
        int brow = wn * 64 + nt * 8 + gid;
        bf[nt][0] = *(const uint32_t*)&sB[brow][kb + tig * 2];
        bf[nt][1] = *(const uint32_t*)&sB[brow][kb + 8 + tig * 2];
      }
      #pragma unroll
      for (int mt = 0; mt < 2; mt++)
        #pragma unroll
        for (int nt = 0; nt < 8; nt++)
          mma16816(acc[mt][nt], af[mt], bf[nt]);
    }
    __syncthreads();
  }

  // epilogue: c0,c1 -> (row, col..col+1); c2,c3 -> (row+8, col..col+1)
  #pragma unroll
  for (int mt = 0; mt < 2; mt++) {
    #pragma unroll
    for (int nt = 0; nt < 8; nt++) {
      int row = m0 + wm * 32 + mt * 16 + gid;
      int col = n0 + wn * 64 + nt * 8 + tig * 2;
      #pragma unroll
      for (int half = 0; half < 2; half++) {
        int r = row + half * 8;
        float d0 = acc[mt][nt][half * 2], d1 = acc[mt][nt][half * 2 + 1];
        size_t off = base + (size_t)r * NSP + col;
        if (mode >= 1) {
          uint32_t vp = *(const uint32_t*)(Vep + off);
          float v0 = __bfloat162float(__ushort_as_bfloat16((uint16_t)vp));
          float v1 = __bfloat162float(__ushort_as_bfloat16((uint16_t)(vp >> 16)));
          d0 = 2.f * v0 - d0;
          d1 = 2.f * v1 - d1;
        }
        if (mode == 2) {
          if (r < SM) {
            float* vb = g_V1 + (size_t)bh * SM * SM + (size_t)r * SM;
            if (col < SM)     vb[col]     = d0;
            if (col + 1 < SM) vb[col + 1] = d1;
          }
        } else {
          *(uint32_t*)(O + off) = pack2(__float2bfloat16(d0), __float2bfloat16(d1));
        }
      }
    }
  }
}

// ---------------- Z = k1^T @ V   [196 x 64, K=3136] ----------------
__global__ __launch_bounds__(256) void k_Z(const float* __restrict__ V) {
  __shared__ __align__(16) float As[16][68];
  __shared__ __align__(16) float Bs[16][68];
  int bh = blockIdx.z;
  int m0 = blockIdx.y * 64;
  int tid = threadIdx.x, tx = tid & 15, ty = tid >> 4;
  const float* k1b = g_k1 + (size_t)bh * SN * SM;
  const float* Vb = V + (size_t)bh * SN * 64;
  float* Zb = g_Z + (size_t)bh * SM * 64;
  float acc[4][4] = {};
  for (int k0 = 0; k0 < SN; k0 += 16) {
    #pragma unroll
    for (int l = 0; l < 4; l++) {
      int idx = tid + l * 256;
      { int kk = idx >> 6, ii = idx & 63; int m = m0 + ii;
        As[kk][ii] = (m < SM) ? k1b[(size_t)(k0 + kk) * SM + m] : 0.f; }
      { int kk = idx >> 6, jj = idx & 63;
        Bs[kk][jj] = Vb[(k0 + kk) * 64 + jj]; }
    }
    __syncthreads();
    GEMM_CORE(As, Bs)
    __syncthreads();
  }
  #pragma unroll
  for (int i = 0; i < 4; i++) {
    int m = m0 + ty * 4 + i; if (m >= SM) continue;
    #pragma unroll
    for (int j = 0; j < 4; j++) {
      int n = tx * 4 + j;
      Zb[m * 64 + n] = acc[i][j];
    }
  }
}

// ---------------- Y = inv @ Z   [196 x 64, K=196] ----------------
__global__ __launch_bounds__(256) void k_Y() {
  __shared__ __align__(16) float As[16][68];
  __shared__ __align__(16) float Bs[16][68];
  int bh = blockIdx.z;
  int m0 = blockIdx.y * 64;
  int tid = threadIdx.x, tx = tid & 15, ty = tid >> 4;
  const float* Ib = g_V1 + (size_t)bh * SM * SM;
  const float* Zb = g_Z + (size_t)bh * SM * 64;
  float* Yb = g_Y + (size_t)bh * SM * 64;
  float acc[4][4] = {};
  for (int k0 = 0; k0 < SM; k0 += 16) {
    #pragma unroll
    for (int l = 0; l < 4; l++) {
      int idx = tid + l * 256;
      { int ii = idx >> 4, kk = idx & 15; int m = m0 + ii, k = k0 + kk;
        As[kk][ii] = (m < SM && k < SM) ? Ib[m * SM + k] : 0.f; }
      { int kk = idx >> 6, jj = idx & 63; int k = k0 + kk;
        Bs[kk][jj] = (k < SM) ? Zb[k * 64 + jj] : 0.f; }
    }
    __syncthreads();
    GEMM_CORE(As, Bs)
    __syncthreads();
  }
  #pragma unroll
  for (int i = 0; i < 4; i++) {
    int m = m0 + ty * 4 + i; if (m >= SM) continue;
    #pragma unroll
    for (int j = 0; j < 4; j++) {
      int n = tx * 4 + j;
      Yb[m * 64 + n] = acc[i][j];
    }
  }
}

// ---------------- depthwise 3x3 conv residual -> d_out ----------------
__global__ __launch_bounds__(256) void k_conv(const float* __restrict__ V,
        const float* __restrict__ cw, float* __restrict__ out) {
  int bh = blockIdx.y;
  int h = bh & 7;
  int e = blockIdx.x * 256 + threadIdx.x;
  int c = e & 63, n = e >> 6;
  int y = n / SHW, x = n % SHW;
  const float* Vb = V + (size_t)bh * SN * 64;
  float acc = 0.f;
  #pragma unroll
  for (int dy = -1; dy <= 1; dy++)
    #pragma unroll
    for (int dx = -1; dx <= 1; dx++) {
      int yy = y + dy, xx = x + dx;
      if ((unsigned)yy < SHW && (unsigned)xx < SHW)
        acc += cw[((dy + 1) * 3 + (dx + 1)) * 8 + h] * Vb[(yy * SHW + xx) * 64 + c];
    }
  out[(size_t)bh * SN * 64 + e] = acc;
}

// ---------------- out += k1 @ Y   [3136 x 64, K=196] ----------------
__global__ __launch_bounds__(256) void k_X(float* __restrict__ out) {
  __shared__ __align__(16) float As[16][68];
  __shared__ __align__(16) float Bs[16][68];
  int bh = blockIdx.z;
  int m0 = blockIdx.y * 64;
  int tid = threadIdx.x, tx = tid & 15, ty = tid >> 4;
  const float* k1b = g_k1 + (size_t)bh * SN * SM;
  const float* Yb = g_Y + (size_t)bh * SM * 64;
  float* ob = out + (size_t)bh * SN * 64;
  float acc[4][4] = {};
  for (int k0 = 0; k0 < SM; k0 += 16) {
    #pragma unroll
    for (int l = 0; l < 4; l++) {
      int idx = tid + l * 256;
      { int ii = idx >> 4, kk = idx & 15; int k = k0 + kk;
        As[kk][ii] = (k < SM) ? k1b[(size_t)(m0 + ii) * SM + k] : 0.f; }
      { int kk = idx >> 6, jj = idx & 63; int k = k0 + kk;
        Bs[kk][jj] = (k < SM) ? Yb[k * 64 + jj] : 0.f; }
    }
    __syncthreads();
    GEMM_CORE(As, Bs)
    __syncthreads();
  }
  #pragma unroll
  for (int i = 0; i < 4; i++) {
    int m = m0 + ty * 4 + i;
    #pragma unroll
    for (int j = 0; j < 4; j++) {
      int n = tx * 4 + j;
      ob[m * 64 + n] += acc[i][j];
    }
  }
}

// ---------------- host launch ----------------
extern "C" void kernel_launch(void* const* d_in, const int* in_sizes, int n_in,
                              void* d_out, int out_size) {
  const float* Q     = (const float*)d_in[0];
  const float* V     = (const float*)d_in[1];
  const float* wl    = (const float*)d_in[2];
  const float* gamma = (const float*)d_in[3];
  const float* beta  = (const float*)d_in[4];
  const float* cw    = (const float*)d_in[5];
  float* out = (float*)d_out;

  float *pQl, *pql2, *pqn2, *pk1, *pP;
  cudaGetSymbolAddress((void**)&pQl,  g_Ql);
  cudaGetSymbolAddress((void**)&pql2, g_ql2);
  cudaGetSymbolAddress((void**)&pqn2, g_qn2);
  cudaGetSymbolAddress((void**)&pk1,  g_k1);
  cudaGetSymbolAddress((void**)&pP,   g_P);

  __nv_bfloat16 *pPb, *pVa, *pVb, *pT;
  cudaGetSymbolAddress((void**)&pPb, g_Pb);
  cudaGetSymbolAddress((void**)&pVa, g_Va);
  cudaGetSymbolAddress((void**)&pVb, g_Vb);
  cudaGetSymbolAddress((void**)&pT,  g_Tt);

  // landmarks (conv + LN + GELU + |ql|^2)
  k_land<<<dim3(1, 4, SBH), 256>>>(Q, wl, gamma, beta);
  // |scaled q|^2
  k_qn2<<<dim3(SN / 8, SBH), 256>>>(Q);
  // k2 = gauss(Ql, Ql) -> g_P
  k_gauss<<<dim3(4, 4, SBH), 256>>>(pQl, pQl, pql2, pql2, pP, SM, SM, 1.f);
  // NS scale + bf16 padded operands
  k_scale<<<SBH, 256>>>();
  k_pad<<<dim3(NSP, SBH), 256>>>();
  // 20 Newton-Schulz iterations on HMMA (bf16, fp32 accum); last writes fp32 g_V1
  __nv_bfloat16 *ch = pVa, *oh = pVb;
  dim3 nsg(2, 2, SBH);
  for (int i = 0; i < 20; i++) {
    // T = V @ P (= V @ P^T, P symmetric)
    k_nsmm<<<nsg, 256>>>(ch, pPb, nullptr, pT, 0);
    // Vnext = 2V - V @ T (= V @ T^T, T symmetric); final iter -> fp32 g_V1
    k_nsmm<<<nsg, 256>>>(ch, pT, ch, oh, (i == 19) ? 2 : 1);
    __nv_bfloat16* t = ch; ch = oh; oh = t;
  }
  // k1 = gauss(Qs, Ql) -> g_k1
  k_gauss<<<dim3(4, 49, SBH), 256>>>(Q, pQl, pqn2, pql2, pk1, SN, SM, QS);
  // Z = k1^T V ; Y = inv Z
  k_Z<<<dim3(1, 4, SBH), 256>>>(V);
  k_Y<<<dim3(1, 4, SBH), 256>>>();
  // depthwise conv residual writes d_out, then out += k1 Y
  k_conv<<<dim3(784, SBH), 256>>>(V, cw, out);
  k_X<<<dim3(1, 49, SBH), 256>>>(out);
}

// round 6
// speedup vs baseline: 2.5129x; 1.2123x over previous
#include <cuda_runtime.h>
#include <cuda_bf16.h>
#include <math.h>
#include <stdint.h>

#define SBH 128
#define SN  3136
#define SM  196
#define SMP 208                    /* k1 row stride, float4-aligned, zero-padded */
#define SHW 56
#define QS  0.35355339059327379f   /* 64^-0.25 */
#define NSP 256
#define NSE ((size_t)(NSP*NSP))

// ---------------- scratch (static device globals; no allocation) ----------------
__device__ float g_Ql [SBH*SM*64];
__device__ float g_ql2[SBH*SM];
__device__ float g_qn2[SBH*SN];
__device__ float g_k1 [(size_t)SBH*SN*SMP];    // 334 MB, padded rows
__device__ float g_P  [SBH*SM*SM];
__device__ float g_V1 [SBH*SM*SM];
__device__ float g_Z  [SBH*SM*64];
__device__ float g_Y  [SBH*SM*64];
__device__ float g_nsc[SBH];
// bf16 NS operands, padded to 256x256
__device__ __nv_bfloat16 g_Pb[SBH*NSE];
__device__ __nv_bfloat16 g_Va[SBH*NSE];
__device__ __nv_bfloat16 g_Vb[SBH*NSE];
__device__ __nv_bfloat16 g_Tt[SBH*NSE];

// ================= helpers =================
__device__ __forceinline__ uint32_t pack2(__nv_bfloat16 a, __nv_bfloat16 b) {
  return (uint32_t)__bfloat16_as_ushort(a) | ((uint32_t)__bfloat16_as_ushort(b) << 16);
}
__device__ __forceinline__ void mma16816(float* c, const uint32_t* a, const uint32_t* b) {
  asm volatile(
    "mma.sync.aligned.m16n8k16.row.col.f32.bf16.bf16.f32 "
    "{%0,%1,%2,%3}, {%4,%5,%6,%7}, {%8,%9}, {%0,%1,%2,%3};"
    : "+f"(c[0]), "+f"(c[1]), "+f"(c[2]), "+f"(c[3])
    : "r"(a[0]), "r"(a[1]), "r"(a[2]), "r"(a[3]), "r"(b[0]), "r"(b[1]));
}
__device__ __forceinline__ uint32_t cvt_tf32(float x) {
  uint32_t r; asm("cvt.rna.tf32.f32 %0, %1;" : "=r"(r) : "f"(x)); return r;
}
__device__ __forceinline__ void mma_tf32(float* c, const uint32_t* a, const uint32_t* b) {
  asm volatile(
    "mma.sync.aligned.m16n8k8.row.col.f32.tf32.tf32.f32 "
    "{%0,%1,%2,%3}, {%4,%5,%6,%7}, {%8,%9}, {%0,%1,%2,%3};"
    : "+f"(c[0]), "+f"(c[1]), "+f"(c[2]), "+f"(c[3])
    : "r"(a[0]), "r"(a[1]), "r"(a[2]), "r"(a[3]), "r"(b[0]), "r"(b[1]));
}
// MUFU-free exp: 2^(x*log2e), deg-6 poly on [-0.5,0.5] + exponent bit inject.
__device__ __forceinline__ float fexp(float x) {
  float t = x * 1.4426950408889634f;
  float j = rintf(t);
  float f = t - j;
  float p = 1.53958971e-4f;
  p = fmaf(p, f, 1.33336498e-3f);
  p = fmaf(p, f, 9.61817851e-3f);
  p = fmaf(p, f, 5.55041087e-2f);
  p = fmaf(p, f, 2.40226507e-1f);
  p = fmaf(p, f, 6.93147181e-1f);
  p = fmaf(p, f, 1.0f);
  j = fmaxf(j, -126.f);
  return p * __int_as_float(((int)j + 127) << 23);
}

// 64x64 tile, BK=16, 256 threads, 4x4 micro-tile (SIMT fp32 GEMM core)
#define GEMM_CORE(As,Bs) \
  _Pragma("unroll") \
  for (int kk = 0; kk < 16; kk++) { \
    float4 a = *(const float4*)(&As[kk][ty*4]); \
    float4 b = *(const float4*)(&Bs[kk][tx*4]); \
    acc[0][0]+=a.x*b.x; acc[0][1]+=a.x*b.y; acc[0][2]+=a.x*b.z; acc[0][3]+=a.x*b.w; \
    acc[1][0]+=a.y*b.x; acc[1][1]+=a.y*b.y; acc[1][2]+=a.y*b.z; acc[1][3]+=a.y*b.w; \
    acc[2][0]+=a.z*b.x; acc[2][1]+=a.z*b.y; acc[2][2]+=a.z*b.z; acc[2][3]+=a.z*b.w; \
    acc[3][0]+=a.w*b.x; acc[3][1]+=a.w*b.y; acc[3][2]+=a.w*b.z; acc[3][3]+=a.w*b.w; \
  }

// ---------------- landmark conv (im2col GEMM) + LayerNorm + GELU + ql2 ----------------
__global__ __launch_bounds__(256) void k_land(const float* __restrict__ Q,
        const float* __restrict__ W, const float* __restrict__ gamma,
        const float* __restrict__ beta) {
  __shared__ __align__(16) float As[16][68];
  __shared__ __align__(16) float Bs[16][68];
  __shared__ __align__(16) float Cs[64][68];
  int bh = blockIdx.z;
  int m0 = blockIdx.y * 64;
  int tid = threadIdx.x, tx = tid & 15, ty = tid >> 4;
  const float* Qb = Q + (size_t)bh * SN * 64;
  float acc[4][4] = {};
  for (int k0 = 0; k0 < 1024; k0 += 16) {
    #pragma unroll
    for (int l = 0; l < 4; l++) {
      int idx = tid + l * 256;
      { int ii = idx >> 4, kk = idx & 15;
        int m = m0 + ii, k = k0 + kk;
        float v = 0.f;
        if (m < SM) {
          int pix = k >> 6, ci = k & 63;
          int ry = pix >> 2, rx = pix & 3;
          int py = m / 14, px = m % 14;
          int n = (py * 4 + ry) * SHW + px * 4 + rx;
          v = Qb[n * 64 + ci] * QS;
        }
        As[kk][ii] = v;
      }
      { int kk = idx >> 6, jj = idx & 63;
        Bs[kk][jj] = W[(k0 + kk) * 64 + jj];
      }
    }
    __syncthreads();
    GEMM_CORE(As, Bs)
    __syncthreads();
  }
  #pragma unroll
  for (int i = 0; i < 4; i++)
    #pragma unroll
    for (int j = 0; j < 4; j++)
      Cs[ty * 4 + i][tx * 4 + j] = acc[i][j];
  __syncthreads();
  if (tid < 64) {
    int p = m0 + tid;
    if (p < SM) {
      float mu = 0.f;
      #pragma unroll 8
      for (int j = 0; j < 64; j++) mu += Cs[tid][j];
      mu *= (1.f / 64.f);
      float s2 = 0.f;
      #pragma unroll 8
      for (int j = 0; j < 64; j++) { float d = Cs[tid][j] - mu; s2 += d * d; }
      float r = rsqrtf(s2 * (1.f / 64.f) + 1e-5f);
      float q2 = 0.f;
      float* o = g_Ql + ((size_t)bh * SM + p) * 64;
      for (int j = 0; j < 64; j++) {
        float g = (Cs[tid][j] - mu) * r * gamma[j] + beta[j];
        g = 0.5f * g * (1.f + erff(g * 0.7071067811865476f));
        q2 += g * g;
        o[j] = g;
      }
      g_ql2[bh * SM + p] = q2;
    }
  }
}

// ---------------- |scaled q_n|^2 ----------------
__global__ __launch_bounds__(256) void k_qn2(const float* __restrict__ Q) {
  int bh = blockIdx.y;
  int warp = threadIdx.x >> 5, lane = threadIdx.x & 31;
  int n = blockIdx.x * 8 + warp;
  const float* q = Q + ((size_t)bh * SN + n) * 64;
  float v0 = q[lane], v1 = q[lane + 32];
  float s = v0 * v0 + v1 * v1;
  #pragma unroll
  for (int o = 16; o; o >>= 1) s += __shfl_xor_sync(0xffffffffu, s, o);
  if (lane == 0) g_qn2[bh * SN + n] = s * (QS * QS);
}

// ---------------- gauss kernel GEMM (P only): C = exp(dot - 0.5(a2+b2)) ----------------
__global__ __launch_bounds__(256) void k_gauss(const float* __restrict__ A,
     const float* __restrict__ B, const float* __restrict__ a2v,
     const float* __restrict__ b2v, float* __restrict__ C,
     int Ma, int Nb, float ascale) {
  __shared__ __align__(16) float As[16][68];
  __shared__ __align__(16) float Bs[16][68];
  int bh = blockIdx.z;
  int m0 = blockIdx.y * 64, n0 = blockIdx.x * 64;
  int tid = threadIdx.x, tx = tid & 15, ty = tid >> 4;
  A += (size_t)bh * Ma * 64;  B += (size_t)bh * Nb * 64;
  a2v += (size_t)bh * Ma;     b2v += (size_t)bh * Nb;
  C += (size_t)bh * Ma * Nb;
  float acc[4][4] = {};
  for (int k0 = 0; k0 < 64; k0 += 16) {
    #pragma unroll
    for (int l = 0; l < 4; l++) {
      int idx = tid + l * 256;
      { int ii = idx >> 4, kk = idx & 15; int m = m0 + ii;
        As[kk][ii] = (m < Ma) ? A[m * 64 + k0 + kk] * ascale : 0.f; }
      { int jj = idx >> 4, kk = idx & 15; int n = n0 + jj;
        Bs[kk][jj] = (n < Nb) ? B[n * 64 + k0 + kk] : 0.f; }
    }
    __syncthreads();
    GEMM_CORE(As, Bs)
    __syncthreads();
  }
  #pragma unroll
  for (int i = 0; i < 4; i++) {
    int m = m0 + ty * 4 + i; if (m >= Ma) continue;
    float am = a2v[m];
    #pragma unroll
    for (int j = 0; j < 4; j++) {
      int n = n0 + tx * 4 + j; if (n >= Nb) continue;
      C[(size_t)m * Nb + n] = expf(acc[i][j] - 0.5f * (am + b2v[n]));
    }
  }
}

// ---------------- NS scale: g_nsc = 1/(n1*ninf); P symmetric => n1 == ninf ----------------
__global__ __launch_bounds__(256) void k_scale() {
  int bh = blockIdx.x;
  const float* P = g_P + (size_t)bh * SM * SM;
  __shared__ float red[256];
  int tid = threadIdx.x;
  float rs = 0.f;
  if (tid < SM) {
    for (int j = 0; j < SM; j++) rs += fabsf(P[tid * SM + j]);
  }
  red[tid] = rs; __syncthreads();
  for (int s = 128; s > 0; s >>= 1) { if (tid < s) red[tid] = fmaxf(red[tid], red[tid + s]); __syncthreads(); }
  if (tid == 0) g_nsc[bh] = 1.f / (red[0] * red[0]);
}

// ---------------- pad + bf16 quantize of P and V0 ----------------
__global__ __launch_bounds__(256) void k_pad() {
  int bh = blockIdx.y, row = blockIdx.x, j = threadIdx.x;
  float s = g_nsc[bh];
  float v = (row < SM && j < SM) ? g_P[(size_t)bh * SM * SM + row * SM + j] : 0.f;
  size_t o = (size_t)bh * NSE + row * NSP + j;
  g_Pb[o] = __float2bfloat16(v);
  g_Va[o] = __float2bfloat16(v * s);
}

// ---------------- HMMA NS GEMM: D = A @ B^T (both row-major [256x256] bf16) ----------
// mode 0: O(bf16)=D ; mode 1: O(bf16)=2*Vep-D ; mode 2: g_V1(fp32 196x196)=2*Vep-D
__global__ __launch_bounds__(256) void k_nsmm(
    const __nv_bfloat16* __restrict__ Ag, const __nv_bfloat16* __restrict__ Bg,
    const __nv_bfloat16* __restrict__ Vep, __nv_bfloat16* __restrict__ O, int mode) {
  __shared__ __align__(16) __nv_bfloat16 sA[128][40];
  __shared__ __align__(16) __nv_bfloat16 sB[128][40];
  int tid = threadIdx.x, w = tid >> 5, lane = tid & 31;
  int gid = lane >> 2, tig = lane & 3;
  int wm = w & 3, wn = w >> 2;
  int bh = blockIdx.z, m0 = blockIdx.y * 128, n0 = blockIdx.x * 128;
  size_t base = (size_t)bh * NSE;
  const uint4* gA = (const uint4*)(Ag + base);
  const uint4* gB = (const uint4*)(Bg + base);
  float acc[2][8][4] = {};
  int r0 = tid >> 2, seg = tid & 3;
  for (int kc = 0; kc < 8; kc++) {
    #pragma unroll
    for (int rr = 0; rr < 2; rr++) {
      int r = r0 + rr * 64;
      *(uint4*)&sA[r][seg * 8] = gA[(m0 + r) * 32 + kc * 4 + seg];
      *(uint4*)&sB[r][seg * 8] = gB[(n0 + r) * 32 + kc * 4 + seg];
    }
    __syncthreads();
    #pragma unroll
    for (int ks = 0; ks < 2; ks++) {
      int kb = ks * 16;
      uint32_t af[2][4], bf[8][2];
      #pragma unroll
      for (int mt = 0; mt < 2; mt++) {
        int row = wm * 32 + mt * 16 + gid;
        af[mt][0] = *(const uint32_t*)&sA[row][kb + tig * 2];
        af[mt][1] = *(const uint32_t*)&sA[row + 8][kb + tig * 2];
        af[mt][2] = *(const uint32_t*)&sA[row][kb + 8 + tig * 2];
        af[mt][3] = *(const uint32_t*)&sA[row + 8][kb + 8 + tig * 2];
      }
      #pragma unroll
      for (int nt = 0; nt < 8; nt++) {
        int brow = wn * 64 + nt * 8 + gid;
        bf[nt][0] = *(const uint32_t*)&sB[brow][kb + tig * 2];
        bf[nt][1] = *(const uint32_t*)&sB[brow][kb + 8 + tig * 2];
      }
      #pragma unroll
      for (int mt = 0; mt < 2; mt++)
        #pragma unroll
        for (int nt = 0; nt < 8; nt++)
          mma16816(acc[mt][nt], af[mt], bf[nt]);
    }
    __syncthreads();
  }
  #pragma unroll
  for (int mt = 0; mt < 2; mt++) {
    #pragma unroll
    for (int nt = 0; nt < 8; nt++) {
      int row = m0 + wm * 32 + mt * 16 + gid;
      int col = n0 + wn * 64 + nt * 8 + tig * 2;
      #pragma unroll
      for (int half = 0; half < 2; half++) {
        int r = row + half * 8;
        float d0 = acc[mt][nt][half * 2], d1 = acc[mt][nt][half * 2 + 1];
        size_t off = base + (size_t)r * NSP + col;
        if (mode >= 1) {
          uint32_t vp = *(const uint32_t*)(Vep + off);
          float v0 = __bfloat162float(__ushort_as_bfloat16((uint16_t)vp));
          float v1 = __bfloat162float(__ushort_as_bfloat16((uint16_t)(vp >> 16)));
          d0 = 2.f * v0 - d0;
          d1 = 2.f * v1 - d1;
        }
        if (mode == 2) {
          if (r < SM) {
            float* vb = g_V1 + (size_t)bh * SM * SM + (size_t)r * SM;
            if (col < SM)     vb[col]     = d0;
            if (col + 1 < SM) vb[col + 1] = d1;
          }
        } else {
          *(uint32_t*)(O + off) = pack2(__float2bfloat16(d0), __float2bfloat16(d1));
        }
      }
    }
  }
}

// ---------------- k1 = gauss(Qs, Ql) via tf32 HMMA + poly-exp -> g_k1 [SN][SMP] -------
// CTA 128x128, warps 4x2 (warp tile 32x64), K=64 in 2 chunks of 32.
__global__ __launch_bounds__(256) void k_g1(const float* __restrict__ Q) {
  __shared__ __align__(16) float sA[128][36];
  __shared__ __align__(16) float sB[128][36];
  int tid = threadIdx.x, w = tid >> 5, lane = tid & 31;
  int gid = lane >> 2, tig = lane & 3;
  int wm = w & 3, wn = w >> 2;
  int bh = blockIdx.z, m0 = blockIdx.y * 128, n0 = blockIdx.x * 128;
  const float* Qb = Q + (size_t)bh * SN * 64;
  const float* Qlb = g_Ql + (size_t)bh * SM * 64;
  float acc[2][8][4] = {};
  int r = tid >> 1, hb = (tid & 1) * 4;
  for (int kc = 0; kc < 2; kc++) {
    int k0 = kc * 32;
    int gm = m0 + r, gn = n0 + r;
    #pragma unroll
    for (int e = 0; e < 4; e++) {
      int c = (hb + e) * 4;
      float4 va = make_float4(0.f, 0.f, 0.f, 0.f);
      if (gm < SN) va = *(const float4*)&Qb[(size_t)gm * 64 + k0 + c];
      va.x *= QS; va.y *= QS; va.z *= QS; va.w *= QS;
      *(float4*)&sA[r][c] = va;
      float4 vb = make_float4(0.f, 0.f, 0.f, 0.f);
      if (gn < SM) vb = *(const float4*)&Qlb[(size_t)gn * 64 + k0 + c];
      *(float4*)&sB[r][c] = vb;
    }
    __syncthreads();
    #pragma unroll
    for (int ks = 0; ks < 4; ks++) {
      int kb = ks * 8;
      uint32_t af[2][4], bf[8][2];
      #pragma unroll
      for (int mt = 0; mt < 2; mt++) {
        int row = wm * 32 + mt * 16 + gid;
        af[mt][0] = cvt_tf32(sA[row][kb + tig]);
        af[mt][1] = cvt_tf32(sA[row + 8][kb + tig]);
        af[mt][2] = cvt_tf32(sA[row][kb + tig + 4]);
        af[mt][3] = cvt_tf32(sA[row + 8][kb + tig + 4]);
      }
      #pragma unroll
      for (int nt = 0; nt < 8; nt++) {
        int brow = wn * 64 + nt * 8 + gid;
        bf[nt][0] = cvt_tf32(sB[brow][kb + tig]);
        bf[nt][1] = cvt_tf32(sB[brow][kb + tig + 4]);
      }
      #pragma unroll
      for (int mt = 0; mt < 2; mt++)
        #pragma unroll
        for (int nt = 0; nt < 8; nt++)
          mma_tf32(acc[mt][nt], af[mt], bf[nt]);
    }
    __syncthreads();
  }
  float* k1b = g_k1 + (size_t)bh * SN * SMP;
  const float* qn2b = g_qn2 + (size_t)bh * SN;
  const float* ql2b = g_ql2 + (size_t)bh * SM;
  #pragma unroll
  for (int mt = 0; mt < 2; mt++) {
    #pragma unroll
    for (int half = 0; half < 2; half++) {
      int m = m0 + wm * 32 + mt * 16 + gid + half * 8;
      if (m >= SN) continue;
      float qm = qn2b[m];
      #pragma unroll
      for (int nt = 0; nt < 8; nt++) {
        int n = n0 + wn * 64 + nt * 8 + tig * 2;
        #pragma unroll
        for (int c2 = 0; c2 < 2; c2++) {
          int nn = n + c2;
          if (nn >= SMP) continue;
          float val = 0.f;
          if (nn < SM)
            val = fexp(acc[mt][nt][half * 2 + c2] - 0.5f * (qm + ql2b[nn]));
          k1b[(size_t)m * SMP + nn] = val;
        }
      }
    }
  }
}

// ---------------- Z = k1^T @ V via tf32 HMMA  [196 x 64, K=3136] ---------------------
// CTA 128(M=landmarks) x 64(N=ch), warps 4x2 (32x32), BK=32. A transposed at fill.
__global__ __launch_bounds__(256) void k_Zt(const float* __restrict__ V) {
  __shared__ __align__(16) float sA[128][36];
  __shared__ __align__(16) float sB[32][68];
  int tid = threadIdx.x, w = tid >> 5, lane = tid & 31;
  int gid = lane >> 2, tig = lane & 3;
  int wm = w & 3, wn = w >> 2;
  int bh = blockIdx.z, m0 = blockIdx.y * 128;
  const float* k1b = g_k1 + (size_t)bh * SN * SMP;
  const float* Vb = V + (size_t)bh * SN * 64;
  float acc[2][4][4] = {};
  int tokA = tid & 31, segA = tid >> 5;
  for (int kc = 0; kc < 98; kc++) {
    int k0 = kc * 32;
    const float* k1r = k1b + (size_t)(k0 + tokA) * SMP;
    #pragma unroll
    for (int i = 0; i < 4; i++) {
      int l = segA * 16 + i * 4;
      int gl = m0 + l;
      float4 v = make_float4(0.f, 0.f, 0.f, 0.f);
      if (gl + 3 < SMP) v = *(const float4*)&k1r[gl];
      sA[l][tokA] = v.x; sA[l + 1][tokA] = v.y;
      sA[l + 2][tokA] = v.z; sA[l + 3][tokA] = v.w;
    }
    #pragma unroll
    for (int e = 0; e < 2; e++) {
      int t2 = tid * 2 + e;
      int tok = t2 >> 4, sg = t2 & 15;
      *(float4*)&sB[tok][sg * 4] = *(const float4*)&Vb[(size_t)(k0 + tok) * 64 + sg * 4];
    }
    __syncthreads();
    #pragma unroll
    for (int ks = 0; ks < 4; ks++) {
      int kb = ks * 8;
      uint32_t af[2][4], bf[4][2];
      #pragma unroll
      for (int mt = 0; mt < 2; mt++) {
        int row = wm * 32 + mt * 16 + gid;
        af[mt][0] = cvt_tf32(sA[row][kb + tig]);
        af[mt][1] = cvt_tf32(sA[row + 8][kb + tig]);
        af[mt][2] = cvt_tf32(sA[row][kb + tig + 4]);
        af[mt][3] = cvt_tf32(sA[row + 8][kb + tig + 4]);
      }
      #pragma unroll
      for (int nt = 0; nt < 4; nt++) {
        int nc = wn * 32 + nt * 8 + gid;
        bf[nt][0] = cvt_tf32(sB[kb + tig][nc]);
        bf[nt][1] = cvt_tf32(sB[kb + tig + 4][nc]);
      }
      #pragma unroll
      for (int mt = 0; mt < 2; mt++)
        #pragma unroll
        for (int nt = 0; nt < 4; nt++)
          mma_tf32(acc[mt][nt], af[mt], bf[nt]);
    }
    __syncthreads();
  }
  float* Zb = g_Z + (size_t)bh * SM * 64;
  #pragma unroll
  for (int mt = 0; mt < 2; mt++)
    #pragma unroll
    for (int half = 0; half < 2; half++) {
      int m = m0 + wm * 32 + mt * 16 + gid + half * 8;
      if (m >= SM) continue;
      #pragma unroll
      for (int nt = 0; nt < 4; nt++) {
        int n = wn * 32 + nt * 8 + tig * 2;
        Zb[(size_t)m * 64 + n]     = acc[mt][nt][half * 2];
        Zb[(size_t)m * 64 + n + 1] = acc[mt][nt][half * 2 + 1];
      }
    }
}

// ---------------- Y = inv @ Z   [196 x 64, K=196] (SIMT, small) ----------------
__global__ __launch_bounds__(256) void k_Y() {
  __shared__ __align__(16) float As[16][68];
  __shared__ __align__(16) float Bs[16][68];
  int bh = blockIdx.z;
  int m0 = blockIdx.y * 64;
  int tid = threadIdx.x, tx = tid & 15, ty = tid >> 4;
  const float* Ib = g_V1 + (size_t)bh * SM * SM;
  const float* Zb = g_Z + (size_t)bh * SM * 64;
  float* Yb = g_Y + (size_t)bh * SM * 64;
  float acc[4][4] = {};
  for (int k0 = 0; k0 < SM; k0 += 16) {
    #pragma unroll
    for (int l = 0; l < 4; l++) {
      int idx = tid + l * 256;
      { int ii = idx >> 4, kk = idx & 15; int m = m0 + ii, k = k0 + kk;
        As[kk][ii] = (m < SM && k < SM) ? Ib[m * SM + k] : 0.f; }
      { int kk = idx >> 6, jj = idx & 63; int k = k0 + kk;
        Bs[kk][jj] = (k < SM) ? Zb[k * 64 + jj] : 0.f; }
    }
    __syncthreads();
    GEMM_CORE(As, Bs)
    __syncthreads();
  }
  #pragma unroll
  for (int i = 0; i < 4; i++) {
    int m = m0 + ty * 4 + i; if (m >= SM) continue;
    #pragma unroll
    for (int j = 0; j < 4; j++) {
      int n = tx * 4 + j;
      Yb[m * 64 + n] = acc[i][j];
    }
  }
}

// ---------------- depthwise 3x3 conv residual -> d_out ----------------
__global__ __launch_bounds__(256) void k_conv(const float* __restrict__ V,
        const float* __restrict__ cw, float* __restrict__ out) {
  int bh = blockIdx.y;
  int h = bh & 7;
  int e = blockIdx.x * 256 + threadIdx.x;
  int c = e & 63, n = e >> 6;
  int y = n / SHW, x = n % SHW;
  const float* Vb = V + (size_t)bh * SN * 64;
  float acc = 0.f;
  #pragma unroll
  for (int dy = -1; dy <= 1; dy++)
    #pragma unroll
    for (int dx = -1; dx <= 1; dx++) {
      int yy = y + dy, xx = x + dx;
      if ((unsigned)yy < SHW && (unsigned)xx < SHW)
        acc += cw[((dy + 1) * 3 + (dx + 1)) * 8 + h] * Vb[(yy * SHW + xx) * 64 + c];
    }
  out[(size_t)bh * SN * 64 + e] = acc;
}

// ---------------- out += k1 @ Y via tf32 HMMA  [3136 x 64, K=196(208)] ---------------
__global__ __launch_bounds__(256) void k_Xt(float* __restrict__ out) {
  __shared__ __align__(16) float sA[128][36];
  __shared__ __align__(16) float sB[32][68];
  int tid = threadIdx.x, w = tid >> 5, lane = tid & 31;
  int gid = lane >> 2, tig = lane & 3;
  int wm = w & 3, wn = w >> 2;
  int bh = blockIdx.z, m0 = blockIdx.y * 128;
  const float* k1b = g_k1 + (size_t)bh * SN * SMP;
  const float* Yb = g_Y + (size_t)bh * SM * 64;
  float acc[2][4][4] = {};
  int r = tid >> 1, hb = (tid & 1) * 4;
  for (int kc = 0; kc < 7; kc++) {
    int k0 = kc * 32;
    int gm = m0 + r;
    #pragma unroll
    for (int e = 0; e < 4; e++) {
      int c = (hb + e) * 4;
      int gk = k0 + c;
      float4 v = make_float4(0.f, 0.f, 0.f, 0.f);
      if (gm < SN && gk + 3 < SMP) v = *(const float4*)&k1b[(size_t)gm * SMP + gk];
      *(float4*)&sA[r][c] = v;
    }
    #pragma unroll
    for (int e = 0; e < 2; e++) {
      int t2 = tid * 2 + e;
      int tok = t2 >> 4, sg = t2 & 15;
      int gk = k0 + tok;
      float4 v = make_float4(0.f, 0.f, 0.f, 0.f);
      if (gk < SM) v = *(const float4*)&Yb[(size_t)gk * 64 + sg * 4];
      *(float4*)&sB[tok][sg * 4] = v;
    }
    __syncthreads();
    #pragma unroll
    for (int ks = 0; ks < 4; ks++) {
      int kb = ks * 8;
      uint32_t af[2][4], bf[4][2];
      #pragma unroll
      for (int mt = 0; mt < 2; mt++) {
        int row = wm * 32 + mt * 16 + gid;
        af[mt][0] = cvt_tf32(sA[row][kb + tig]);
        af[mt][1] = cvt_tf32(sA[row + 8][kb + tig]);
        af[mt][2] = cvt_tf32(sA[row][kb + tig + 4]);
        af[mt][3] = cvt_tf32(sA[row + 8][kb + tig + 4]);
      }
      #pragma unroll
      for (int nt = 0; nt < 4; nt++) {
        int nc = wn * 32 + nt * 8 + gid;
        bf[nt][0] = cvt_tf32(sB[kb + tig][nc]);
        bf[nt][1] = cvt_tf32(sB[kb + tig + 4][nc]);
      }
      #pragma unroll
      for (int mt = 0; mt < 2; mt++)
        #pragma unroll
        for (int nt = 0; nt < 4; nt++)
          mma_tf32(acc[mt][nt], af[mt], bf[nt]);
    }
    __syncthreads();
  }
  float* ob = out + (size_t)bh * SN * 64;
  #pragma unroll
  for (int mt = 0; mt < 2; mt++)
    #pragma unroll
    for (int half = 0; half < 2; half++) {
      int m = m0 + wm * 32 + mt * 16 + gid + half * 8;
      if (m >= SN) continue;
      #pragma unroll
      for (int nt = 0; nt < 4; nt++) {
        int n = wn * 32 + nt * 8 + tig * 2;
        ob[(size_t)m * 64 + n]     += acc[mt][nt][half * 2];
        ob[(size_t)m * 64 + n + 1] += acc[mt][nt][half * 2 + 1];
      }
    }
}

// ---------------- host launch ----------------
extern "C" void kernel_launch(void* const* d_in, const int* in_sizes, int n_in,
                              void* d_out, int out_size) {
  const float* Q     = (const float*)d_in[0];
  const float* V     = (const float*)d_in[1];
  const float* wl    = (const float*)d_in[2];
  const float* gamma = (const float*)d_in[3];
  const float* beta  = (const float*)d_in[4];
  const float* cw    = (const float*)d_in[5];
  float* out = (float*)d_out;

  float *pQl, *pql2, *pP;
  cudaGetSymbolAddress((void**)&pQl,  g_Ql);
  cudaGetSymbolAddress((void**)&pql2, g_ql2);
  cudaGetSymbolAddress((void**)&pP,   g_P);

  __nv_bfloat16 *pPb, *pVa, *pVb, *pT;
  cudaGetSymbolAddress((void**)&pPb, g_Pb);
  cudaGetSymbolAddress((void**)&pVa, g_Va);
  cudaGetSymbolAddress((void**)&pVb, g_Vb);
  cudaGetSymbolAddress((void**)&pT,  g_Tt);

  // landmarks (conv + LN + GELU + |ql|^2)
  k_land<<<dim3(1, 4, SBH), 256>>>(Q, wl, gamma, beta);
  // |scaled q|^2
  k_qn2<<<dim3(SN / 8, SBH), 256>>>(Q);
  // k2 = gauss(Ql, Ql) -> g_P
  k_gauss<<<dim3(4, 4, SBH), 256>>>(pQl, pQl, pql2, pql2, pP, SM, SM, 1.f);
  // NS scale + bf16 padded operands
  k_scale<<<SBH, 256>>>();
  k_pad<<<dim3(NSP, SBH), 256>>>();
  // 20 Newton-Schulz iterations on HMMA (bf16, fp32 accum); last writes fp32 g_V1
  __nv_bfloat16 *ch = pVa, *oh = pVb;
  dim3 nsg(2, 2, SBH);
  for (int i = 0; i < 20; i++) {
    k_nsmm<<<nsg, 256>>>(ch, pPb, nullptr, pT, 0);
    k_nsmm<<<nsg, 256>>>(ch, pT, ch, oh, (i == 19) ? 2 : 1);
    __nv_bfloat16* t = ch; ch = oh; oh = t;
  }
  // k1 = gauss(Qs, Ql) via tf32 HMMA -> g_k1 (padded)
  k_g1<<<dim3(2, 25, SBH), 256>>>(Q);
  // Z = k1^T V (tf32 HMMA) ; Y = inv Z (SIMT)
  k_Zt<<<dim3(1, 2, SBH), 256>>>(V);
  k_Y<<<dim3(1, 4, SBH), 256>>>();
  // depthwise conv residual writes d_out, then out += k1 Y (tf32 HMMA)
  k_conv<<<dim3(784, SBH), 256>>>(V, cw, out);
  k_Xt<<<dim3(1, 25, SBH), 256>>>(out);
}

// round 8
// speedup vs baseline: 2.6452x; 1.0527x over previous
#include <cuda_runtime.h>
#include <cuda_bf16.h>
#include <math.h>
#include <stdint.h>

#define SBH 128
#define SN  3136
#define SM  196
#define SMP 208                    /* k1 row stride, float4-aligned, zero-padded */
#define SHW 56
#define QS  0.35355339059327379f   /* 64^-0.25 */
#define NSP 256
#define NSE ((size_t)(NSP*NSP))

// ---------------- scratch (static device globals; no allocation) ----------------
__device__ float g_Ql [SBH*SM*64];
__device__ float g_ql2[SBH*SM];
__device__ float g_qn2[SBH*SN];
__device__ float g_k1 [(size_t)SBH*SN*SMP];    // 334 MB, padded rows
__device__ float g_P  [SBH*SM*SM];
__device__ float g_nsc[SBH];
__device__ __nv_bfloat16 g_Pb[SBH*NSE];        // bf16 P, padded 256x256
__device__ __nv_bfloat16 g_Ea[SBH*NSE];        // E ping
__device__ __nv_bfloat16 g_Eb[SBH*NSE];        // E pong
__device__ float g_y0[SBH*256*64];             // y ping (fp32)
__device__ float g_y1[SBH*256*64];             // y pong

// ================= helpers =================
__device__ __forceinline__ uint32_t pack2(__nv_bfloat16 a, __nv_bfloat16 b) {
  return (uint32_t)__bfloat16_as_ushort(a) | ((uint32_t)__bfloat16_as_ushort(b) << 16);
}
__device__ __forceinline__ void mma16816(float* c, const uint32_t* a, const uint32_t* b) {
  asm volatile(
    "mma.sync.aligned.m16n8k16.row.col.f32.bf16.bf16.f32 "
    "{%0,%1,%2,%3}, {%4,%5,%6,%7}, {%8,%9}, {%0,%1,%2,%3};"
    : "+f"(c[0]), "+f"(c[1]), "+f"(c[2]), "+f"(c[3])
    : "r"(a[0]), "r"(a[1]), "r"(a[2]), "r"(a[3]), "r"(b[0]), "r"(b[1]));
}
__device__ __forceinline__ uint32_t cvt_tf32(float x) {
  uint32_t r; asm("cvt.rna.tf32.f32 %0, %1;" : "=r"(r) : "f"(x)); return r;
}
__device__ __forceinline__ void mma_tf32(float* c, const uint32_t* a, const uint32_t* b) {
  asm volatile(
    "mma.sync.aligned.m16n8k8.row.col.f32.tf32.tf32.f32 "
    "{%0,%1,%2,%3}, {%4,%5,%6,%7}, {%8,%9}, {%0,%1,%2,%3};"
    : "+f"(c[0]), "+f"(c[1]), "+f"(c[2]), "+f"(c[3])
    : "r"(a[0]), "r"(a[1]), "r"(a[2]), "r"(a[3]), "r"(b[0]), "r"(b[1]));
}
__device__ __forceinline__ void cpa16(void* s, const void* g) {
  uint32_t sa = (uint32_t)__cvta_generic_to_shared(s);
  asm volatile("cp.async.cg.shared.global [%0], [%1], 16;" :: "r"(sa), "l"(g));
}
#define CPA_COMMIT asm volatile("cp.async.commit_group;" ::: "memory")
#define CPA_WAIT1  asm volatile("cp.async.wait_group 1;" ::: "memory")
#define CPA_WAIT0  asm volatile("cp.async.wait_group 0;" ::: "memory")
// MUFU-free exp: 2^(x*log2e), deg-6 poly + exponent bit inject.
__device__ __forceinline__ float fexp(float x) {
  float t = x * 1.4426950408889634f;
  float j = rintf(t);
  float f = t - j;
  float p = 1.53958971e-4f;
  p = fmaf(p, f, 1.33336498e-3f);
  p = fmaf(p, f, 9.61817851e-3f);
  p = fmaf(p, f, 5.55041087e-2f);
  p = fmaf(p, f, 2.40226507e-1f);
  p = fmaf(p, f, 6.93147181e-1f);
  p = fmaf(p, f, 1.0f);
  j = fmaxf(j, -126.f);
  return p * __int_as_float(((int)j + 127) << 23);
}

// 64x64 tile, BK=16, 256 threads, 4x4 micro-tile (SIMT fp32 GEMM core)
#define GEMM_CORE(As,Bs) \
  _Pragma("unroll") \
  for (int kk = 0; kk < 16; kk++) { \
    float4 a = *(const float4*)(&As[kk][ty*4]); \
    float4 b = *(const float4*)(&Bs[kk][tx*4]); \
    acc[0][0]+=a.x*b.x; acc[0][1]+=a.x*b.y; acc[0][2]+=a.x*b.z; acc[0][3]+=a.x*b.w; \
    acc[1][0]+=a.y*b.x; acc[1][1]+=a.y*b.y; acc[1][2]+=a.y*b.z; acc[1][3]+=a.y*b.w; \
    acc[2][0]+=a.z*b.x; acc[2][1]+=a.z*b.y; acc[2][2]+=a.z*b.z; acc[2][3]+=a.z*b.w; \
    acc[3][0]+=a.w*b.x; acc[3][1]+=a.w*b.y; acc[3][2]+=a.w*b.z; acc[3][3]+=a.w*b.w; \
  }

// ---------------- landmark conv (im2col GEMM) + LayerNorm + GELU + ql2 ----------------
__global__ __launch_bounds__(256) void k_land(const float* __restrict__ Q,
        const float* __restrict__ W, const float* __restrict__ gamma,
        const float* __restrict__ beta) {
  __shared__ __align__(16) float As[16][68];
  __shared__ __align__(16) float Bs[16][68];
  __shared__ __align__(16) float Cs[64][68];
  int bh = blockIdx.z;
  int m0 = blockIdx.y * 64;
  int tid = threadIdx.x, tx = tid & 15, ty = tid >> 4;
  const float* Qb = Q + (size_t)bh * SN * 64;
  float acc[4][4] = {};
  for (int k0 = 0; k0 < 1024; k0 += 16) {
    #pragma unroll
    for (int l = 0; l < 4; l++) {
      int idx = tid + l * 256;
      { int ii = idx >> 4, kk = idx & 15;
        int m = m0 + ii, k = k0 + kk;
        float v = 0.f;
        if (m < SM) {
          int pix = k >> 6, ci = k & 63;
          int ry = pix >> 2, rx = pix & 3;
          int py = m / 14, px = m % 14;
          int n = (py * 4 + ry) * SHW + px * 4 + rx;
          v = Qb[n * 64 + ci] * QS;
        }
        As[kk][ii] = v;
      }
      { int kk = idx >> 6, jj = idx & 63;
        Bs[kk][jj] = W[(k0 + kk) * 64 + jj];
      }
    }
    __syncthreads();
    GEMM_CORE(As, Bs)
    __syncthreads();
  }
  #pragma unroll
  for (int i = 0; i < 4; i++)
    #pragma unroll
    for (int j = 0; j < 4; j++)
      Cs[ty * 4 + i][tx * 4 + j] = acc[i][j];
  __syncthreads();
  if (tid < 64) {
    int p = m0 + tid;
    if (p < SM) {
      float mu = 0.f;
      #pragma unroll 8
      for (int j = 0; j < 64; j++) mu += Cs[tid][j];
      mu *= (1.f / 64.f);
      float s2 = 0.f;
      #pragma unroll 8
      for (int j = 0; j < 64; j++) { float d = Cs[tid][j] - mu; s2 += d * d; }
      float r = rsqrtf(s2 * (1.f / 64.f) + 1e-5f);
      float q2 = 0.f;
      float* o = g_Ql + ((size_t)bh * SM + p) * 64;
      for (int j = 0; j < 64; j++) {
        float g = (Cs[tid][j] - mu) * r * gamma[j] + beta[j];
        g = 0.5f * g * (1.f + erff(g * 0.7071067811865476f));
        q2 += g * g;
        o[j] = g;
      }
      g_ql2[bh * SM + p] = q2;
    }
  }
}

// ---------------- |scaled q_n|^2 ----------------
__global__ __launch_bounds__(256) void k_qn2(const float* __restrict__ Q) {
  int bh = blockIdx.y;
  int warp = threadIdx.x >> 5, lane = threadIdx.x & 31;
  int n = blockIdx.x * 8 + warp;
  const float* q = Q + ((size_t)bh * SN + n) * 64;
  float v0 = q[lane], v1 = q[lane + 32];
  float s = v0 * v0 + v1 * v1;
  #pragma unroll
  for (int o = 16; o; o >>= 1) s += __shfl_xor_sync(0xffffffffu, s, o);
  if (lane == 0) g_qn2[bh * SN + n] = s * (QS * QS);
}

// ---------------- gauss kernel GEMM (P only): C = exp(dot - 0.5(a2+b2)) ----------------
__global__ __launch_bounds__(256) void k_gauss(const float* __restrict__ A,
     const float* __restrict__ B, const float* __restrict__ a2v,
     const float* __restrict__ b2v, float* __restrict__ C,
     int Ma, int Nb, float ascale) {
  __shared__ __align__(16) float As[16][68];
  __shared__ __align__(16) float Bs[16][68];
  int bh = blockIdx.z;
  int m0 = blockIdx.y * 64, n0 = blockIdx.x * 64;
  int tid = threadIdx.x, tx = tid & 15, ty = tid >> 4;
  A += (size_t)bh * Ma * 64;  B += (size_t)bh * Nb * 64;
  a2v += (size_t)bh * Ma;     b2v += (size_t)bh * Nb;
  C += (size_t)bh * Ma * Nb;
  float acc[4][4] = {};
  for (int k0 = 0; k0 < 64; k0 += 16) {
    #pragma unroll
    for (int l = 0; l < 4; l++) {
      int idx = tid + l * 256;
      { int ii = idx >> 4, kk = idx & 15; int m = m0 + ii;
        As[kk][ii] = (m < Ma) ? A[m * 64 + k0 + kk] * ascale : 0.f; }
      { int jj = idx >> 4, kk = idx & 15; int n = n0 + jj;
        Bs[kk][jj] = (n < Nb) ? B[n * 64 + k0 + kk] : 0.f; }
    }
    __syncthreads();
    GEMM_CORE(As, Bs)
    __syncthreads();
  }
  #pragma unroll
  for (int i = 0; i < 4; i++) {
    int m = m0 + ty * 4 + i; if (m >= Ma) continue;
    float am = a2v[m];
    #pragma unroll
    for (int j = 0; j < 4; j++) {
      int n = n0 + tx * 4 + j; if (n >= Nb) continue;
      C[(size_t)m * Nb + n] = expf(acc[i][j] - 0.5f * (am + b2v[n]));
    }
  }
}

// ---------------- NS scale: g_nsc = 1/(n1*ninf); P symmetric => n1 == ninf ----------------
__global__ __launch_bounds__(256) void k_scale() {
  int bh = blockIdx.x;
  const float* P = g_P + (size_t)bh * SM * SM;
  __shared__ float red[256];
  int tid = threadIdx.x;
  float rs = 0.f;
  if (tid < SM) {
    for (int j = 0; j < SM; j++) rs += fabsf(P[tid * SM + j]);
  }
  red[tid] = rs; __syncthreads();
  for (int s = 128; s > 0; s >>= 1) { if (tid < s) red[tid] = fmaxf(red[tid], red[tid + s]); __syncthreads(); }
  if (tid == 0) g_nsc[bh] = 1.f / (red[0] * red[0]);
}

// ---------------- pad + bf16 quantize of P ----------------
__global__ __launch_bounds__(256) void k_pad() {
  int bh = blockIdx.y, row = blockIdx.x, j = threadIdx.x;
  float v = (row < SM && j < SM) ? g_P[(size_t)bh * SM * SM + row * SM + j] : 0.f;
  g_Pb[(size_t)bh * NSE + row * NSP + j] = __float2bfloat16(v);
}

// =====================================================================================
// k_ns: merged Newton-Schulz step.
//   Squaring slots (slot < nsq, nsq=3): D = Esq @ Esq (symmetric; slot1 mirrors).
//     initmode: Eout = I - s*D (masked to [SM,SM]); else Eout = D.
//   Chain slots (slot >= nsq, 2 slots): D = Ech @ yin;
//     finmode: yout = s*D; else yout = yin + D.
// =====================================================================================
__global__ __launch_bounds__(256, 2) void k_ns(
    const __nv_bfloat16* __restrict__ Esq, __nv_bfloat16* __restrict__ Eout,
    const __nv_bfloat16* __restrict__ Ech,
    const float* __restrict__ yin, float* __restrict__ yout,
    int nsq, int initmode, int finmode) {
  __shared__ __align__(16) char smraw[41984];
  typedef __nv_bfloat16 (*TileP)[40];
  int tid = threadIdx.x, w = tid >> 5, lane = tid & 31;
  int gid = lane >> 2, tig = lane & 3;
  int bh = blockIdx.z, slot = blockIdx.x;
  size_t base = (size_t)bh * NSE;

  if (slot < nsq) {
    // ---------------- squaring role ----------------
    TileP sA0 = (TileP)(smraw);
    TileP sA1 = (TileP)(smraw + 10240);
    TileP sB0 = (TileP)(smraw + 20480);
    TileP sB1 = (TileP)(smraw + 30720);
    int m0 = (slot == 2) ? 128 : 0;
    int n0 = (slot >= 1) ? 128 : 0;
    int wm = w & 3, wn = w >> 2;                 // warp grid 4x2, warp tile 32x64
    const uint4* gE = (const uint4*)(Esq + base);
    float acc[2][8][4] = {};
    int r0 = tid >> 2, seg = tid & 3;
    // prologue: chunk 0 -> stage 0
    cpa16(&sA0[r0][seg * 8],      gE + ((m0 + r0) * 32 + seg));
    cpa16(&sA0[r0 + 64][seg * 8], gE + ((m0 + r0 + 64) * 32 + seg));
    cpa16(&sB0[r0][seg * 8],      gE + ((n0 + r0) * 32 + seg));
    cpa16(&sB0[r0 + 64][seg * 8], gE + ((n0 + r0 + 64) * 32 + seg));
    CPA_COMMIT;
    for (int kc = 0; kc < 8; kc++) {
      TileP cA = (kc & 1) ? sA1 : sA0;
      TileP cB = (kc & 1) ? sB1 : sB0;
      if (kc < 7) {
        TileP nA = (kc & 1) ? sA0 : sA1;
        TileP nB = (kc & 1) ? sB0 : sB1;
        int kn = (kc + 1) * 4;
        cpa16(&nA[r0][seg * 8],      gE + ((m0 + r0) * 32 + kn + seg));
        cpa16(&nA[r0 + 64][seg * 8], gE + ((m0 + r0 + 64) * 32 + kn + seg));
        cpa16(&nB[r0][seg * 8],      gE + ((n0 + r0) * 32 + kn + seg));
        cpa16(&nB[r0 + 64][seg * 8], gE + ((n0 + r0 + 64) * 32 + kn + seg));
        CPA_COMMIT;
        CPA_WAIT1;
      } else {
        CPA_WAIT0;
      }
      __syncthreads();
      #pragma unroll
      for (int ks = 0; ks < 2; ks++) {
        int kb = ks * 16;
        uint32_t af[2][4], bf[8][2];
        #pragma unroll
        for (int mt = 0; mt < 2; mt++) {
          int row = wm * 32 + mt * 16 + gid;
          af[mt][0] = *(const uint32_t*)&cA[row][kb + tig * 2];
          af[mt][1] = *(const uint32_t*)&cA[row + 8][kb + tig * 2];
          af[mt][2] = *(const uint32_t*)&cA[row][kb + 8 + tig * 2];
          af[mt][3] = *(const uint32_t*)&cA[row + 8][kb + 8 + tig * 2];
        }
        #pragma unroll
        for (int nt = 0; nt < 8; nt++) {
          int brow = wn * 64 + nt * 8 + gid;
          bf[nt][0] = *(const uint32_t*)&cB[brow][kb + tig * 2];
          bf[nt][1] = *(const uint32_t*)&cB[brow][kb + 8 + tig * 2];
        }
        #pragma unroll
        for (int mt = 0; mt < 2; mt++)
          #pragma unroll
          for (int nt = 0; nt < 8; nt++)
            mma16816(acc[mt][nt], af[mt], bf[nt]);
      }
      __syncthreads();
    }
    float s = g_nsc[bh];
    #pragma unroll
    for (int mt = 0; mt < 2; mt++) {
      #pragma unroll
      for (int nt = 0; nt < 8; nt++) {
        int row = m0 + wm * 32 + mt * 16 + gid;
        int col = n0 + wn * 64 + nt * 8 + tig * 2;
        #pragma unroll
        for (int half = 0; half < 2; half++) {
          int r = row + half * 8;
          float d0 = acc[mt][nt][half * 2], d1 = acc[mt][nt][half * 2 + 1];
          if (initmode) {
            d0 = (r < SM && col < SM) ? ((r == col ? 1.f : 0.f) - s * d0) : 0.f;
            d1 = (r < SM && col + 1 < SM) ? ((r == col + 1 ? 1.f : 0.f) - s * d1) : 0.f;
          }
          __nv_bfloat16 h0 = __float2bfloat16(d0), h1 = __float2bfloat16(d1);
          *(uint32_t*)(Eout + base + (size_t)r * NSP + col) = pack2(h0, h1);
          if (slot == 1) {                       // mirror transpose tile
            Eout[base + (size_t)col * NSP + r] = h0;
            Eout[base + (size_t)(col + 1) * NSP + r] = h1;
          }
        }
      }
    }
  } else {
    // ---------------- chain role: D = Ech @ yin ----------------
    TileP sAc = (TileP)(smraw);                              // [128][40]
    __nv_bfloat16 (*sBy)[40] = (__nv_bfloat16(*)[40])(smraw + 10240);  // [64][40]
    int cslot = slot - nsq;
    int m0c = cslot * 128;
    int wm = w & 3, wn = w >> 2;                 // warp tile 32x32
    const uint4* gAc = (const uint4*)(Ech + base);
    const float* yb_in = yin + (size_t)bh * 256 * 64;
    float* yb_out = yout + (size_t)bh * 256 * 64;
    float acc[2][4][4] = {};
    int r0 = tid >> 2, seg = tid & 3;
    int kk = tid & 31, nb = (tid >> 5) * 8;
    for (int kc = 0; kc < 8; kc++) {
      *(uint4*)&sAc[r0][seg * 8]      = gAc[(m0c + r0) * 32 + kc * 4 + seg];
      *(uint4*)&sAc[r0 + 64][seg * 8] = gAc[(m0c + r0 + 64) * 32 + kc * 4 + seg];
      #pragma unroll
      for (int i = 0; i < 8; i++)
        sBy[nb + i][kk] = __float2bfloat16(yb_in[(size_t)(kc * 32 + kk) * 64 + nb + i]);
      __syncthreads();
      #pragma unroll
      for (int ks = 0; ks < 2; ks++) {
        int kb = ks * 16;
        uint32_t af[2][4], bf[4][2];
        #pragma unroll
        for (int mt = 0; mt < 2; mt++) {
          int row = wm * 32 + mt * 16 + gid;
          af[mt][0] = *(const uint32_t*)&sAc[row][kb + tig * 2];
          af[mt][1] = *(const uint32_t*)&sAc[row + 8][kb + tig * 2];
          af[mt][2] = *(const uint32_t*)&sAc[row][kb + 8 + tig * 2];
          af[mt][3] = *(const uint32_t*)&sAc[row + 8][kb + 8 + tig * 2];
        }
        #pragma unroll
        for (int nt = 0; nt < 4; nt++) {
          int brow = wn * 32 + nt * 8 + gid;
          bf[nt][0] = *(const uint32_t*)&sBy[brow][kb + tig * 2];
          bf[nt][1] = *(const uint32_t*)&sBy[brow][kb + 8 + tig * 2];
        }
        #pragma unroll
        for (int mt = 0; mt < 2; mt++)
          #pragma unroll
          for (int nt = 0; nt < 4; nt++)
            mma16816(acc[mt][nt], af[mt], bf[nt]);
      }
      __syncthreads();
    }
    float s = g_nsc[bh];
    #pragma unroll
    for (int mt = 0; mt < 2; mt++)
      #pragma unroll
      for (int half = 0; half < 2; half++) {
        int m = m0c + wm * 32 + mt * 16 + gid + half * 8;
        #pragma unroll
        for (int nt = 0; nt < 4; nt++) {
          int col = wn * 32 + nt * 8 + tig * 2;
          float d0 = acc[mt][nt][half * 2], d1 = acc[mt][nt][half * 2 + 1];
          float o0, o1;
          if (finmode) { o0 = s * d0; o1 = s * d1; }
          else {
            o0 = yb_in[(size_t)m * 64 + col] + d0;
            o1 = yb_in[(size_t)m * 64 + col + 1] + d1;
          }
          yb_out[(size_t)m * 64 + col] = o0;
          yb_out[(size_t)m * 64 + col + 1] = o1;
        }
      }
  }
}

// ---------------- k1 = gauss(Qs, Ql) via tf32 HMMA + poly-exp -> g_k1 [SN][SMP] -------
__global__ __launch_bounds__(256) void k_g1(const float* __restrict__ Q) {
  __shared__ __align__(16) float sA[128][36];
  __shared__ __align__(16) float sB[128][36];
  int tid = threadIdx.x, w = tid >> 5, lane = tid & 31;
  int gid = lane >> 2, tig = lane & 3;
  int wm = w & 3, wn = w >> 2;
  int bh = blockIdx.z, m0 = blockIdx.y * 128, n0 = blockIdx.x * 128;
  const float* Qb = Q + (size_t)bh * SN * 64;
  const float* Qlb = g_Ql + (size_t)bh * SM * 64;
  float acc[2][8][4] = {};
  int r = tid >> 1, hb = (tid & 1) * 4;
  for (int kc = 0; kc < 2; kc++) {
    int k0 = kc * 32;
    int gm = m0 + r, gn = n0 + r;
    #pragma unroll
    for (int e = 0; e < 4; e++) {
      int c = (hb + e) * 4;
      float4 va = make_float4(0.f, 0.f, 0.f, 0.f);
      if (gm < SN) va = *(const float4*)&Qb[(size_t)gm * 64 + k0 + c];
      va.x *= QS; va.y *= QS; va.z *= QS; va.w *= QS;
      *(float4*)&sA[r][c] = va;
      float4 vb = make_float4(0.f, 0.f, 0.f, 0.f);
      if (gn < SM) vb = *(const float4*)&Qlb[(size_t)gn * 64 + k0 + c];
      *(float4*)&sB[r][c] = vb;
    }
    __syncthreads();
    #pragma unroll
    for (int ks = 0; ks < 4; ks++) {
      int kb = ks * 8;
      uint32_t af[2][4], bf[8][2];
      #pragma unroll
      for (int mt = 0; mt < 2; mt++) {
        int row = wm * 32 + mt * 16 + gid;
        af[mt][0] = cvt_tf32(sA[row][kb + tig]);
        af[mt][1] = cvt_tf32(sA[row + 8][kb + tig]);
        af[mt][2] = cvt_tf32(sA[row][kb + tig + 4]);
        af[mt][3] = cvt_tf32(sA[row + 8][kb + tig + 4]);
      }
      #pragma unroll
      for (int nt = 0; nt < 8; nt++) {
        int brow = wn * 64 + nt * 8 + gid;
        bf[nt][0] = cvt_tf32(sB[brow][kb + tig]);
        bf[nt][1] = cvt_tf32(sB[brow][kb + tig + 4]);
      }
      #pragma unroll
      for (int mt = 0; mt < 2; mt++)
        #pragma unroll
        for (int nt = 0; nt < 8; nt++)
          mma_tf32(acc[mt][nt], af[mt], bf[nt]);
    }
    __syncthreads();
  }
  float* k1b = g_k1 + (size_t)bh * SN * SMP;
  const float* qn2b = g_qn2 + (size_t)bh * SN;
  const float* ql2b = g_ql2 + (size_t)bh * SM;
  #pragma unroll
  for (int mt = 0; mt < 2; mt++) {
    #pragma unroll
    for (int half = 0; half < 2; half++) {
      int m = m0 + wm * 32 + mt * 16 + gid + half * 8;
      if (m >= SN) continue;
      float qm = qn2b[m];
      #pragma unroll
      for (int nt = 0; nt < 8; nt++) {
        int n = n0 + wn * 64 + nt * 8 + tig * 2;
        #pragma unroll
        for (int c2 = 0; c2 < 2; c2++) {
          int nn = n + c2;
          if (nn >= SMP) continue;
          float val = 0.f;
          if (nn < SM)
            val = fexp(acc[mt][nt][half * 2 + c2] - 0.5f * (qm + ql2b[nn]));
          k1b[(size_t)m * SMP + nn] = val;
        }
      }
    }
  }
}

// ---------------- y0 = Z = k1^T @ V via tf32 HMMA  [256(pad) x 64, K=3136] ------------
__global__ __launch_bounds__(256) void k_Zt(const float* __restrict__ V,
                                            float* __restrict__ y0) {
  __shared__ __align__(16) float sA[128][36];
  __shared__ __align__(16) float sB[32][68];
  int tid = threadIdx.x, w = tid >> 5, lane = tid & 31;
  int gid = lane >> 2, tig = lane & 3;
  int wm = w & 3, wn = w >> 2;
  int bh = blockIdx.z, m0 = blockIdx.y * 128;
  const float* k1b = g_k1 + (size_t)bh * SN * SMP;
  const float* Vb = V + (size_t)bh * SN * 64;
  float acc[2][4][4] = {};
  int tokA = tid & 31, segA = tid >> 5;
  for (int kc = 0; kc < 98; kc++) {
    int k0 = kc * 32;
    const float* k1r = k1b + (size_t)(k0 + tokA) * SMP;
    #pragma unroll
    for (int i = 0; i < 4; i++) {
      int l = segA * 16 + i * 4;
      int gl = m0 + l;
      float4 v = make_float4(0.f, 0.f, 0.f, 0.f);
      if (gl + 3 < SMP) v = *(const float4*)&k1r[gl];
      sA[l][tokA] = v.x; sA[l + 1][tokA] = v.y;
      sA[l + 2][tokA] = v.z; sA[l + 3][tokA] = v.w;
    }
    #pragma unroll
    for (int e = 0; e < 2; e++) {
      int t2 = tid * 2 + e;
      int tok = t2 >> 4, sg = t2 & 15;
      *(float4*)&sB[tok][sg * 4] = *(const float4*)&Vb[(size_t)(k0 + tok) * 64 + sg * 4];
    }
    __syncthreads();
    #pragma unroll
    for (int ks = 0; ks < 4; ks++) {
      int kb = ks * 8;
      uint32_t af[2][4], bf[4][2];
      #pragma unroll
      for (int mt = 0; mt < 2; mt++) {
        int row = wm * 32 + mt * 16 + gid;
        af[mt][0] = cvt_tf32(sA[row][kb + tig]);
        af[mt][1] = cvt_tf32(sA[row + 8][kb + tig]);
        af[mt][2] = cvt_tf32(sA[row][kb + tig + 4]);
        af[mt][3] = cvt_tf32(sA[row + 8][kb + tig + 4]);
      }
      #pragma unroll
      for (int nt = 0; nt < 4; nt++) {
        int nc = wn * 32 + nt * 8 + gid;
        bf[nt][0] = cvt_tf32(sB[kb + tig][nc]);
        bf[nt][1] = cvt_tf32(sB[kb + tig + 4][nc]);
      }
      #pragma unroll
      for (int mt = 0; mt < 2; mt++)
        #pragma unroll
        for (int nt = 0; nt < 4; nt++)
          mma_tf32(acc[mt][nt], af[mt], bf[nt]);
    }
    __syncthreads();
  }
  float* yb = y0 + (size_t)bh * 256 * 64;
  #pragma unroll
  for (int mt = 0; mt < 2; mt++)
    #pragma unroll
    for (int half = 0; half < 2; half++) {
      int m = m0 + wm * 32 + mt * 16 + gid + half * 8;
      #pragma unroll
      for (int nt = 0; nt < 4; nt++) {
        int n = wn * 32 + nt * 8 + tig * 2;
        yb[(size_t)m * 64 + n]     = acc[mt][nt][half * 2];
        yb[(size_t)m * 64 + n + 1] = acc[mt][nt][half * 2 + 1];
      }
    }
}

// ---------------- depthwise 3x3 conv residual -> d_out ----------------
__global__ __launch_bounds__(256) void k_conv(const float* __restrict__ V,
        const float* __restrict__ cw, float* __restrict__ out) {
  int bh = blockIdx.y;
  int h = bh & 7;
  int e = blockIdx.x * 256 + threadIdx.x;
  int c = e & 63, n = e >> 6;
  int y = n / SHW, x = n % SHW;
  const float* Vb = V + (size_t)bh * SN * 64;
  float acc = 0.f;
  #pragma unroll
  for (int dy = -1; dy <= 1; dy++)
    #pragma unroll
    for (int dx = -1; dx <= 1; dx++) {
      int yy = y + dy, xx = x + dx;
      if ((unsigned)yy < SHW && (unsigned)xx < SHW)
        acc += cw[((dy + 1) * 3 + (dx + 1)) * 8 + h] * Vb[(yy * SHW + xx) * 64 + c];
    }
  out[(size_t)bh * SN * 64 + e] = acc;
}

// ---------------- out += k1 @ Y via tf32 HMMA  [3136 x 64, K=196(208)] ---------------
__global__ __launch_bounds__(256) void k_Xt(const float* __restrict__ Yf,
                                            float* __restrict__ out) {
  __shared__ __align__(16) float sA[128][36];
  __shared__ __align__(16) float sB[32][68];
  int tid = threadIdx.x, w = tid >> 5, lane = tid & 31;
  int gid = lane >> 2, tig = lane & 3;
  int wm = w & 3, wn = w >> 2;
  int bh = blockIdx.z, m0 = blockIdx.y * 128;
  const float* k1b = g_k1 + (size_t)bh * SN * SMP;
  const float* Yb = Yf + (size_t)bh * 256 * 64;
  float acc[2][4][4] = {};
  int r = tid >> 1, hb = (tid & 1) * 4;
  for (int kc = 0; kc < 7; kc++) {
    int k0 = kc * 32;
    int gm = m0 + r;
    #pragma unroll
    for (int e = 0; e < 4; e++) {
      int c = (hb + e) * 4;
      int gk = k0 + c;
      float4 v = make_float4(0.f, 0.f, 0.f, 0.f);
      if (gm < SN && gk + 3 < SMP) v = *(const float4*)&k1b[(size_t)gm * SMP + gk];
      *(float4*)&sA[r][c] = v;
    }
    #pragma unroll
    for (int e = 0; e < 2; e++) {
      int t2 = tid * 2 + e;
      int tok = t2 >> 4, sg = t2 & 15;
      int gk = k0 + tok;
      float4 v = make_float4(0.f, 0.f, 0.f, 0.f);
      if (gk < SM) v = *(const float4*)&Yb[(size_t)gk * 64 + sg * 4];
      *(float4*)&sB[tok][sg * 4] = v;
    }
    __syncthreads();
    #pragma unroll
    for (int ks = 0; ks < 4; ks++) {
      int kb = ks * 8;
      uint32_t af[2][4], bf[4][2];
      #pragma unroll
      for (int mt = 0; mt < 2; mt++) {
        int row = wm * 32 + mt * 16 + gid;
        af[mt][0] = cvt_tf32(sA[row][kb + tig]);
        af[mt][1] = cvt_tf32(sA[row + 8][kb + tig]);
        af[mt][2] = cvt_tf32(sA[row][kb + tig + 4]);
        af[mt][3] = cvt_tf32(sA[row + 8][kb + tig + 4]);
      }
      #pragma unroll
      for (int nt = 0; nt < 4; nt++) {
        int nc = wn * 32 + nt * 8 + gid;
        bf[nt][0] = cvt_tf32(sB[kb + tig][nc]);
        bf[nt][1] = cvt_tf32(sB[kb + tig + 4][nc]);
      }
      #pragma unroll
      for (int mt = 0; mt < 2; mt++)
        #pragma unroll
        for (int nt = 0; nt < 4; nt++)
          mma_tf32(acc[mt][nt], af[mt], bf[nt]);
    }
    __syncthreads();
  }
  float* ob = out + (size_t)bh * SN * 64;
  #pragma unroll
  for (int mt = 0; mt < 2; mt++)
    #pragma unroll
    for (int half = 0; half < 2; half++) {
      int m = m0 + wm * 32 + mt * 16 + gid + half * 8;
      if (m >= SN) continue;
      #pragma unroll
      for (int nt = 0; nt < 4; nt++) {
        int n = wn * 32 + nt * 8 + tig * 2;
        ob[(size_t)m * 64 + n]     += acc[mt][nt][half * 2];
        ob[(size_t)m * 64 + n + 1] += acc[mt][nt][half * 2 + 1];
      }
    }
}

// ---------------- host launch ----------------
extern "C" void kernel_launch(void* const* d_in, const int* in_sizes, int n_in,
                              void* d_out, int out_size) {
  const float* Q     = (const float*)d_in[0];
  const float* V     = (const float*)d_in[1];
  const float* wl    = (const float*)d_in[2];
  const float* gamma = (const float*)d_in[3];
  const float* beta  = (const float*)d_in[4];
  const float* cw    = (const float*)d_in[5];
  float* out = (float*)d_out;

  float *pQl, *pql2, *pP, *py0, *py1;
  cudaGetSymbolAddress((void**)&pQl,  g_Ql);
  cudaGetSymbolAddress((void**)&pql2, g_ql2);
  cudaGetSymbolAddress((void**)&pP,   g_P);
  cudaGetSymbolAddress((void**)&py0,  g_y0);
  cudaGetSymbolAddress((void**)&py1,  g_y1);
  __nv_bfloat16 *pPb, *pEa, *pEb;
  cudaGetSymbolAddress((void**)&pPb, g_Pb);
  cudaGetSymbolAddress((void**)&pEa, g_Ea);
  cudaGetSymbolAddress((void**)&pEb, g_Eb);

  // landmarks (conv + LN + GELU + |ql|^2), |q|^2, P, scale, bf16 P
  k_land<<<dim3(1, 4, SBH), 256>>>(Q, wl, gamma, beta);
  k_qn2<<<dim3(SN / 8, SBH), 256>>>(Q);
  k_gauss<<<dim3(4, 4, SBH), 256>>>(pQl, pQl, pql2, pql2, pP, SM, SM, 1.f);
  k_scale<<<SBH, 256>>>();
  k_pad<<<dim3(NSP, SBH), 256>>>();
  // k1 and y0 = Z (independent of NS)
  k_g1<<<dim3(2, 25, SBH), 256>>>(Q);
  k_Zt<<<dim3(1, 2, SBH), 256>>>(V, py0);
  // E_0 = I - s*P^2   (3 squaring slots)
  k_ns<<<dim3(3, 1, SBH), 256>>>(pPb, pEa, nullptr, nullptr, nullptr, 3, 1, 0);
  // 19 merged steps: E_{k+1}=E_k^2  +  y_{k+1}=(I+E_k)y_k
  __nv_bfloat16 *ec = pEa, *en = pEb;
  float *yc = py0, *yn = py1;
  for (int k = 0; k < 19; k++) {
    k_ns<<<dim3(5, 1, SBH), 256>>>(ec, en, ec, yc, yn, 3, 0, 0);
    __nv_bfloat16* te = ec; ec = en; en = te;
    float* ty = yc; yc = yn; yn = ty;
  }
  // chain-only with E_19
  k_ns<<<dim3(2, 1, SBH), 256>>>(nullptr, nullptr, ec, yc, yn, 0, 0, 0);
  { float* ty = yc; yc = yn; yn = ty; }
  // final: Y = s * (P @ y_20) = V_0 y_20
  k_ns<<<dim3(2, 1, SBH), 256>>>(nullptr, nullptr, pPb, yc, yn, 0, 0, 1);
  // conv residual -> out, then out += k1 @ Y
  k_conv<<<dim3(784, SBH), 256>>>(V, cw, out);
  k_Xt<<<dim3(1, 25, SBH), 256>>>(yn, out);
}

// round 10
// speedup vs baseline: 2.8509x; 1.0778x over previous
#include <cuda_runtime.h>
#include <cuda_bf16.h>
#include <math.h>
#include <stdint.h>

#define SBH 128
#define SN  3136
#define SM  196
#define SMP 224                    /* k1 row stride (bf16), 32-aligned, zero-padded */
#define SHW 56
#define QS  0.35355339059327379f   /* 64^-0.25 */
#define NSP 256
#define NSE ((size_t)(NSP*NSP))

// ---------------- scratch (static device globals; no allocation) ----------------
__device__ float g_Ql [SBH*SM*64];
__device__ float g_ql2[SBH*SM];
__device__ float g_qn2[SBH*SN];
__device__ __align__(16) __nv_bfloat16 g_k1[(size_t)SBH*SN*SMP];   // 180 MB bf16
__device__ float g_P  [SBH*SM*SM];
__device__ float g_nsc[SBH];
__device__ __align__(16) __nv_bfloat16 g_Pb[SBH*NSE];   // bf16 P, padded 256x256
__device__ __align__(16) __nv_bfloat16 g_Ea[SBH*NSE];   // E ping
__device__ __align__(16) __nv_bfloat16 g_Eb[SBH*NSE];   // E pong
__device__ float g_y0[SBH*256*64];             // y ping (fp32)
__device__ float g_y1[SBH*256*64];             // y pong

// ================= helpers =================
__device__ __forceinline__ uint32_t pack2(__nv_bfloat16 a, __nv_bfloat16 b) {
  return (uint32_t)__bfloat16_as_ushort(a) | ((uint32_t)__bfloat16_as_ushort(b) << 16);
}
__device__ __forceinline__ void mma16816(float* c, const uint32_t* a, const uint32_t* b) {
  asm volatile(
    "mma.sync.aligned.m16n8k16.row.col.f32.bf16.bf16.f32 "
    "{%0,%1,%2,%3}, {%4,%5,%6,%7}, {%8,%9}, {%0,%1,%2,%3};"
    : "+f"(c[0]), "+f"(c[1]), "+f"(c[2]), "+f"(c[3])
    : "r"(a[0]), "r"(a[1]), "r"(a[2]), "r"(a[3]), "r"(b[0]), "r"(b[1]));
}
__device__ __forceinline__ uint32_t cvt_tf32(float x) {
  uint32_t r; asm("cvt.rna.tf32.f32 %0, %1;" : "=r"(r) : "f"(x)); return r;
}
__device__ __forceinline__ void mma_tf32(float* c, const uint32_t* a, const uint32_t* b) {
  asm volatile(
    "mma.sync.aligned.m16n8k8.row.col.f32.tf32.tf32.f32 "
    "{%0,%1,%2,%3}, {%4,%5,%6,%7}, {%8,%9}, {%0,%1,%2,%3};"
    : "+f"(c[0]), "+f"(c[1]), "+f"(c[2]), "+f"(c[3])
    : "r"(a[0]), "r"(a[1]), "r"(a[2]), "r"(a[3]), "r"(b[0]), "r"(b[1]));
}
__device__ __forceinline__ void cpa16(void* s, const void* g) {
  uint32_t sa = (uint32_t)__cvta_generic_to_shared(s);
  asm volatile("cp.async.cg.shared.global [%0], [%1], 16;" :: "r"(sa), "l"(g));
}
#define CPA_COMMIT asm volatile("cp.async.commit_group;" ::: "memory")
#define CPA_WAIT1  asm volatile("cp.async.wait_group 1;" ::: "memory")
#define CPA_WAIT0  asm volatile("cp.async.wait_group 0;" ::: "memory")
// MUFU-free exp: 2^(x*log2e), deg-6 poly + exponent bit inject.
__device__ __forceinline__ float fexp(float x) {
  float t = x * 1.4426950408889634f;
  float j = rintf(t);
  float f = t - j;
  float p = 1.53958971e-4f;
  p = fmaf(p, f, 1.33336498e-3f);
  p = fmaf(p, f, 9.61817851e-3f);
  p = fmaf(p, f, 5.55041087e-2f);
  p = fmaf(p, f, 2.40226507e-1f);
  p = fmaf(p, f, 6.93147181e-1f);
  p = fmaf(p, f, 1.0f);
  j = fmaxf(j, -126.f);
  return p * __int_as_float(((int)j + 127) << 23);
}

// 64x64 tile, BK=16, 256 threads, 4x4 micro-tile (SIMT fp32 GEMM core)
#define GEMM_CORE(As,Bs) \
  _Pragma("unroll") \
  for (int kk = 0; kk < 16; kk++) { \
    float4 a = *(const float4*)(&As[kk][ty*4]); \
    float4 b = *(const float4*)(&Bs[kk][tx*4]); \
    acc[0][0]+=a.x*b.x; acc[0][1]+=a.x*b.y; acc[0][2]+=a.x*b.z; acc[0][3]+=a.x*b.w; \
    acc[1][0]+=a.y*b.x; acc[1][1]+=a.y*b.y; acc[1][2]+=a.y*b.z; acc[1][3]+=a.y*b.w; \
    acc[2][0]+=a.z*b.x; acc[2][1]+=a.z*b.y; acc[2][2]+=a.z*b.z; acc[2][3]+=a.z*b.w; \
    acc[3][0]+=a.w*b.x; acc[3][1]+=a.w*b.y; acc[3][2]+=a.w*b.z; acc[3][3]+=a.w*b.w; \
  }

// ---------------- landmark conv (im2col GEMM) + LayerNorm + GELU + ql2 ----------------
__global__ __launch_bounds__(256) void k_land(const float* __restrict__ Q,
        const float* __restrict__ W, const float* __restrict__ gamma,
        const float* __restrict__ beta) {
  __shared__ __align__(16) float As[16][68];
  __shared__ __align__(16) float Bs[16][68];
  __shared__ __align__(16) float Cs[64][68];
  int bh = blockIdx.z;
  int m0 = blockIdx.y * 64;
  int tid = threadIdx.x, tx = tid & 15, ty = tid >> 4;
  const float* Qb = Q + (size_t)bh * SN * 64;
  float acc[4][4] = {};
  for (int k0 = 0; k0 < 1024; k0 += 16) {
    #pragma unroll
    for (int l = 0; l < 4; l++) {
      int idx = tid + l * 256;
      { int ii = idx >> 4, kk = idx & 15;
        int m = m0 + ii, k = k0 + kk;
        float v = 0.f;
        if (m < SM) {
          int pix = k >> 6, ci = k & 63;
          int ry = pix >> 2, rx = pix & 3;
          int py = m / 14, px = m % 14;
          int n = (py * 4 + ry) * SHW + px * 4 + rx;
          v = Qb[n * 64 + ci] * QS;
        }
        As[kk][ii] = v;
      }
      { int kk = idx >> 6, jj = idx & 63;
        Bs[kk][jj] = W[(k0 + kk) * 64 + jj];
      }
    }
    __syncthreads();
    GEMM_CORE(As, Bs)
    __syncthreads();
  }
  #pragma unroll
  for (int i = 0; i < 4; i++)
    #pragma unroll
    for (int j = 0; j < 4; j++)
      Cs[ty * 4 + i][tx * 4 + j] = acc[i][j];
  __syncthreads();
  if (tid < 64) {
    int p = m0 + tid;
    if (p < SM) {
      float mu = 0.f;
      #pragma unroll 8
      for (int j = 0; j < 64; j++) mu += Cs[tid][j];
      mu *= (1.f / 64.f);
      float s2 = 0.f;
      #pragma unroll 8
      for (int j = 0; j < 64; j++) { float d = Cs[tid][j] - mu; s2 += d * d; }
      float r = rsqrtf(s2 * (1.f / 64.f) + 1e-5f);
      float q2 = 0.f;
      float* o = g_Ql + ((size_t)bh * SM + p) * 64;
      for (int j = 0; j < 64; j++) {
        float g = (Cs[tid][j] - mu) * r * gamma[j] + beta[j];
        g = 0.5f * g * (1.f + erff(g * 0.7071067811865476f));
        q2 += g * g;
        o[j] = g;
      }
      g_ql2[bh * SM + p] = q2;
    }
  }
}

// ---------------- |scaled q_n|^2 ----------------
__global__ __launch_bounds__(256) void k_qn2(const float* __restrict__ Q) {
  int bh = blockIdx.y;
  int warp = threadIdx.x >> 5, lane = threadIdx.x & 31;
  int n = blockIdx.x * 8 + warp;
  const float* q = Q + ((size_t)bh * SN + n) * 64;
  float v0 = q[lane], v1 = q[lane + 32];
  float s = v0 * v0 + v1 * v1;
  #pragma unroll
  for (int o = 16; o; o >>= 1) s += __shfl_xor_sync(0xffffffffu, s, o);
  if (lane == 0) g_qn2[bh * SN + n] = s * (QS * QS);
}

// ---------------- gauss kernel GEMM (P only): C = exp(dot - 0.5(a2+b2)) ----------------
__global__ __launch_bounds__(256) void k_gauss(const float* __restrict__ A,
     const float* __restrict__ B, const float* __restrict__ a2v,
     const float* __restrict__ b2v, float* __restrict__ C,
     int Ma, int Nb, float ascale) {
  __shared__ __align__(16) float As[16][68];
  __shared__ __align__(16) float Bs[16][68];
  int bh = blockIdx.z;
  int m0 = blockIdx.y * 64, n0 = blockIdx.x * 64;
  int tid = threadIdx.x, tx = tid & 15, ty = tid >> 4;
  A += (size_t)bh * Ma * 64;  B += (size_t)bh * Nb * 64;
  a2v += (size_t)bh * Ma;     b2v += (size_t)bh * Nb;
  C += (size_t)bh * Ma * Nb;
  float acc[4][4] = {};
  for (int k0 = 0; k0 < 64; k0 += 16) {
    #pragma unroll
    for (int l = 0; l < 4; l++) {
      int idx = tid + l * 256;
      { int ii = idx >> 4, kk = idx & 15; int m = m0 + ii;
        As[kk][ii] = (m < Ma) ? A[m * 64 + k0 + kk] * ascale : 0.f; }
      { int jj = idx >> 4, kk = idx & 15; int n = n0 + jj;
        Bs[kk][jj] = (n < Nb) ? B[n * 64 + k0 + kk] : 0.f; }
    }
    __syncthreads();
    GEMM_CORE(As, Bs)
    __syncthreads();
  }
  #pragma unroll
  for (int i = 0; i < 4; i++) {
    int m = m0 + ty * 4 + i; if (m >= Ma) continue;
    float am = a2v[m];
    #pragma unroll
    for (int j = 0; j < 4; j++) {
      int n = n0 + tx * 4 + j; if (n >= Nb) continue;
      C[(size_t)m * Nb + n] = expf(acc[i][j] - 0.5f * (am + b2v[n]));
    }
  }
}

// ---------------- NS scale: g_nsc = 1/(n1*ninf); P symmetric => n1 == ninf ----------------
__global__ __launch_bounds__(256) void k_scale() {
  int bh = blockIdx.x;
  const float* P = g_P + (size_t)bh * SM * SM;
  __shared__ float red[256];
  int tid = threadIdx.x;
  float rs = 0.f;
  if (tid < SM) {
    for (int j = 0; j < SM; j++) rs += fabsf(P[tid * SM + j]);
  }
  red[tid] = rs; __syncthreads();
  for (int s = 128; s > 0; s >>= 1) { if (tid < s) red[tid] = fmaxf(red[tid], red[tid + s]); __syncthreads(); }
  if (tid == 0) g_nsc[bh] = 1.f / (red[0] * red[0]);
}

// ---------------- pad + bf16 quantize of P; zero y0 ----------------
__global__ __launch_bounds__(256) void k_pad() {
  int bh = blockIdx.y, row = blockIdx.x, j = threadIdx.x;
  float v = (row < SM && j < SM) ? g_P[(size_t)bh * SM * SM + row * SM + j] : 0.f;
  g_Pb[(size_t)bh * NSE + row * NSP + j] = __float2bfloat16(v);
  if (j < 64) g_y0[(size_t)bh * 256 * 64 + row * 64 + j] = 0.f;
}

// =====================================================================================
// k_ns: merged Newton-Schulz step.
//   Squaring slots (slot < nsq, nsq=4): D = Esq @ Esq; quadrant (slot>>1, slot&1).
//     initmode: Eout = I - s*D (masked to [SM,SM]); else Eout = D.
//   Chain slots (slot >= nsq, 2 slots): D = Ech @ yin;
//     finmode: yout = s*D; else yout = yin + D.
// =====================================================================================
__global__ __launch_bounds__(256, 2) void k_ns(
    const __nv_bfloat16* __restrict__ Esq, __nv_bfloat16* __restrict__ Eout,
    const __nv_bfloat16* __restrict__ Ech,
    const float* __restrict__ yin, float* __restrict__ yout,
    int nsq, int initmode, int finmode) {
  __shared__ __align__(16) char smraw[41984];
  typedef __nv_bfloat16 (*TileP)[40];
  int tid = threadIdx.x, w = tid >> 5, lane = tid & 31;
  int gid = lane >> 2, tig = lane & 3;
  int bh = blockIdx.z, slot = blockIdx.x;
  size_t base = (size_t)bh * NSE;

  if (slot < nsq) {
    // ---------------- squaring role ----------------
    TileP sA0 = (TileP)(smraw);
    TileP sA1 = (TileP)(smraw + 10240);
    TileP sB0 = (TileP)(smraw + 20480);
    TileP sB1 = (TileP)(smraw + 30720);
    int m0 = (slot >> 1) * 128;
    int n0 = (slot & 1) * 128;
    int wm = w & 3, wn = w >> 2;                 // warp grid 4x2, warp tile 32x64
    const uint4* gE = (const uint4*)(Esq + base);
    float acc[2][8][4] = {};
    int r0 = tid >> 2, seg = tid & 3;
    cpa16(&sA0[r0][seg * 8],      gE + ((m0 + r0) * 32 + seg));
    cpa16(&sA0[r0 + 64][seg * 8], gE + ((m0 + r0 + 64) * 32 + seg));
    cpa16(&sB0[r0][seg * 8],      gE + ((n0 + r0) * 32 + seg));
    cpa16(&sB0[r0 + 64][seg * 8], gE + ((n0 + r0 + 64) * 32 + seg));
    CPA_COMMIT;
    for (int kc = 0; kc < 8; kc++) {
      TileP cA = (kc & 1) ? sA1 : sA0;
      TileP cB = (kc & 1) ? sB1 : sB0;
      if (kc < 7) {
        TileP nA = (kc & 1) ? sA0 : sA1;
        TileP nB = (kc & 1) ? sB0 : sB1;
        int kn = (kc + 1) * 4;
        cpa16(&nA[r0][seg * 8],      gE + ((m0 + r0) * 32 + kn + seg));
        cpa16(&nA[r0 + 64][seg * 8], gE + ((m0 + r0 + 64) * 32 + kn + seg));
        cpa16(&nB[r0][seg * 8],      gE + ((n0 + r0) * 32 + kn + seg));
        cpa16(&nB[r0 + 64][seg * 8], gE + ((n0 + r0 + 64) * 32 + kn + seg));
        CPA_COMMIT;
        CPA_WAIT1;
      } else {
        CPA_WAIT0;
      }
      __syncthreads();
      #pragma unroll
      for (int ks = 0; ks < 2; ks++) {
        int kb = ks * 16;
        uint32_t af[2][4], bf[8][2];
        #pragma unroll
        for (int mt = 0; mt < 2; mt++) {
          int row = wm * 32 + mt * 16 + gid;
          af[mt][0] = *(const uint32_t*)&cA[row][kb + tig * 2];
          af[mt][1] = *(const uint32_t*)&cA[row + 8][kb + tig * 2];
          af[mt][2] = *(const uint32_t*)&cA[row][kb + 8 + tig * 2];
          af[mt][3] = *(const uint32_t*)&cA[row + 8][kb + 8 + tig * 2];
        }
        #pragma unroll
        for (int nt = 0; nt < 8; nt++) {
          int brow = wn * 64 + nt * 8 + gid;
          bf[nt][0] = *(const uint32_t*)&cB[brow][kb + tig * 2];
          bf[nt][1] = *(const uint32_t*)&cB[brow][kb + 8 + tig * 2];
        }
        #pragma unroll
        for (int mt = 0; mt < 2; mt++)
          #pragma unroll
          for (int nt = 0; nt < 8; nt++)
            mma16816(acc[mt][nt], af[mt], bf[nt]);
      }
      __syncthreads();
    }
    float s = g_nsc[bh];
    #pragma unroll
    for (int mt = 0; mt < 2; mt++) {
      #pragma unroll
      for (int nt = 0; nt < 8; nt++) {
        int row = m0 + wm * 32 + mt * 16 + gid;
        int col = n0 + wn * 64 + nt * 8 + tig * 2;
        #pragma unroll
        for (int half = 0; half < 2; half++) {
          int r = row + half * 8;
          float d0 = acc[mt][nt][half * 2], d1 = acc[mt][nt][half * 2 + 1];
          if (initmode) {
            d0 = (r < SM && col < SM) ? ((r == col ? 1.f : 0.f) - s * d0) : 0.f;
            d1 = (r < SM && col + 1 < SM) ? ((r == col + 1 ? 1.f : 0.f) - s * d1) : 0.f;
          }
          *(uint32_t*)(Eout + base + (size_t)r * NSP + col) =
              pack2(__float2bfloat16(d0), __float2bfloat16(d1));
        }
      }
    }
  } else {
    // ---------------- chain role: D = Ech @ yin ----------------
    TileP sAc = (TileP)(smraw);                              // [128][40]
    __nv_bfloat16 (*sBy)[40] = (__nv_bfloat16(*)[40])(smraw + 10240);  // [64][40]
    int cslot = slot - nsq;
    int m0c = cslot * 128;
    int wm = w & 3, wn = w >> 2;                 // warp tile 32x32
    const uint4* gAc = (const uint4*)(Ech + base);
    const float* yb_in = yin + (size_t)bh * 256 * 64;
    float* yb_out = yout + (size_t)bh * 256 * 64;
    float acc[2][4][4] = {};
    int r0 = tid >> 2, seg = tid & 3;
    int kk = tid & 31, nb = (tid >> 5) * 8;
    for (int kc = 0; kc < 8; kc++) {
      *(uint4*)&sAc[r0][seg * 8]      = gAc[(m0c + r0) * 32 + kc * 4 + seg];
      *(uint4*)&sAc[r0 + 64][seg * 8] = gAc[(m0c + r0 + 64) * 32 + kc * 4 + seg];
      #pragma unroll
      for (int i = 0; i < 8; i++)
        sBy[nb + i][kk] = __float2bfloat16(yb_in[(size_t)(kc * 32 + kk) * 64 + nb + i]);
      __syncthreads();
      #pragma unroll
      for (int ks = 0; ks < 2; ks++) {
        int kb = ks * 16;
        uint32_t af[2][4], bf[4][2];
        #pragma unroll
        for (int mt = 0; mt < 2; mt++) {
          int row = wm * 32 + mt * 16 + gid;
          af[mt][0] = *(const uint32_t*)&sAc[row][kb + tig * 2];
          af[mt][1] = *(const uint32_t*)&sAc[row + 8][kb + tig * 2];
          af[mt][2] = *(const uint32_t*)&sAc[row][kb + 8 + tig * 2];
          af[mt][3] = *(const uint32_t*)&sAc[row + 8][kb + 8 + tig * 2];
        }
        #pragma unroll
        for (int nt = 0; nt < 4; nt++) {
          int brow = wn * 32 + nt * 8 + gid;
          bf[nt][0] = *(const uint32_t*)&sBy[brow][kb + tig * 2];
          bf[nt][1] = *(const uint32_t*)&sBy[brow][kb + 8 + tig * 2];
        }
        #pragma unroll
        for (int mt = 0; mt < 2; mt++)
          #pragma unroll
          for (int nt = 0; nt < 4; nt++)
            mma16816(acc[mt][nt], af[mt], bf[nt]);
      }
      __syncthreads();
    }
    float s = g_nsc[bh];
    #pragma unroll
    for (int mt = 0; mt < 2; mt++)
      #pragma unroll
      for (int half = 0; half < 2; half++) {
        int m = m0c + wm * 32 + mt * 16 + gid + half * 8;
        #pragma unroll
        for (int nt = 0; nt < 4; nt++) {
          int col = wn * 32 + nt * 8 + tig * 2;
          float d0 = acc[mt][nt][half * 2], d1 = acc[mt][nt][half * 2 + 1];
          float o0, o1;
          if (finmode) { o0 = s * d0; o1 = s * d1; }
          else {
            o0 = yb_in[(size_t)m * 64 + col] + d0;
            o1 = yb_in[(size_t)m * 64 + col + 1] + d1;
          }
          yb_out[(size_t)m * 64 + col] = o0;
          yb_out[(size_t)m * 64 + col + 1] = o1;
        }
      }
  }
}

// ---------------- k1 = gauss(Qs, Ql) via tf32 HMMA + poly-exp -> bf16 g_k1 ------------
__global__ __launch_bounds__(256) void k_g1(const float* __restrict__ Q) {
  __shared__ __align__(16) float sA[128][36];
  __shared__ __align__(16) float sB[128][36];
  int tid = threadIdx.x, w = tid >> 5, lane = tid & 31;
  int gid = lane >> 2, tig = lane & 3;
  int wm = w & 3, wn = w >> 2;
  int bh = blockIdx.z, m0 = blockIdx.y * 128, n0 = blockIdx.x * 128;
  const float* Qb = Q + (size_t)bh * SN * 64;
  const float* Qlb = g_Ql + (size_t)bh * SM * 64;
  float acc[2][8][4] = {};
  int r = tid >> 1, hb = (tid & 1) * 4;
  for (int kc = 0; kc < 2; kc++) {
    int k0 = kc * 32;
    int gm = m0 + r, gn = n0 + r;
    #pragma unroll
    for (int e = 0; e < 4; e++) {
      int c = (hb + e) * 4;
      float4 va = make_float4(0.f, 0.f, 0.f, 0.f);
      if (gm < SN) va = *(const float4*)&Qb[(size_t)gm * 64 + k0 + c];
      va.x *= QS; va.y *= QS; va.z *= QS; va.w *= QS;
      *(float4*)&sA[r][c] = va;
      float4 vb = make_float4(0.f, 0.f, 0.f, 0.f);
      if (gn < SM) vb = *(const float4*)&Qlb[(size_t)gn * 64 + k0 + c];
      *(float4*)&sB[r][c] = vb;
    }
    __syncthreads();
    #pragma unroll
    for (int ks = 0; ks < 4; ks++) {
      int kb = ks * 8;
      uint32_t af[2][4], bf[8][2];
      #pragma unroll
      for (int mt = 0; mt < 2; mt++) {
        int row = wm * 32 + mt * 16 + gid;
        af[mt][0] = cvt_tf32(sA[row][kb + tig]);
        af[mt][1] = cvt_tf32(sA[row + 8][kb + tig]);
        af[mt][2] = cvt_tf32(sA[row][kb + tig + 4]);
        af[mt][3] = cvt_tf32(sA[row + 8][kb + tig + 4]);
      }
      #pragma unroll
      for (int nt = 0; nt < 8; nt++) {
        int brow = wn * 64 + nt * 8 + gid;
        bf[nt][0] = cvt_tf32(sB[brow][kb + tig]);
        bf[nt][1] = cvt_tf32(sB[brow][kb + tig + 4]);
      }
      #pragma unroll
      for (int mt = 0; mt < 2; mt++)
        #pragma unroll
        for (int nt = 0; nt < 8; nt++)
          mma_tf32(acc[mt][nt], af[mt], bf[nt]);
    }
    __syncthreads();
  }
  __nv_bfloat16* k1b = g_k1 + (size_t)bh * SN * SMP;
  const float* qn2b = g_qn2 + (size_t)bh * SN;
  const float* ql2b = g_ql2 + (size_t)bh * SM;
  #pragma unroll
  for (int mt = 0; mt < 2; mt++) {
    #pragma unroll
    for (int half = 0; half < 2; half++) {
      int m = m0 + wm * 32 + mt * 16 + gid + half * 8;
      if (m >= SN) continue;
      float qm = qn2b[m];
      #pragma unroll
      for (int nt = 0; nt < 8; nt++) {
        int n = n0 + wn * 64 + nt * 8 + tig * 2;
        if (n + 1 >= SMP) continue;
        float v0 = 0.f, v1 = 0.f;
        if (n < SM)     v0 = fexp(acc[mt][nt][half * 2]     - 0.5f * (qm + ql2b[n]));
        if (n + 1 < SM) v1 = fexp(acc[mt][nt][half * 2 + 1] - 0.5f * (qm + ql2b[n + 1]));
        *(uint32_t*)(k1b + (size_t)m * SMP + n) =
            pack2(__float2bfloat16(v0), __float2bfloat16(v1));
      }
    }
  }
}

// ---------------- y0 += slice of Z = k1^T @ V (bf16 HMMA, K split over grid.x) --------
__global__ __launch_bounds__(256) void k_Zt(const float* __restrict__ V,
                                            float* __restrict__ y0) {
  __shared__ __align__(16) __nv_bfloat16 sA[128][40];   // [landmark][token]
  __shared__ __align__(16) __nv_bfloat16 sB[64][40];    // [channel][token]
  int tid = threadIdx.x, w = tid >> 5, lane = tid & 31;
  int gid = lane >> 2, tig = lane & 3;
  int wm = w & 3, wn = w >> 2;
  int bh = blockIdx.z, m0 = blockIdx.y * 128, kslice = blockIdx.x;
  const __nv_bfloat16* k1b = g_k1 + (size_t)bh * SN * SMP;
  const float* Vb = V + (size_t)bh * SN * 64;
  float acc[2][4][4] = {};
  int tokA = tid & 31, segA = tid >> 5;
  int cB = tid & 63, gB = tid >> 6;
  for (int kc = kslice * 14; kc < kslice * 14 + 14; kc++) {
    int k0 = kc * 32;
    const __nv_bfloat16* k1r = k1b + (size_t)(k0 + tokA) * SMP;
    #pragma unroll
    for (int i = 0; i < 4; i++) {
      int l = segA * 16 + i * 4;
      int gl = m0 + l;
      __align__(8) __nv_bfloat16 v4[4];
      if (gl + 3 < SMP) *(uint2*)v4 = *(const uint2*)&k1r[gl];
      else { v4[0] = v4[1] = v4[2] = v4[3] = __float2bfloat16(0.f); }
      sA[l][tokA] = v4[0]; sA[l + 1][tokA] = v4[1];
      sA[l + 2][tokA] = v4[2]; sA[l + 3][tokA] = v4[3];
    }
    #pragma unroll
    for (int i = 0; i < 8; i++) {
      int t = gB * 8 + i;
      sB[cB][t] = __float2bfloat16(Vb[(size_t)(k0 + t) * 64 + cB]);
    }
    __syncthreads();
    #pragma unroll
    for (int ks = 0; ks < 2; ks++) {
      int kb = ks * 16;
      uint32_t af[2][4], bf[4][2];
      #pragma unroll
      for (int mt = 0; mt < 2; mt++) {
        int row = wm * 32 + mt * 16 + gid;
        af[mt][0] = *(const uint32_t*)&sA[row][kb + tig * 2];
        af[mt][1] = *(const uint32_t*)&sA[row + 8][kb + tig * 2];
        af[mt][2] = *(const uint32_t*)&sA[row][kb + 8 + tig * 2];
        af[mt][3] = *(const uint32_t*)&sA[row + 8][kb + 8 + tig * 2];
      }
      #pragma unroll
      for (int nt = 0; nt < 4; nt++) {
        int brow = wn * 32 + nt * 8 + gid;
        bf[nt][0] = *(const uint32_t*)&sB[brow][kb + tig * 2];
        bf[nt][1] = *(const uint32_t*)&sB[brow][kb + 8 + tig * 2];
      }
      #pragma unroll
      for (int mt = 0; mt < 2; mt++)
        #pragma unroll
        for (int nt = 0; nt < 4; nt++)
          mma16816(acc[mt][nt], af[mt], bf[nt]);
    }
    __syncthreads();
  }
  float* yb = y0 + (size_t)bh * 256 * 64;
  #pragma unroll
  for (int mt = 0; mt < 2; mt++)
    #pragma unroll
    for (int half = 0; half < 2; half++) {
      int m = m0 + wm * 32 + mt * 16 + gid + half * 8;
      #pragma unroll
      for (int nt = 0; nt < 4; nt++) {
        int n = wn * 32 + nt * 8 + tig * 2;
        atomicAdd(&yb[(size_t)m * 64 + n],     acc[mt][nt][half * 2]);
        atomicAdd(&yb[(size_t)m * 64 + n + 1], acc[mt][nt][half * 2 + 1]);
      }
    }
}

// ---------------- depthwise 3x3 conv residual -> d_out ----------------
__global__ __launch_bounds__(256) void k_conv(const float* __restrict__ V,
        const float* __restrict__ cw, float* __restrict__ out) {
  int bh = blockIdx.y;
  int h = bh & 7;
  int e = blockIdx.x * 256 + threadIdx.x;
  int c = e & 63, n = e >> 6;
  int y = n / SHW, x = n % SHW;
  const float* Vb = V + (size_t)bh * SN * 64;
  float acc = 0.f;
  #pragma unroll
  for (int dy = -1; dy <= 1; dy++)
    #pragma unroll
    for (int dx = -1; dx <= 1; dx++) {
      int yy = y + dy, xx = x + dx;
      if ((unsigned)yy < SHW && (unsigned)xx < SHW)
        acc += cw[((dy + 1) * 3 + (dx + 1)) * 8 + h] * Vb[(yy * SHW + xx) * 64 + c];
    }
  out[(size_t)bh * SN * 64 + e] = acc;
}

// ---------------- out += k1 @ Y (bf16 HMMA, K=224 in 7 chunks) ----------------
__global__ __launch_bounds__(256) void k_Xt(const float* __restrict__ Yf,
                                            float* __restrict__ out) {
  __shared__ __align__(16) __nv_bfloat16 sA[128][40];   // [token][landmark-k]
  __shared__ __align__(16) __nv_bfloat16 sB[64][40];    // [channel][landmark-k]
  int tid = threadIdx.x, w = tid >> 5, lane = tid & 31;
  int gid = lane >> 2, tig = lane & 3;
  int wm = w & 3, wn = w >> 2;
  int bh = blockIdx.z, m0 = blockIdx.y * 128;
  const __nv_bfloat16* k1b = g_k1 + (size_t)bh * SN * SMP;
  const float* Yb = Yf + (size_t)bh * 256 * 64;
  float acc[2][4][4] = {};
  int r0 = tid >> 2, seg = tid & 3;
  int cB = tid & 63, gB = tid >> 6;
  for (int kc = 0; kc < 7; kc++) {
    int k0 = kc * 32;
    #pragma unroll
    for (int rr = 0; rr < 2; rr++) {
      int gm = m0 + r0 + rr * 64;
      uint4 v = make_uint4(0, 0, 0, 0);
      if (gm < SN) v = *(const uint4*)&k1b[(size_t)gm * SMP + k0 + seg * 8];
      *(uint4*)&sA[r0 + rr * 64][seg * 8] = v;
    }
    #pragma unroll
    for (int i = 0; i < 8; i++) {
      int t = gB * 8 + i;
      sB[cB][t] = __float2bfloat16(Yb[(size_t)(k0 + t) * 64 + cB]);
    }
    __syncthreads();
    #pragma unroll
    for (int ks = 0; ks < 2; ks++) {
      int kb = ks * 16;
      uint32_t af[2][4], bf[4][2];
      #pragma unroll
      for (int mt = 0; mt < 2; mt++) {
        int row = wm * 32 + mt * 16 + gid;
        af[mt][0] = *(const uint32_t*)&sA[row][kb + tig * 2];
        af[mt][1] = *(const uint32_t*)&sA[row + 8][kb + tig * 2];
        af[mt][2] = *(const uint32_t*)&sA[row][kb + 8 + tig * 2];
        af[mt][3] = *(const uint32_t*)&sA[row + 8][kb + 8 + tig * 2];
      }
      #pragma unroll
      for (int nt = 0; nt < 4; nt++) {
        int brow = wn * 32 + nt * 8 + gid;
        bf[nt][0] = *(const uint32_t*)&sB[brow][kb + tig * 2];
        bf[nt][1] = *(const uint32_t*)&sB[brow][kb + 8 + tig * 2];
      }
      #pragma unroll
      for (int mt = 0; mt < 2; mt++)
        #pragma unroll
        for (int nt = 0; nt < 4; nt++)
          mma16816(acc[mt][nt], af[mt], bf[nt]);
    }
    __syncthreads();
  }
  float* ob = out + (size_t)bh * SN * 64;
  #pragma unroll
  for (int mt = 0; mt < 2; mt++)
    #pragma unroll
    for (int half = 0; half < 2; half++) {
      int m = m0 + wm * 32 + mt * 16 + gid + half * 8;
      if (m >= SN) continue;
      #pragma unroll
      for (int nt = 0; nt < 4; nt++) {
        int n = wn * 32 + nt * 8 + tig * 2;
        ob[(size_t)m * 64 + n]     += acc[mt][nt][half * 2];
        ob[(size_t)m * 64 + n + 1] += acc[mt][nt][half * 2 + 1];
      }
    }
}

// ---------------- host launch ----------------
extern "C" void kernel_launch(void* const* d_in, const int* in_sizes, int n_in,
                              void* d_out, int out_size) {
  const float* Q     = (const float*)d_in[0];
  const float* V     = (const float*)d_in[1];
  const float* wl    = (const float*)d_in[2];
  const float* gamma = (const float*)d_in[3];
  const float* beta  = (const float*)d_in[4];
  const float* cw    = (const float*)d_in[5];
  float* out = (float*)d_out;

  float *pQl, *pql2, *pP, *py0, *py1;
  cudaGetSymbolAddress((void**)&pQl,  g_Ql);
  cudaGetSymbolAddress((void**)&pql2, g_ql2);
  cudaGetSymbolAddress((void**)&pP,   g_P);
  cudaGetSymbolAddress((void**)&py0,  g_y0);
  cudaGetSymbolAddress((void**)&py1,  g_y1);
  __nv_bfloat16 *pPb, *pEa, *pEb;
  cudaGetSymbolAddress((void**)&pPb, g_Pb);
  cudaGetSymbolAddress((void**)&pEa, g_Ea);
  cudaGetSymbolAddress((void**)&pEb, g_Eb);

  // landmarks (conv + LN + GELU + |ql|^2), |q|^2, P, scale, bf16 P + zero y0
  k_land<<<dim3(1, 4, SBH), 256>>>(Q, wl, gamma, beta);
  k_qn2<<<dim3(SN / 8, SBH), 256>>>(Q);
  k_gauss<<<dim3(4, 4, SBH), 256>>>(pQl, pQl, pql2, pql2, pP, SM, SM, 1.f);
  k_scale<<<SBH, 256>>>();
  k_pad<<<dim3(NSP, SBH), 256>>>();
  // k1 (bf16) and y0 = Z via K-split atomics
  k_g1<<<dim3(2, 25, SBH), 256>>>(Q);
  k_Zt<<<dim3(7, 2, SBH), 256>>>(V, py0);
  // E_0 = I - s*P^2   (4 squaring quadrants)
  k_ns<<<dim3(4, 1, SBH), 256>>>(pPb, pEa, nullptr, nullptr, nullptr, 4, 1, 0);
  // 19 merged steps: E_{k+1}=E_k^2  +  y_{k+1}=(I+E_k)y_k
  __nv_bfloat16 *ec = pEa, *en = pEb;
  float *yc = py0, *yn = py1;
  for (int k = 0; k < 19; k++) {
    k_ns<<<dim3(6, 1, SBH), 256>>>(ec, en, ec, yc, yn, 4, 0, 0);
    __nv_bfloat16* te = ec; ec = en; en = te;
    float* ty = yc; yc = yn; yn = ty;
  }
  // chain-only with E_19
  k_ns<<<dim3(2, 1, SBH), 256>>>(nullptr, nullptr, ec, yc, yn, 0, 0, 0);
  { float* ty = yc; yc = yn; yn = ty; }
  // final: Y = s * (P @ y_20) = V_0 y_20
  k_ns<<<dim3(2, 1, SBH), 256>>>(nullptr, nullptr, pPb, yc, yn, 0, 0, 1);
  // conv residual -> out, then out += k1 @ Y
  k_conv<<<dim3(784, SBH), 256>>>(V, cw, out);
  k_Xt<<<dim3(1, 25, SBH), 256>>>(yn, out);
}

// round 13
// speedup vs baseline: 3.0893x; 1.0836x over previous
#include <cuda_runtime.h>
#include <cuda_bf16.h>
#include <math.h>
#include <stdint.h>

#define SBH 128
#define SN  3136
#define SM  196
#define SMP 224                    /* k1 row stride (bf16), 32-aligned, zero-padded */
#define SHW 56
#define QS  0.35355339059327379f   /* 64^-0.25 */
#define NSP 256
#define NSE ((size_t)(NSP*NSP))

// ---------------- scratch (static device globals; no allocation) ----------------
__device__ float g_Ql [SBH*SM*64];
__device__ float g_ql2[SBH*SM];
__device__ float g_qn2[SBH*SN];
__device__ __align__(16) __nv_bfloat16 g_k1[(size_t)SBH*SN*SMP];   // 180 MB bf16
__device__ float g_P  [SBH*SM*SM];
__device__ float g_nsc[SBH];
__device__ __align__(16) __nv_bfloat16 g_Pb[SBH*NSE];   // bf16 P, padded 256x256
__device__ __align__(16) __nv_bfloat16 g_Ea[SBH*NSE];   // E ping
__device__ __align__(16) __nv_bfloat16 g_Eb[SBH*NSE];   // E pong
__device__ __align__(16) float g_y0[SBH*256*64];        // y ping (fp32)
__device__ __align__(16) float g_y1[SBH*256*64];        // y pong

// ================= helpers =================
__device__ __forceinline__ uint32_t pack2(__nv_bfloat16 a, __nv_bfloat16 b) {
  return (uint32_t)__bfloat16_as_ushort(a) | ((uint32_t)__bfloat16_as_ushort(b) << 16);
}
__device__ __forceinline__ void mma16816(float* c, const uint32_t* a, const uint32_t* b) {
  asm volatile(
    "mma.sync.aligned.m16n8k16.row.col.f32.bf16.bf16.f32 "
    "{%0,%1,%2,%3}, {%4,%5,%6,%7}, {%8,%9}, {%0,%1,%2,%3};"
    : "+f"(c[0]), "+f"(c[1]), "+f"(c[2]), "+f"(c[3])
    : "r"(a[0]), "r"(a[1]), "r"(a[2]), "r"(a[3]), "r"(b[0]), "r"(b[1]));
}
__device__ __forceinline__ uint32_t cvt_tf32(float x) {
  uint32_t r; asm("cvt.rna.tf32.f32 %0, %1;" : "=r"(r) : "f"(x)); return r;
}
__device__ __forceinline__ void mma_tf32(float* c, const uint32_t* a, const uint32_t* b) {
  asm volatile(
    "mma.sync.aligned.m16n8k8.row.col.f32.tf32.tf32.f32 "
    "{%0,%1,%2,%3}, {%4,%5,%6,%7}, {%8,%9}, {%0,%1,%2,%3};"
    : "+f"(c[0]), "+f"(c[1]), "+f"(c[2]), "+f"(c[3])
    : "r"(a[0]), "r"(a[1]), "r"(a[2]), "r"(a[3]), "r"(b[0]), "r"(b[1]));
}
__device__ __forceinline__ void cpa16(void* s, const void* g) {
  uint32_t sa = (uint32_t)__cvta_generic_to_shared(s);
  asm volatile("cp.async.cg.shared.global [%0], [%1], 16;" :: "r"(sa), "l"(g));
}
#define CPA_COMMIT asm volatile("cp.async.commit_group;" ::: "memory")
#define CPA_WAIT1  asm volatile("cp.async.wait_group 1;" ::: "memory")
#define CPA_WAIT0  asm volatile("cp.async.wait_group 0;" ::: "memory")
// MUFU-free exp: 2^(x*log2e), deg-6 poly + exponent bit inject.
__device__ __forceinline__ float fexp(float x) {
  float t = x * 1.4426950408889634f;
  float j = rintf(t);
  float f = t - j;
  float p = 1.53958971e-4f;
  p = fmaf(p, f, 1.33336498e-3f);
  p = fmaf(p, f, 9.61817851e-3f);
  p = fmaf(p, f, 5.55041087e-2f);
  p = fmaf(p, f, 2.40226507e-1f);
  p = fmaf(p, f, 6.93147181e-1f);
  p = fmaf(p, f, 1.0f);
  j = fmaxf(j, -126.f);
  return p * __int_as_float(((int)j + 127) << 23);
}

// ---------------- landmark conv via tf32 HMMA + LayerNorm + GELU + ql2 ----------------
// im2col GEMM [128 rows x 64 cols, K=1024], grid (1, 2, SBH).
__global__ __launch_bounds__(256) void k_land(const float* __restrict__ Q,
        const float* __restrict__ W, const float* __restrict__ gamma,
        const float* __restrict__ beta) {
  __shared__ __align__(16) char smraw[34304];
  float (*sA)[36] = (float(*)[36])smraw;                 // 128 x 32 (pitch 36)
  float (*sB)[68] = (float(*)[68])(smraw + 18432);       // 32 x 64 (pitch 68)
  float (*Cs)[67] = (float(*)[67])smraw;                 // reused after GEMM
  int tid = threadIdx.x, w = tid >> 5, lane = tid & 31;
  int gid = lane >> 2, tig = lane & 3;
  int wm = w & 3, wn = w >> 2;
  int bh = blockIdx.z, m0 = blockIdx.y * 128;
  const float* Qb = Q + (size_t)bh * SN * 64;
  float acc[2][4][4] = {};
  int r = tid >> 1, kh = (tid & 1) * 16;
  int m = m0 + r;
  int py = m / 14, px = m % 14;
  for (int kc = 0; kc < 32; kc++) {
    int k0 = kc * 32;
    {
      int k = k0 + kh;
      int pix = k >> 6, ci = k & 63;
      int ry = pix >> 2, rx = pix & 3;
      float4 v[4] = {};
      if (m < SM) {
        int n = (py * 4 + ry) * SHW + px * 4 + rx;
        const float4* src = (const float4*)&Qb[(size_t)n * 64 + ci];
        #pragma unroll
        for (int e = 0; e < 4; e++) {
          float4 t = src[e];
          t.x *= QS; t.y *= QS; t.z *= QS; t.w *= QS;
          v[e] = t;
        }
      }
      #pragma unroll
      for (int e = 0; e < 4; e++) *(float4*)&sA[r][kh + e * 4] = v[e];
    }
    #pragma unroll
    for (int e = 0; e < 2; e++) {
      int t2 = tid * 2 + e;
      int tok = t2 >> 4, sg = t2 & 15;
      *(float4*)&sB[tok][sg * 4] = *(const float4*)&W[(size_t)(k0 + tok) * 64 + sg * 4];
    }
    __syncthreads();
    #pragma unroll
    for (int ks = 0; ks < 4; ks++) {
      int kb = ks * 8;
      uint32_t af[2][4], bf[4][2];
      #pragma unroll
      for (int mt = 0; mt < 2; mt++) {
        int row = wm * 32 + mt * 16 + gid;
        af[mt][0] = cvt_tf32(sA[row][kb + tig]);
        af[mt][1] = cvt_tf32(sA[row + 8][kb + tig]);
        af[mt][2] = cvt_tf32(sA[row][kb + tig + 4]);
        af[mt][3] = cvt_tf32(sA[row + 8][kb + tig + 4]);
      }
      #pragma unroll
      for (int nt = 0; nt < 4; nt++) {
        int nc = wn * 32 + nt * 8 + gid;
        bf[nt][0] = cvt_tf32(sB[kb + tig][nc]);
        bf[nt][1] = cvt_tf32(sB[kb + tig + 4][nc]);
      }
      #pragma unroll
      for (int mt = 0; mt < 2; mt++)
        #pragma unroll
        for (int nt = 0; nt < 4; nt++)
          mma_tf32(acc[mt][nt], af[mt], bf[nt]);
    }
    __syncthreads();
  }
  // stage C to smem for row-wise LN
  #pragma unroll
  for (int mt = 0; mt < 2; mt++)
    #pragma unroll
    for (int half = 0; half < 2; half++) {
      int rl = wm * 32 + mt * 16 + gid + half * 8;
      #pragma unroll
      for (int nt = 0; nt < 4; nt++) {
        int c = wn * 32 + nt * 8 + tig * 2;
        Cs[rl][c]     = acc[mt][nt][half * 2];
        Cs[rl][c + 1] = acc[mt][nt][half * 2 + 1];
      }
    }
  __syncthreads();
  if (tid < 128) {
    int p = m0 + tid;
    if (p < SM) {
      float mu = 0.f;
      #pragma unroll 8
      for (int j = 0; j < 64; j++) mu += Cs[tid][j];
      mu *= (1.f / 64.f);
      float s2 = 0.f;
      #pragma unroll 8
      for (int j = 0; j < 64; j++) { float d = Cs[tid][j] - mu; s2 += d * d; }
      float rr = rsqrtf(s2 * (1.f / 64.f) + 1e-5f);
      float q2 = 0.f;
      float* o = g_Ql + ((size_t)bh * SM + p) * 64;
      for (int j = 0; j < 64; j++) {
        float g = (Cs[tid][j] - mu) * rr * gamma[j] + beta[j];
        g = 0.5f * g * (1.f + erff(g * 0.7071067811865476f));
        q2 += g * g;
        o[j] = g;
      }
      g_ql2[bh * SM + p] = q2;
    }
  }
}

// ---------------- |scaled q_n|^2 ----------------
__global__ __launch_bounds__(256) void k_qn2(const float* __restrict__ Q) {
  int bh = blockIdx.y;
  int warp = threadIdx.x >> 5, lane = threadIdx.x & 31;
  int n = blockIdx.x * 8 + warp;
  const float* q = Q + ((size_t)bh * SN + n) * 64;
  float v0 = q[lane], v1 = q[lane + 32];
  float s = v0 * v0 + v1 * v1;
  #pragma unroll
  for (int o = 16; o; o >>= 1) s += __shfl_xor_sync(0xffffffffu, s, o);
  if (lane == 0) g_qn2[bh * SN + n] = s * (QS * QS);
}

// ---------------- unified gauss GEMM (tf32 HMMA + poly-exp) ----------------
// pmode=1: P = gauss(Ql,Ql) -> fp32 g_P [SM,SM] + bf16 g_Pb [256,256]; grid (2,2,SBH)
// pmode=0: k1 = gauss(Qs,Ql) -> bf16 g_k1 [SN,SMP]; grid (2,25,SBH)
__global__ __launch_bounds__(256) void k_gs(const float* __restrict__ A,
        const float* __restrict__ a2v, int Ma, float ascale, int pmode) {
  __shared__ __align__(16) float sA[128][36];
  __shared__ __align__(16) float sB[128][36];
  int tid = threadIdx.x, w = tid >> 5, lane = tid & 31;
  int gid = lane >> 2, tig = lane & 3;
  int wm = w & 3, wn = w >> 2;
  int bh = blockIdx.z, m0 = blockIdx.y * 128, n0 = blockIdx.x * 128;
  const float* Ab = A + (size_t)bh * Ma * 64;
  const float* Qlb = g_Ql + (size_t)bh * SM * 64;
  const float* a2b = a2v + (size_t)bh * Ma;
  const float* ql2b = g_ql2 + (size_t)bh * SM;
  float acc[2][8][4] = {};
  int r = tid >> 1, hb = (tid & 1) * 4;
  for (int kc = 0; kc < 2; kc++) {
    int k0 = kc * 32;
    int gm = m0 + r, gn = n0 + r;
    #pragma unroll
    for (int e = 0; e < 4; e++) {
      int c = (hb + e) * 4;
      float4 va = make_float4(0.f, 0.f, 0.f, 0.f);
      if (gm < Ma) va = *(const float4*)&Ab[(size_t)gm * 64 + k0 + c];
      va.x *= ascale; va.y *= ascale; va.z *= ascale; va.w *= ascale;
      *(float4*)&sA[r][c] = va;
      float4 vb = make_float4(0.f, 0.f, 0.f, 0.f);
      if (gn < SM) vb = *(const float4*)&Qlb[(size_t)gn * 64 + k0 + c];
      *(float4*)&sB[r][c] = vb;
    }
    __syncthreads();
    #pragma unroll
    for (int ks = 0; ks < 4; ks++) {
      int kb = ks * 8;
      uint32_t af[2][4], bf[8][2];
      #pragma unroll
      for (int mt = 0; mt < 2; mt++) {
        int row = wm * 32 + mt * 16 + gid;
        af[mt][0] = cvt_tf32(sA[row][kb + tig]);
        af[mt][1] = cvt_tf32(sA[row + 8][kb + tig]);
        af[mt][2] = cvt_tf32(sA[row][kb + tig + 4]);
        af[mt][3] = cvt_tf32(sA[row + 8][kb + tig + 4]);
      }
      #pragma unroll
      for (int nt = 0; nt < 8; nt++) {
        int brow = wn * 64 + nt * 8 + gid;
        bf[nt][0] = cvt_tf32(sB[brow][kb + tig]);
        bf[nt][1] = cvt_tf32(sB[brow][kb + tig + 4]);
      }
      #pragma unroll
      for (int mt = 0; mt < 2; mt++)
        #pragma unroll
        for (int nt = 0; nt < 8; nt++)
          mma_tf32(acc[mt][nt], af[mt], bf[nt]);
    }
    __syncthreads();
  }
  if (pmode) {
    float* P32 = g_P + (size_t)bh * SM * SM;
    __nv_bfloat16* Pbb = g_Pb + (size_t)bh * NSE;
    #pragma unroll
    for (int mt = 0; mt < 2; mt++) {
      #pragma unroll
      for (int half = 0; half < 2; half++) {
        int mm = m0 + wm * 32 + mt * 16 + gid + half * 8;
        float qm = (mm < SM) ? a2b[mm] : 0.f;
        #pragma unroll
        for (int nt = 0; nt < 8; nt++) {
          int n = n0 + wn * 64 + nt * 8 + tig * 2;
          float v0 = 0.f, v1 = 0.f;
          if (mm < SM) {
            if (n < SM)     v0 = fexp(acc[mt][nt][half * 2]     - 0.5f * (qm + ql2b[n]));
            if (n + 1 < SM) v1 = fexp(acc[mt][nt][half * 2 + 1] - 0.5f * (qm + ql2b[n + 1]));
          }
          *(uint32_t*)(Pbb + (size_t)mm * NSP + n) =
              pack2(__float2bfloat16(v0), __float2bfloat16(v1));
          if (mm < SM) {
            if (n < SM)     P32[(size_t)mm * SM + n] = v0;
            if (n + 1 < SM) P32[(size_t)mm * SM + n + 1] = v1;
          }
        }
      }
    }
  } else {
    __nv_bfloat16* k1b = g_k1 + (size_t)bh * SN * SMP;
    #pragma unroll
    for (int mt = 0; mt < 2; mt++) {
      #pragma unroll
      for (int half = 0; half < 2; half++) {
        int mm = m0 + wm * 32 + mt * 16 + gid + half * 8;
        if (mm >= SN) continue;
        float qm = a2b[mm];
        #pragma unroll
        for (int nt = 0; nt < 8; nt++) {
          int n = n0 + wn * 64 + nt * 8 + tig * 2;
          if (n + 1 >= SMP) continue;
          float v0 = 0.f, v1 = 0.f;
          if (n < SM)     v0 = fexp(acc[mt][nt][half * 2]     - 0.5f * (qm + ql2b[n]));
          if (n + 1 < SM) v1 = fexp(acc[mt][nt][half * 2 + 1] - 0.5f * (qm + ql2b[n + 1]));
          *(uint32_t*)(k1b + (size_t)mm * SMP + n) =
              pack2(__float2bfloat16(v0), __float2bfloat16(v1));
        }
      }
    }
  }
}

// ---------------- NS scale: g_nsc = 1/(n1*ninf) (P symmetric); also zero y0 ----------
__global__ __launch_bounds__(256) void k_scale() {
  int bh = blockIdx.x;
  const float* P = g_P + (size_t)bh * SM * SM;
  __shared__ float red[256];
  int tid = threadIdx.x;
  float rs = 0.f;
  if (tid < SM) {
    for (int j = 0; j < SM; j++) rs += fabsf(P[tid * SM + j]);
  }
  red[tid] = rs; __syncthreads();
  for (int s = 128; s > 0; s >>= 1) { if (tid < s) red[tid] = fmaxf(red[tid], red[tid + s]); __syncthreads(); }
  if (tid == 0) g_nsc[bh] = 1.f / (red[0] * red[0]);
  float4* yb = (float4*)(g_y0 + (size_t)bh * 256 * 64);
  for (int i = tid; i < 256 * 64 / 4; i += 256) yb[i] = make_float4(0.f, 0.f, 0.f, 0.f);
}

// =====================================================================================
// k_ns: merged Newton-Schulz step.
//   Squaring slots (slot < nsq, nsq=3): D = Esq @ Esq; slot0=(0,0), slot1=(0,1)+mirror
//     via smem transpose, slot2=(1,1). initmode: Eout = I - s*D masked; else Eout = D.
//   Chain slots (slot >= nsq): D = Ech @ yin; finmode: yout = s*D; else yout = yin + D.
// =====================================================================================
__global__ __launch_bounds__(256, 2) void k_ns(
    const __nv_bfloat16* __restrict__ Esq, __nv_bfloat16* __restrict__ Eout,
    const __nv_bfloat16* __restrict__ Ech,
    const float* __restrict__ yin, float* __restrict__ yout,
    int nsq, int initmode, int finmode) {
  __shared__ __align__(16) char smraw[41984];
  typedef __nv_bfloat16 (*TileP)[40];
  int tid = threadIdx.x, w = tid >> 5, lane = tid & 31;
  int gid = lane >> 2, tig = lane & 3;
  int bh = blockIdx.z, slot = blockIdx.x;
  size_t base = (size_t)bh * NSE;

  if (slot < nsq) {
    // ---------------- squaring role ----------------
    TileP sA0 = (TileP)(smraw);
    TileP sA1 = (TileP)(smraw + 10240);
    TileP sB0 = (TileP)(smraw + 20480);
    TileP sB1 = (TileP)(smraw + 30720);
    int m0 = (slot == 2) ? 128 : 0;
    int n0 = (slot >= 1) ? 128 : 0;
    int wm = w & 3, wn = w >> 2;                 // warp grid 4x2, warp tile 32x64
    const uint4* gE = (const uint4*)(Esq + base);
    float acc[2][8][4] = {};
    int r0 = tid >> 2, seg = tid & 3;
    cpa16(&sA0[r0][seg * 8],      gE + ((m0 + r0) * 32 + seg));
    cpa16(&sA0[r0 + 64][seg * 8], gE + ((m0 + r0 + 64) * 32 + seg));
    cpa16(&sB0[r0][seg * 8],      gE + ((n0 + r0) * 32 + seg));
    cpa16(&sB0[r0 + 64][seg * 8], gE + ((n0 + r0 + 64) * 32 + seg));
    CPA_COMMIT;
    for (int kc = 0; kc < 8; kc++) {
      TileP cA = (kc & 1) ? sA1 : sA0;
      TileP cB = (kc & 1) ? sB1 : sB0;
      if (kc < 7) {
        TileP nA = (kc & 1) ? sA0 : sA1;
        TileP nB = (kc & 1) ? sB0 : sB1;
        int kn = (kc + 1) * 4;
        cpa16(&nA[r0][seg * 8],      gE + ((m0 + r0) * 32 + kn + seg));
        cpa16(&nA[r0 + 64][seg * 8], gE + ((m0 + r0 + 64) * 32 + kn + seg));
        cpa16(&nB[r0][seg * 8],      gE + ((n0 + r0) * 32 + kn + seg));
        cpa16(&nB[r0 + 64][seg * 8], gE + ((n0 + r0 + 64) * 32 + kn + seg));
        CPA_COMMIT;
        CPA_WAIT1;
      } else {
        CPA_WAIT0;
      }
      __syncthreads();
      #pragma unroll
      for (int ks = 0; ks < 2; ks++) {
        int kb = ks * 16;
        uint32_t af[2][4], bf[8][2];
        #pragma unroll
        for (int mt = 0; mt < 2; mt++) {
          int row = wm * 32 + mt * 16 + gid;
          af[mt][0] = *(const uint32_t*)&cA[row][kb + tig * 2];
          af[mt][1] = *(const uint32_t*)&cA[row + 8][kb + tig * 2];
          af[mt][2] = *(const uint32_t*)&cA[row][kb + 8 + tig * 2];
          af[mt][3] = *(const uint32_t*)&cA[row + 8][kb + 8 + tig * 2];
        }
        #pragma unroll
        for (int nt = 0; nt < 8; nt++) {
          int brow = wn * 64 + nt * 8 + gid;
          bf[nt][0] = *(const uint32_t*)&cB[brow][kb + tig * 2];
          bf[nt][1] = *(const uint32_t*)&cB[brow][kb + 8 + tig * 2];
        }
        #pragma unroll
        for (int mt = 0; mt < 2; mt++)
          #pragma unroll
          for (int nt = 0; nt < 8; nt++)
            mma16816(acc[mt][nt], af[mt], bf[nt]);
      }
      __syncthreads();
    }
    float s = g_nsc[bh];
    __nv_bfloat16 (*tr)[129] = (__nv_bfloat16(*)[129])smraw;   // mirror stage (slot1)
    #pragma unroll
    for (int mt = 0; mt < 2; mt++) {
      #pragma unroll
      for (int nt = 0; nt < 8; nt++) {
        int row = m0 + wm * 32 + mt * 16 + gid;
        int col = n0 + wn * 64 + nt * 8 + tig * 2;
        #pragma unroll
        for (int half = 0; half < 2; half++) {
          int r = row + half * 8;
          float d0 = acc[mt][nt][half * 2], d1 = acc[mt][nt][half * 2 + 1];
          if (initmode) {
            d0 = (r < SM && col < SM) ? ((r == col ? 1.f : 0.f) - s * d0) : 0.f;
            d1 = (r < SM && col + 1 < SM) ? ((r == col + 1 ? 1.f : 0.f) - s * d1) : 0.f;
          }
          __nv_bfloat16 h0 = __float2bfloat16(d0), h1 = __float2bfloat16(d1);
          *(uint32_t*)(Eout + base + (size_t)r * NSP + col) = pack2(h0, h1);
          if (slot == 1) {
            int cl = col - 128;
            tr[r][cl] = h0;
            tr[r][cl + 1] = h1;
          }
        }
      }
    }
    if (slot == 1) {
      __syncthreads();
      // transposed coalesced store: D[128+cl][rl] = tr[rl][cl]
      #pragma unroll
      for (int i = 0; i < 16; i++) {
        int r2 = w * 16 + i;              // cl index -> global row 128+r2
        int j = lane * 4;                 // rl index
        uint2 pk;
        pk.x = pack2(tr[j][r2], tr[j + 1][r2]);
        pk.y = pack2(tr[j + 2][r2], tr[j + 3][r2]);
        *(uint2*)(Eout + base + (size_t)(128 + r2) * NSP + j) = pk;
      }
    }
  } else {
    // ---------------- chain role: D = Ech @ yin ----------------
    TileP sAc = (TileP)(smraw);                              // [128][40]
    __nv_bfloat16 (*sBy)[40] = (__nv_bfloat16(*)[40])(smraw + 10240);  // [64][40]
    int cslot = slot - nsq;
    int m0c = cslot * 128;
    int wm = w & 3, wn = w >> 2;                 // warp tile 32x32
    const uint4* gAc = (const uint4*)(Ech + base);
    const float* yb_in = yin + (size_t)bh * 256 * 64;
    float* yb_out = yout + (size_t)bh * 256 * 64;
    float acc[2][4][4] = {};
    int r0 = tid >> 2, seg = tid & 3;
    int kk = tid & 31, nb = (tid >> 5) * 8;
    for (int kc = 0; kc < 8; kc++) {
      *(uint4*)&sAc[r0][seg * 8]      = gAc[(m0c + r0) * 32 + kc * 4 + seg];
      *(uint4*)&sAc[r0 + 64][seg * 8] = gAc[(m0c + r0 + 64) * 32 + kc * 4 + seg];
      #pragma unroll
      for (int i = 0; i < 8; i++)
        sBy[nb + i][kk] = __float2bfloat16(yb_in[(size_t)(kc * 32 + kk) * 64 + nb + i]);
      __syncthreads();
      #pragma unroll
      for (int ks = 0; ks < 2; ks++) {
        int kb = ks * 16;
        uint32_t af[2][4], bf[4][2];
        #pragma unroll
        for (int mt = 0; mt < 2; mt++) {
          int row = wm * 32 + mt * 16 + gid;
          af[mt][0] = *(const uint32_t*)&sAc[row][kb + tig * 2];
          af[mt][1] = *(const uint32_t*)&sAc[row + 8][kb + tig * 2];
          af[mt][2] = *(const uint32_t*)&sAc[row][kb + 8 + tig * 2];
          af[mt][3] = *(const uint32_t*)&sAc[row + 8][kb + 8 + tig * 2];
        }
        #pragma unroll
        for (int nt = 0; nt < 4; nt++) {
          int brow = wn * 32 + nt * 8 + gid;
          bf[nt][0] = *(const uint32_t*)&sBy[brow][kb + tig * 2];
          bf[nt][1] = *(const uint32_t*)&sBy[brow][kb + 8 + tig * 2];
        }
        #pragma unroll
        for (int mt = 0; mt < 2; mt++)
          #pragma unroll
          for (int nt = 0; nt < 4; nt++)
            mma16816(acc[mt][nt], af[mt], bf[nt]);
      }
      __syncthreads();
    }
    float s = g_nsc[bh];
    #pragma unroll
    for (int mt = 0; mt < 2; mt++)
      #pragma unroll
      for (int half = 0; half < 2; half++) {
        int mr = m0c + wm * 32 + mt * 16 + gid + half * 8;
        #pragma unroll
        for (int nt = 0; nt < 4; nt++) {
          int col = wn * 32 + nt * 8 + tig * 2;
          float d0 = acc[mt][nt][half * 2], d1 = acc[mt][nt][half * 2 + 1];
          float o0, o1;
          if (finmode) { o0 = s * d0; o1 = s * d1; }
          else {
            o0 = yb_in[(size_t)mr * 64 + col] + d0;
            o1 = yb_in[(size_t)mr * 64 + col + 1] + d1;
          }
          yb_out[(size_t)mr * 64 + col] = o0;
          yb_out[(size_t)mr * 64 + col + 1] = o1;
        }
      }
  }
}

// ---------------- y0 += slice of Z = k1^T @ V (bf16 HMMA, K split over grid.x) --------
__global__ __launch_bounds__(256) void k_Zt(const float* __restrict__ V,
                                            float* __restrict__ y0) {
  __shared__ __align__(16) __nv_bfloat16 sA[128][40];   // [landmark][token]
  __shared__ __align__(16) __nv_bfloat16 sB[64][40];    // [channel][token]
  int tid = threadIdx.x, w = tid >> 5, lane = tid & 31;
  int gid = lane >> 2, tig = lane & 3;
  int wm = w & 3, wn = w >> 2;
  int bh = blockIdx.z, m0 = blockIdx.y * 128, kslice = blockIdx.x;
  const __nv_bfloat16* k1b = g_k1 + (size_t)bh * SN * SMP;
  const float* Vb = V + (size_t)bh * SN * 64;
  float acc[2][4][4] = {};
  int tokA = tid & 31, segA = tid >> 5;
  int cB = tid & 63, gB = tid >> 6;
  for (int kc = kslice * 14; kc < kslice * 14 + 14; kc++) {
    int k0 = kc * 32;
    const __nv_bfloat16* k1r = k1b + (size_t)(k0 + tokA) * SMP;
    #pragma unroll
    for (int i = 0; i < 4; i++) {
      int l = segA * 16 + i * 4;
      int gl = m0 + l;
      __align__(8) __nv_bfloat16 v4[4];
      if (gl + 3 < SMP) *(uint2*)v4 = *(const uint2*)&k1r[gl];
      else { v4[0] = v4[1] = v4[2] = v4[3] = __float2bfloat16(0.f); }
      sA[l][tokA] = v4[0]; sA[l + 1][tokA] = v4[1];
      sA[l + 2][tokA] = v4[2]; sA[l + 3][tokA] = v4[3];
    }
    #pragma unroll
    for (int i = 0; i < 8; i++) {
      int t = gB * 8 + i;
      sB[cB][t] = __float2bfloat16(Vb[(size_t)(k0 + t) * 64 + cB]);
    }
    __syncthreads();
    #pragma unroll
    for (int ks = 0; ks < 2; ks++) {
      int kb = ks * 16;
      uint32_t af[2][4], bf[4][2];
      #pragma unroll
      for (int mt = 0; mt < 2; mt++) {
        int row = wm * 32 + mt * 16 + gid;
        af[mt][0] = *(const uint32_t*)&sA[row][kb + tig * 2];
        af[mt][1] = *(const uint32_t*)&sA[row + 8][kb + tig * 2];
        af[mt][2] = *(const uint32_t*)&sA[row][kb + 8 + tig * 2];
        af[mt][3] = *(const uint32_t*)&sA[row + 8][kb + 8 + tig * 2];
      }
      #pragma unroll
      for (int nt = 0; nt < 4; nt++) {
        int brow = wn * 32 + nt * 8 + gid;
        bf[nt][0] = *(const uint32_t*)&sB[brow][kb + tig * 2];
        bf[nt][1] = *(const uint32_t*)&sB[brow][kb + 8 + tig * 2];
      }
      #pragma unroll
      for (int mt = 0; mt < 2; mt++)
        #pragma unroll
        for (int nt = 0; nt < 4; nt++)
          mma16816(acc[mt][nt], af[mt], bf[nt]);
    }
    __syncthreads();
  }
  float* yb = y0 + (size_t)bh * 256 * 64;
  #pragma unroll
  for (int mt = 0; mt < 2; mt++)
    #pragma unroll
    for (int half = 0; half < 2; half++) {
      int mr = m0 + wm * 32 + mt * 16 + gid + half * 8;
      #pragma unroll
      for (int nt = 0; nt < 4; nt++) {
        int n = wn * 32 + nt * 8 + tig * 2;
        atomicAdd(&yb[(size_t)mr * 64 + n],     acc[mt][nt][half * 2]);
        atomicAdd(&yb[(size_t)mr * 64 + n + 1], acc[mt][nt][half * 2 + 1]);
      }
    }
}

// ---------------- depthwise 3x3 conv residual -> d_out ----------------
__global__ __launch_bounds__(256) void k_conv(const float* __restrict__ V,
        const float* __restrict__ cw, float* __restrict__ out) {
  int bh = blockIdx.y;
  int h = bh & 7;
  int e = blockIdx.x * 256 + threadIdx.x;
  int c = e & 63, n = e >> 6;
  int y = n / SHW, x = n % SHW;
  const float* Vb = V + (size_t)bh * SN * 64;
  float acc = 0.f;
  #pragma unroll
  for (int dy = -1; dy <= 1; dy++)
    #pragma unroll
    for (int dx = -1; dx <= 1; dx++) {
      int yy = y + dy, xx = x + dx;
      if ((unsigned)yy < SHW && (unsigned)xx < SHW)
        acc += cw[((dy + 1) * 3 + (dx + 1)) * 8 + h] * Vb[(yy * SHW + xx) * 64 + c];
    }
  out[(size_t)bh * SN * 64 + e] = acc;
}

// ---------------- out += k1 @ Y (bf16 HMMA, K=224 in 7 chunks) ----------------
__global__ __launch_bounds__(256) void k_Xt(const float* __restrict__ Yf,
                                            float* __restrict__ out) {
  __shared__ __align__(16) __nv_bfloat16 sA[128][40];   // [token][landmark-k]
  __shared__ __align__(16) __nv_bfloat16 sB[64][40];    // [channel][landmark-k]
  int tid = threadIdx.x, w = tid >> 5, lane = tid & 31;
  int gid = lane >> 2, tig = lane & 3;
  int wm = w & 3, wn = w >> 2;
  int bh = blockIdx.z, m0 = blockIdx.y * 128;
  const __nv_bfloat16* k1b = g_k1 + (size_t)bh * SN * SMP;
  const float* Yb = Yf + (size_t)bh * 256 * 64;
  float acc[2][4][4] = {};
  int r0 = tid >> 2, seg = tid & 3;
  int cB = tid & 63, gB = tid >> 6;
  for (int kc = 0; kc < 7; kc++) {
    int k0 = kc * 32;
    #pragma unroll
    for (int rr = 0; rr < 2; rr++) {
      int gm = m0 + r0 + rr * 64;
      uint4 v = make_uint4(0, 0, 0, 0);
      if (gm < SN) v = *(const uint4*)&k1b[(size_t)gm * SMP + k0 + seg * 8];
      *(uint4*)&sA[r0 + rr * 64][seg * 8] = v;
    }
    #pragma unroll
    for (int i = 0; i < 8; i++) {
      int t = gB * 8 + i;
      sB[cB][t] = __float2bfloat16(Yb[(size_t)(k0 + t) * 64 + cB]);
    }
    __syncthreads();
    #pragma unroll
    for (int ks = 0; ks < 2; ks++) {
      int kb = ks * 16;
      uint32_t af[2][4], bf[4][2];
      #pragma unroll
      for (int mt = 0; mt < 2; mt++) {
        int row = wm * 32 + mt * 16 + gid;
        af[mt][0] = *(const uint32_t*)&sA[row][kb + tig * 2];
        af[mt][1] = *(const uint32_t*)&sA[row + 8][kb + tig * 2];
        af[mt][2] = *(const uint32_t*)&sA[row][kb + 8 + tig * 2];
        af[mt][3] = *(const uint32_t*)&sA[row + 8][kb + 8 + tig * 2];
      }
      #pragma unroll
      for (int nt = 0; nt < 4; nt++) {
        int brow = wn * 32 + nt * 8 + gid;
        bf[nt][0] = *(const uint32_t*)&sB[brow][kb + tig * 2];
        bf[nt][1] = *(const uint32_t*)&sB[brow][kb + 8 + tig * 2];
      }
      #pragma unroll
      for (int mt = 0; mt < 2; mt++)
        #pragma unroll
        for (int nt = 0; nt < 4; nt++)
          mma16816(acc[mt][nt], af[mt], bf[nt]);
    }
    __syncthreads();
  }
  float* ob = out + (size_t)bh * SN * 64;
  #pragma unroll
  for (int mt = 0; mt < 2; mt++)
    #pragma unroll
    for (int half = 0; half < 2; half++) {
      int mr = m0 + wm * 32 + mt * 16 + gid + half * 8;
      if (mr >= SN) continue;
      #pragma unroll
      for (int nt = 0; nt < 4; nt++) {
        int n = wn * 32 + nt * 8 + tig * 2;
        ob[(size_t)mr * 64 + n]     += acc[mt][nt][half * 2];
        ob[(size_t)mr * 64 + n + 1] += acc[mt][nt][half * 2 + 1];
      }
    }
}

// ---------------- host launch ----------------
extern "C" void kernel_launch(void* const* d_in, const int* in_sizes, int n_in,
                              void* d_out, int out_size) {
  const float* Q     = (const float*)d_in[0];
  const float* V     = (const float*)d_in[1];
  const float* wl    = (const float*)d_in[2];
  const float* gamma = (const float*)d_in[3];
  const float* beta  = (const float*)d_in[4];
  const float* cw    = (const float*)d_in[5];
  float* out = (float*)d_out;

  float *pQl, *pql2, *pqn2, *py0, *py1;
  cudaGetSymbolAddress((void**)&pQl,  g_Ql);
  cudaGetSymbolAddress((void**)&pql2, g_ql2);
  cudaGetSymbolAddress((void**)&pqn2, g_qn2);
  cudaGetSymbolAddress((void**)&py0,  g_y0);
  cudaGetSymbolAddress((void**)&py1,  g_y1);
  __nv_bfloat16 *pEa, *pEb, *pPb;
  cudaGetSymbolAddress((void**)&pPb, g_Pb);
  cudaGetSymbolAddress((void**)&pEa, g_Ea);
  cudaGetSymbolAddress((void**)&pEb, g_Eb);

  // landmarks (tf32 conv + LN + GELU + |ql|^2), |q|^2
  k_land<<<dim3(1, 2, SBH), 256>>>(Q, wl, gamma, beta);
  k_qn2<<<dim3(SN / 8, SBH), 256>>>(Q);
  // P = gauss(Ql,Ql) -> fp32 g_P + bf16 g_Pb (padded)
  k_gs<<<dim3(2, 2, SBH), 256>>>(pQl, pql2, SM, 1.f, 1);
  // scale + zero y0
  k_scale<<<SBH, 256>>>();
  // k1 = gauss(Qs,Ql) bf16; y0 = Z via K-split atomics
  k_gs<<<dim3(2, 25, SBH), 256>>>(Q, pqn2, SN, QS, 0);
  k_Zt<<<dim3(7, 2, SBH), 256>>>(V, py0);
  // E_0 = I - s*P^2   (3 squaring slots, slot1 mirrors via smem transpose)
  k_ns<<<dim3(3, 1, SBH), 256>>>(pPb, pEa, nullptr, nullptr, nullptr, 3, 1, 0);
  // 19 merged steps: E_{k+1}=E_k^2  +  y_{k+1}=(I+E_k)y_k
  __nv_bfloat16 *ec = pEa, *en = pEb;
  float *yc = py0, *yn = py1;
  for (int k = 0; k < 19; k++) {
    k_ns<<<dim3(5, 1, SBH), 256>>>(ec, en, ec, yc, yn, 3, 0, 0);
    __nv_bfloat16* te = ec; ec = en; en = te;
    float* ty = yc; yc = yn; yn = ty;
  }
  // chain-only with E_19
  k_ns<<<dim3(2, 1, SBH), 256>>>(nullptr, nullptr, ec, yc, yn, 0, 0, 0);
  { float* ty = yc; yc = yn; yn = ty; }
  // final: Y = s * (P @ y_20) = V_0 y_20
  k_ns<<<dim3(2, 1, SBH), 256>>>(nullptr, nullptr, pPb, yc, yn, 0, 0, 1);
  // conv residual -> out, then out += k1 @ Y
  k_conv<<<dim3(784, SBH), 256>>>(V, cw, out);
  k_Xt<<<dim3(1, 25, SBH), 256>>>(yn, out);
}